// round 10
// baseline (speedup 1.0000x reference)
#include <cuda_runtime.h>
#include <cuda_bf16.h>
#include <mma.h>
#include <math.h>
#include <stdint.h>

using namespace nvcuda;
typedef __nv_bfloat16 bf16;

#define B_      2
#define N_      2048
#define DIM_    1024
#define INNER_  512
#define HEADS_  8
#define DHEAD_  64
#define WS_     512
#define FF_     4096
#define BN_     (B_*N_)
#define NP_     (N_+WS_)
#define NWIN_   (N_/WS_)

// ---- fp32 scratch ----
__device__ float g_at [BN_*DIM_];
__device__ float g_vt [BN_*DIM_];
__device__ float g_probs[B_*NWIN_*WS_*2*WS_];
__device__ float g_x  [BN_*DIM_];
__device__ float g_q  [BN_*INNER_];
__device__ float g_kv [BN_*2*INNER_];
__device__ float g_o  [BN_*INNER_];
__device__ float g_x2 [BN_*DIM_];
__device__ float g_ff [BN_*FF_];

// ---- bf16 hi/lo scratch ----
__device__ bf16 g_audH[BN_*DIM_],  g_audL[BN_*DIM_];
__device__ bf16 g_vidH[BN_*DIM_],  g_vidL[BN_*DIM_];
__device__ bf16 g_qh [BN_*DIM_],   g_ql [BN_*DIM_];
__device__ bf16 g_kh [B_*NP_*DIM_],g_kl [B_*NP_*DIM_];
__device__ bf16 g_vTh[B_*DIM_*NP_],g_vTl[B_*DIM_*NP_];
__device__ bf16 g_ph [B_*NWIN_*WS_*2*WS_], g_pl[B_*NWIN_*WS_*2*WS_];
__device__ bf16 g_hh [BN_*DIM_],   g_hl [BN_*DIM_];
__device__ bf16 g_obH[BN_*INNER_], g_obL[BN_*INNER_];
__device__ bf16 g_x2H[BN_*DIM_],   g_x2L[BN_*DIM_];
__device__ bf16 g_ffH[BN_*FF_],    g_ffL[BN_*FF_];
__device__ bf16 g_WaTh [DIM_*DIM_],   g_WaTl [DIM_*DIM_];
__device__ bf16 g_WvTh [DIM_*DIM_],   g_WvTl [DIM_*DIM_];
__device__ bf16 g_WqTh [INNER_*DIM_], g_WqTl [INNER_*DIM_];
__device__ bf16 g_WkvTh[2*INNER_*DIM_],g_WkvTl[2*INNER_*DIM_];
__device__ bf16 g_WoTh [DIM_*INNER_], g_WoTl [DIM_*INNER_];
__device__ bf16 g_W1Th [FF_*DIM_],    g_W1Tl [FF_*DIM_];
__device__ bf16 g_W2Th [DIM_*FF_],    g_W2Tl [DIM_*FF_];

// ---- helpers ----
__device__ __forceinline__ uint32_t s2u(const void* p){
    uint32_t a;
    asm("{ .reg .u64 t; cvta.to.shared.u64 t, %1; cvt.u32.u64 %0, t; }"
        : "=r"(a) : "l"(p));
    return a;
}
__device__ __forceinline__ void cpa16(uint32_t d, const void* s){
    asm volatile("cp.async.cg.shared.global [%0], [%1], 16;" :: "r"(d), "l"(s));
}
__device__ __forceinline__ void cpa_commit(){
    asm volatile("cp.async.commit_group;" ::: "memory");
}
__device__ __forceinline__ void cpa_wait0(){
    asm volatile("cp.async.wait_group 0;" ::: "memory");
}
__device__ __forceinline__ void cpa_wait1(){
    asm volatile("cp.async.wait_group 1;" ::: "memory");
}
__device__ __forceinline__ void split2(float v, bf16& h, bf16& l){
    h = __float2bfloat16(v);
    l = __float2bfloat16(v - __bfloat162float(h));
}
__device__ __forceinline__ float gelu_tanh(float v){
    float c = v + 0.044715f * v * v * v;
    return 0.5f * v * (1.0f + tanhf(0.7978845608028654f * c));
}

// ---- bf16x3 wmma GEMM: 128x128 tile, warp 64x32, BK=32 ----
// LDSB=40 elems -> 80B rows: ldmatrix start banks (r*20)%32 all-distinct.
#define LDSB 40
#define MATB (128*LDSB*2)          // 10240 bytes per matrix per stage
#define AH_OFF 0
#define AL_OFF MATB
#define BH_OFF (2*MATB)
#define BL_OFF (3*MATB)
#define STGB  (4*MATB)             // 40960 per stage
#define GEMM_SMEM_DYN (2*STGB)     // 81920

#define EPI_NONE       0
#define EPI_BIAS       1
#define EPI_BIAS_GELU  2
#define EPI_BIAS_RES   3
#define EPI_SPLIT      4          // alpha, write fp32 C + bf16 hi/lo

template<int EPI>
__global__ void __launch_bounds__(256, 1)
gemm_wmma(const bf16* __restrict__ Ah, const bf16* __restrict__ Al,
          const bf16* __restrict__ Bh, const bf16* __restrict__ Bl,
          float* __restrict__ C, const float* __restrict__ bias,
          const float* __restrict__ res,
          bf16* __restrict__ Ch, bf16* __restrict__ Cl,
          int K, int lda, int ldb, int ldc, float alpha, int wdiv,
          long long sAb, long long sAw, long long sBb, long long sBw,
          long long sCb, long long sCw)
{
    extern __shared__ char dsm[];
    uint32_t sb0 = s2u(dsm);

    int tid = threadIdx.x;
    int wid = tid >> 5;
    int lane = tid & 31;
    int wm = wid >> 2;          // 0..1
    int wn = wid & 3;           // 0..3
    int z = blockIdx.z;
    int zb = z / wdiv, zw = z - zb * wdiv;
    long long aoff = zb * sAb + zw * sAw;
    long long boff = zb * sBb + zw * sBw;
    long long coff = zb * sCb + zw * sCw;
    Ah += aoff; Al += aoff;
    Bh += boff; Bl += boff;
    C  += coff;
    const float* Rp = (EPI == EPI_BIAS_RES) ? (res + coff) : nullptr;

    int m0 = blockIdx.y * 128;
    int n0 = blockIdx.x * 128;

    wmma::fragment<wmma::accumulator, 16, 16, 16, float> acc[4][2];
#pragma unroll
    for (int i = 0; i < 4; i++)
#pragma unroll
        for (int j = 0; j < 2; j++) wmma::fill_fragment(acc[i][j], 0.f);

    auto loadStage = [&](int stg, int kk){
        uint32_t sb = sb0 + stg * STGB;
#pragma unroll
        for (int half = 0; half < 2; half++){
            int i = tid + half * 256;           // 0..511
            int row = i >> 2, ch = i & 3;
            uint32_t d = row * (LDSB*2) + ch * 16;
            long long ga = (long long)(m0 + row) * lda + kk + ch * 8;
            long long gb = (long long)(n0 + row) * ldb + kk + ch * 8;
            cpa16(sb + AH_OFF + d, Ah + ga);
            cpa16(sb + AL_OFF + d, Al + ga);
            cpa16(sb + BH_OFF + d, Bh + gb);
            cpa16(sb + BL_OFF + d, Bl + gb);
        }
    };

    int KT = K >> 5;
    loadStage(0, 0);
    cpa_commit();

    for (int kt = 0; kt < KT; kt++){
        if (kt + 1 < KT){
            loadStage((kt + 1) & 1, (kt + 1) * 32);
            cpa_commit();
            cpa_wait1();
        } else {
            cpa_wait0();
        }
        __syncthreads();

        const bf16* st = (const bf16*)(dsm + (kt & 1) * STGB);
        const bf16* pAh = st + (AH_OFF/2) + (wm*64)*LDSB;
        const bf16* pAl = st + (AL_OFF/2) + (wm*64)*LDSB;
        const bf16* pBh = st + (BH_OFF/2) + (wn*32)*LDSB;
        const bf16* pBl = st + (BL_OFF/2) + (wn*32)*LDSB;
#pragma unroll
        for (int ks = 0; ks < 2; ks++){
            wmma::fragment<wmma::matrix_a, 16,16,16, bf16, wmma::row_major> fAh[4], fAl[4];
            wmma::fragment<wmma::matrix_b, 16,16,16, bf16, wmma::col_major> fBh[2], fBl[2];
#pragma unroll
            for (int i = 0; i < 4; i++){
                wmma::load_matrix_sync(fAh[i], pAh + i*16*LDSB + ks*16, LDSB);
                wmma::load_matrix_sync(fAl[i], pAl + i*16*LDSB + ks*16, LDSB);
            }
#pragma unroll
            for (int j = 0; j < 2; j++){
                wmma::load_matrix_sync(fBh[j], pBh + j*16*LDSB + ks*16, LDSB);
                wmma::load_matrix_sync(fBl[j], pBl + j*16*LDSB + ks*16, LDSB);
            }
#pragma unroll
            for (int i = 0; i < 4; i++)
#pragma unroll
                for (int j = 0; j < 2; j++){
                    wmma::mma_sync(acc[i][j], fAh[i], fBh[j], acc[i][j]);
                    wmma::mma_sync(acc[i][j], fAh[i], fBl[j], acc[i][j]);
                    wmma::mma_sync(acc[i][j], fAl[i], fBh[j], acc[i][j]);
                }
        }
        __syncthreads();
    }

    // ---- per-warp epilogue: each warp stages its 16x32 chunks privately ----
    float* scratch = (float*)dsm + wid * 512;   // 16x32 fp32 = 2KB per warp
#pragma unroll 1
    for (int i = 0; i < 4; i++){
        wmma::store_matrix_sync(scratch,      acc[i][0], 32, wmma::mem_row_major);
        wmma::store_matrix_sync(scratch + 16, acc[i][1], 32, wmma::mem_row_major);
        __syncwarp();
#pragma unroll
        for (int it = 0; it < 4; it++){
            int t = lane + it * 32;              // 0..127 float4s
            int r = t >> 3, c4 = (t & 7) * 4;
            float4 v = *(float4*)&scratch[r * 32 + c4];
            v.x *= alpha; v.y *= alpha; v.z *= alpha; v.w *= alpha;
            int gc = n0 + wn*32 + c4;
            if (EPI == EPI_BIAS || EPI == EPI_BIAS_GELU || EPI == EPI_BIAS_RES){
                float4 bb = *(const float4*)&bias[gc];
                v.x += bb.x; v.y += bb.y; v.z += bb.z; v.w += bb.w;
            }
            if (EPI == EPI_BIAS_GELU){
                v.x = gelu_tanh(v.x); v.y = gelu_tanh(v.y);
                v.z = gelu_tanh(v.z); v.w = gelu_tanh(v.w);
            }
            long long crow = (long long)(m0 + wm*64 + i*16 + r) * ldc + gc;
            if (EPI == EPI_BIAS_RES){
                float4 rr = *(const float4*)&Rp[crow];
                v.x += rr.x; v.y += rr.y; v.z += rr.z; v.w += rr.w;
            }
            *(float4*)&C[crow] = v;
            if (EPI == EPI_SPLIT){
                bf16 hh, ll;
                long long so = coff + crow - coff;   // same index space
                split2(v.x, hh, ll); Ch[so+0] = hh; Cl[so+0] = ll;
                split2(v.y, hh, ll); Ch[so+1] = hh; Cl[so+1] = ll;
                split2(v.z, hh, ll); Ch[so+2] = hh; Cl[so+2] = ll;
                split2(v.w, hh, ll); Ch[so+3] = hh; Cl[so+3] = ll;
            }
        }
        __syncwarp();
    }
}

// ---- LayerNorm fp32 out ----
__global__ void ln_kernel(const float* __restrict__ x, float* __restrict__ y,
                          const float* __restrict__ g, const float* __restrict__ bv,
                          int L)
{
    __shared__ float buf[4096];
    __shared__ float r1[8], r2[8], st[2];
    long long row = blockIdx.x;
    const float* xr = x + row * L;
    int tid = threadIdx.x;
    float s = 0.f, s2 = 0.f;
    for (int c = tid; c < L; c += 256){ float v = xr[c]; buf[c] = v; s += v; s2 += v*v; }
#pragma unroll
    for (int o = 16; o > 0; o >>= 1){
        s  += __shfl_xor_sync(0xffffffffu, s,  o);
        s2 += __shfl_xor_sync(0xffffffffu, s2, o);
    }
    int lane = tid & 31, w = tid >> 5;
    if (lane == 0){ r1[w] = s; r2[w] = s2; }
    __syncthreads();
    if (tid == 0){
        float ts = 0.f, ts2 = 0.f;
        for (int k = 0; k < 8; k++){ ts += r1[k]; ts2 += r2[k]; }
        float mean = ts / (float)L;
        st[0] = mean; st[1] = rsqrtf(ts2 / (float)L - mean*mean + 1e-5f);
    }
    __syncthreads();
    float mean = st[0], rstd = st[1];
    float* yr = y + row * L;
    for (int c = tid; c < L; c += 256)
        yr[c] = (buf[c] - mean) * rstd * g[c] + bv[c];
}

// ---- LayerNorm -> bf16 hi/lo ----
__global__ void ln_bf_kernel(const float* __restrict__ x, bf16* __restrict__ yh,
                             bf16* __restrict__ yl,
                             const float* __restrict__ g, const float* __restrict__ bv,
                             int L)
{
    __shared__ float buf[4096];
    __shared__ float r1[8], r2[8], st[2];
    long long row = blockIdx.x;
    const float* xr = x + row * L;
    int tid = threadIdx.x;
    float s = 0.f, s2 = 0.f;
    for (int c = tid; c < L; c += 256){ float v = xr[c]; buf[c] = v; s += v; s2 += v*v; }
#pragma unroll
    for (int o = 16; o > 0; o >>= 1){
        s  += __shfl_xor_sync(0xffffffffu, s,  o);
        s2 += __shfl_xor_sync(0xffffffffu, s2, o);
    }
    int lane = tid & 31, w = tid >> 5;
    if (lane == 0){ r1[w] = s; r2[w] = s2; }
    __syncthreads();
    if (tid == 0){
        float ts = 0.f, ts2 = 0.f;
        for (int k = 0; k < 8; k++){ ts += r1[k]; ts2 += r2[k]; }
        float mean = ts / (float)L;
        st[0] = mean; st[1] = rsqrtf(ts2 / (float)L - mean*mean + 1e-5f);
    }
    __syncthreads();
    float mean = st[0], rstd = st[1];
    for (int c = tid; c < L; c += 256){
        float v = (buf[c] - mean) * rstd * g[c] + bv[c];
        bf16 h, l; split2(v, h, l);
        yh[row * L + c] = h; yl[row * L + c] = l;
    }
}

// ---- RMSNorm over 64-dim head vectors ----
__global__ void rms_kernel(float* __restrict__ x, const float* __restrict__ g,
                           int vecs_per_row, int row_stride, int nrows)
{
    int vid = blockIdx.x * 8 + (threadIdx.x >> 5);
    int lane = threadIdx.x & 31;
    int r = vid / vecs_per_row;
    int h = vid - r * vecs_per_row;
    if (r >= nrows) return;
    float* p = x + (long long)r * row_stride + h * DHEAD_;
    float v0 = p[lane], v1 = p[lane + 32];
    float ss = v0*v0 + v1*v1;
#pragma unroll
    for (int o = 16; o > 0; o >>= 1) ss += __shfl_xor_sync(0xffffffffu, ss, o);
    float rs = rsqrtf(ss * (1.0f/64.0f) + 1e-6f);
    p[lane]      = v0 * rs * g[lane];
    p[lane + 32] = v1 * rs * g[lane + 32];
}

// ---- rotary prep -> bf16 hi/lo ----
__global__ void prep_kernel(const float* __restrict__ text,
                            const float* __restrict__ at,
                            bf16* __restrict__ qh, bf16* __restrict__ ql,
                            bf16* __restrict__ kh, bf16* __restrict__ kl)
{
    int row = blockIdx.x;
    int b = row / NP_;
    int pr = row - b * NP_;
    long long kout = (long long)row * DIM_;
    if (pr < WS_){
        bf16 zz = __float2bfloat16(0.f);
        for (int c = threadIdx.x; c < DIM_; c += 256){ kh[kout+c] = zz; kl[kout+c] = zz; }
        return;
    }
    int t = pr - WS_;
    long long src = ((long long)b * N_ + t) * DIM_;
    for (int c = threadIdx.x; c < DIM_; c += 256){
        int j = c & 511;
        // invf = 10000^(-j/512) via exp2f (fast, ~1e-7 rel err)
        float invf = exp2f((float)j * (-13.28771238f * (1.0f/512.0f)));
        float ang = (float)t * invf;
        float cs = cosf(ang), sn = sinf(ang);
        float kx = at[src + c];
        float ko = (c < 512) ? -at[src + c + 512] : at[src + c - 512];
        bf16 h, l;
        split2(kx * cs + ko * sn, h, l);
        kh[kout + c] = h; kl[kout + c] = l;
        float qx = text[src + c];
        float qo = (c < 512) ? -text[src + c + 512] : text[src + c - 512];
        split2(qx * cs + qo * sn, h, l);
        qh[src + c] = h; ql[src + c] = l;
    }
}

// ---- transpose + split ----
__global__ void tconv_kernel(const float* __restrict__ in, bf16* __restrict__ oh,
                             bf16* __restrict__ ol,
                             int inLd, int outLd, int pad,
                             long long inB, long long outB)
{
    __shared__ float t[32][33];
    in += blockIdx.z * inB;
    oh += blockIdx.z * outB;
    ol += blockIdx.z * outB;
    int p0 = blockIdx.x * 32, c0 = blockIdx.y * 32;
    int tx = threadIdx.x, ty = threadIdx.y;
    for (int i = ty; i < 32; i += 8){
        int r = p0 + i - pad;
        t[i][tx] = (r >= 0) ? in[(long long)r * inLd + c0 + tx] : 0.f;
    }
    __syncthreads();
    for (int i = ty; i < 32; i += 8){
        float v = t[tx][i];
        bf16 h, l; split2(v, h, l);
        long long o = (long long)(c0 + i) * outLd + p0 + tx;
        oh[o] = h; ol[o] = l;
    }
}

// ---- elementwise split fp32 -> bf16 hi/lo ----
__global__ void conv_kernel(const float* __restrict__ x, bf16* __restrict__ h,
                            bf16* __restrict__ l, int n)
{
    int i = (blockIdx.x * 256 + threadIdx.x) * 4;
    if (i < n){
        float4 v = *(const float4*)&x[i];
        bf16 hh, ll;
        split2(v.x, hh, ll); h[i+0] = hh; l[i+0] = ll;
        split2(v.y, hh, ll); h[i+1] = hh; l[i+1] = ll;
        split2(v.z, hh, ll); h[i+2] = hh; l[i+2] = ll;
        split2(v.w, hh, ll); h[i+3] = hh; l[i+3] = ll;
    }
}

// ---- local-attention masked softmax -> bf16 hi/lo ----
__global__ void softmax_local_kernel(const float* __restrict__ p,
                                     bf16* __restrict__ ph, bf16* __restrict__ pl)
{
    __shared__ float buf[1024];
    __shared__ float red[8], bc[2];
    int r = blockIdx.x;
    int i = r & (WS_ - 1);
    int z = r >> 9;
    int w = z & (NWIN_ - 1);
    int qp = w * WS_ + i;
    const float* row = p + (long long)r * (2 * WS_);
    int tid = threadIdx.x, lane = tid & 31, wp = tid >> 5;

    float mx = -1e30f;
    for (int j = tid; j < 2*WS_; j += 256){
        int kp = (w - 1) * WS_ + j;
        float v = (kp >= 0 && kp <= qp) ? row[j] : -1e9f;
        buf[j] = v;
        mx = fmaxf(mx, v);
    }
#pragma unroll
    for (int o = 16; o > 0; o >>= 1) mx = fmaxf(mx, __shfl_xor_sync(0xffffffffu, mx, o));
    if (lane == 0) red[wp] = mx;
    __syncthreads();
    if (tid == 0){
        float m = red[0];
        for (int k = 1; k < 8; k++) m = fmaxf(m, red[k]);
        bc[0] = m;
    }
    __syncthreads();
    mx = bc[0];
    float sum = 0.f;
    for (int j = tid; j < 2*WS_; j += 256){
        float e = __expf(buf[j] - mx);
        buf[j] = e; sum += e;
    }
#pragma unroll
    for (int o = 16; o > 0; o >>= 1) sum += __shfl_xor_sync(0xffffffffu, sum, o);
    if (lane == 0) red[wp] = sum;
    __syncthreads();
    if (tid == 0){
        float t = 0.f;
        for (int k = 0; k < 8; k++) t += red[k];
        bc[1] = 1.0f / t;
    }
    __syncthreads();
    float inv = bc[1];
    for (int j = tid; j < 2*WS_; j += 256){
        bf16 h, l; split2(buf[j] * inv, h, l);
        long long o = (long long)r * (2*WS_) + j;
        ph[o] = h; pl[o] = l;
    }
}

// ---- causal flash attention fp32 (per head, D=64), emits hi/lo too ----
#define QP_ 68
#define ATTN_SMEM_BYTES (4 * 64 * QP_ * 4 + 3 * 64 * 4)

__global__ void __launch_bounds__(256)
attn_kernel(const float* __restrict__ q, const float* __restrict__ kv,
            float* __restrict__ o, bf16* __restrict__ oh, bf16* __restrict__ ol)
{
    extern __shared__ float sm[];
    float* QsT = sm;
    float* KsT = QsT + 64 * QP_;
    float* Vs  = KsT + 64 * QP_;
    float* SsT = Vs  + 64 * QP_;
    float* Ms = SsT + 64 * QP_;
    float* Ls = Ms + 64;
    float* Cs = Ls + 64;

    int tid = threadIdx.x;
    int bh = blockIdx.y;
    int b = bh >> 3, h = bh & 7;
    int q0 = blockIdx.x * 64;
    int ty = tid >> 4, tx = tid & 15;

    for (int idx = tid; idx < 4096; idx += 256){
        int r = idx >> 6, c = idx & 63;
        QsT[c * QP_ + r] =
            q[((long long)(b * N_ + q0 + r)) * INNER_ + h * 64 + c] * 0.125f;
    }
    if (tid < 64){ Ms[tid] = -INFINITY; Ls[tid] = 0.f; }
    float oacc[16];
#pragma unroll
    for (int i = 0; i < 16; i++) oacc[i] = 0.f;
    __syncthreads();

    int lastTile = blockIdx.x;
    for (int kt = 0; kt <= lastTile; kt++){
        for (int idx = tid; idx < 4096; idx += 256){
            int r = idx >> 6, c = idx & 63;
            long long base =
                ((long long)(b * N_ + kt * 64 + r)) * (2 * INNER_) + h * 64 + c;
            KsT[c * QP_ + r] = kv[base];
            Vs[r * QP_ + c]  = kv[base + INNER_];
        }
        __syncthreads();

        float sacc[16];
#pragma unroll
        for (int i = 0; i < 16; i++) sacc[i] = 0.f;
#pragma unroll 8
        for (int kk = 0; kk < 64; kk++){
            float4 aq = *(const float4*)&QsT[kk * QP_ + ty * 4];
            float4 bk = *(const float4*)&KsT[kk * QP_ + tx * 4];
            float a4[4] = {aq.x, aq.y, aq.z, aq.w};
            float b4[4] = {bk.x, bk.y, bk.z, bk.w};
#pragma unroll
            for (int i = 0; i < 4; i++)
#pragma unroll
                for (int j = 0; j < 4; j++)
                    sacc[i*4+j] += a4[i] * b4[j];
        }
        bool diag = (kt == lastTile);
#pragma unroll
        for (int i = 0; i < 4; i++)
#pragma unroll
            for (int j = 0; j < 4; j++){
                int qr = ty * 4 + i, kc = tx * 4 + j;
                float s = sacc[i*4+j];
                if (diag && kc > qr) s = -INFINITY;
                SsT[kc * QP_ + qr] = s;
            }
        __syncthreads();

        if (tid < 64){
            int r = tid;
            float mt = -INFINITY;
#pragma unroll 8
            for (int c = 0; c < 64; c++) mt = fmaxf(mt, SsT[c * QP_ + r]);
            float mo = Ms[r];
            float mn = fmaxf(mo, mt);
            float corr = __expf(mo - mn);
            float ls = 0.f;
#pragma unroll 8
            for (int c = 0; c < 64; c++){
                float e = __expf(SsT[c * QP_ + r] - mn);
                SsT[c * QP_ + r] = e;
                ls += e;
            }
            Ls[r] = Ls[r] * corr + ls;
            Ms[r] = mn;
            Cs[r] = corr;
        }
        __syncthreads();

        float cf[4];
#pragma unroll
        for (int i = 0; i < 4; i++) cf[i] = Cs[ty * 4 + i];
#pragma unroll
        for (int i = 0; i < 4; i++)
#pragma unroll
            for (int j = 0; j < 4; j++) oacc[i*4+j] *= cf[i];

#pragma unroll 8
        for (int kk = 0; kk < 64; kk++){
            float4 ap = *(const float4*)&SsT[kk * QP_ + ty * 4];
            float4 vv = *(const float4*)&Vs[kk * QP_ + tx * 4];
            float a4[4] = {ap.x, ap.y, ap.z, ap.w};
            float b4[4] = {vv.x, vv.y, vv.z, vv.w};
#pragma unroll
            for (int i = 0; i < 4; i++)
#pragma unroll
                for (int j = 0; j < 4; j++)
                    oacc[i*4+j] += a4[i] * b4[j];
        }
        __syncthreads();
    }

#pragma unroll
    for (int i = 0; i < 4; i++){
        float inv = 1.0f / Ls[ty * 4 + i];
        long long orow =
            ((long long)(b * N_ + q0 + ty * 4 + i)) * INNER_ + h * 64 + tx * 4;
        float4 vo = make_float4(oacc[i*4+0]*inv, oacc[i*4+1]*inv,
                                oacc[i*4+2]*inv, oacc[i*4+3]*inv);
        *(float4*)&o[orow] = vo;
        bf16 hh, ll;
        split2(vo.x, hh, ll); oh[orow+0] = hh; ol[orow+0] = ll;
        split2(vo.y, hh, ll); oh[orow+1] = hh; ol[orow+1] = ll;
        split2(vo.z, hh, ll); oh[orow+2] = hh; ol[orow+2] = ll;
        split2(vo.w, hh, ll); oh[orow+3] = hh; ol[orow+3] = ll;
    }
}

// ---- launch ----
extern "C" void kernel_launch(void* const* d_in, const int* in_sizes, int n_in,
                              void* d_out, int out_size)
{
    (void)in_sizes; (void)n_in; (void)out_size;
    const float* text  = (const float*)d_in[0];
    const float* audio = (const float*)d_in[1];
    const float* video = (const float*)d_in[2];
    const float* Wa    = (const float*)d_in[3];
    const float* ba    = (const float*)d_in[4];
    const float* lna_g = (const float*)d_in[5];
    const float* lna_b = (const float*)d_in[6];
    const float* Wvid  = (const float*)d_in[7];
    const float* bvid  = (const float*)d_in[8];
    const float* lnv_g = (const float*)d_in[9];
    const float* lnv_b = (const float*)d_in[10];
    const float* ln1_g = (const float*)d_in[11];
    const float* ln1_b = (const float*)d_in[12];
    const float* Wq    = (const float*)d_in[13];
    const float* Wkv   = (const float*)d_in[14];
    const float* qn_g  = (const float*)d_in[15];
    const float* kn_g  = (const float*)d_in[16];
    const float* Wo    = (const float*)d_in[17];
    const float* W1    = (const float*)d_in[18];
    const float* b1    = (const float*)d_in[19];
    const float* ln2_g = (const float*)d_in[20];
    const float* ln2_b = (const float*)d_in[21];
    const float* W2    = (const float*)d_in[22];
    const float* b2    = (const float*)d_in[23];
    float* out = (float*)d_out;

#define SYM(p, s) void* p; cudaGetSymbolAddress(&p, s)
    SYM(at, g_at);   SYM(vt, g_vt);   SYM(probs, g_probs);
    SYM(x, g_x);     SYM(qb, g_q);    SYM(kvb, g_kv);
    SYM(ob, g_o);    SYM(x2, g_x2);   SYM(ff, g_ff);
    SYM(audH, g_audH); SYM(audL, g_audL);
    SYM(vidH, g_vidH); SYM(vidL, g_vidL);
    SYM(qh, g_qh);   SYM(ql, g_ql);
    SYM(kh, g_kh);   SYM(kl, g_kl);
    SYM(vTh, g_vTh); SYM(vTl, g_vTl);
    SYM(ph, g_ph);   SYM(pl, g_pl);
    SYM(hh, g_hh);   SYM(hl, g_hl);
    SYM(obH, g_obH); SYM(obL, g_obL);
    SYM(x2H, g_x2H); SYM(x2L, g_x2L);
    SYM(ffH, g_ffH); SYM(ffL, g_ffL);
    SYM(WaTh, g_WaTh); SYM(WaTl, g_WaTl);
    SYM(WvTh, g_WvTh); SYM(WvTl, g_WvTl);
    SYM(WqTh, g_WqTh); SYM(WqTl, g_WqTl);
    SYM(WkvTh, g_WkvTh); SYM(WkvTl, g_WkvTl);
    SYM(WoTh, g_WoTh); SYM(WoTl, g_WoTl);
    SYM(W1Th, g_W1Th); SYM(W1Tl, g_W1Tl);
    SYM(W2Th, g_W2Th); SYM(W2Tl, g_W2Tl);
#undef SYM

    cudaFuncSetAttribute(gemm_wmma<EPI_NONE>,      cudaFuncAttributeMaxDynamicSharedMemorySize, GEMM_SMEM_DYN);
    cudaFuncSetAttribute(gemm_wmma<EPI_BIAS>,      cudaFuncAttributeMaxDynamicSharedMemorySize, GEMM_SMEM_DYN);
    cudaFuncSetAttribute(gemm_wmma<EPI_BIAS_GELU>, cudaFuncAttributeMaxDynamicSharedMemorySize, GEMM_SMEM_DYN);
    cudaFuncSetAttribute(gemm_wmma<EPI_BIAS_RES>,  cudaFuncAttributeMaxDynamicSharedMemorySize, GEMM_SMEM_DYN);
    cudaFuncSetAttribute(gemm_wmma<EPI_SPLIT>,     cudaFuncAttributeMaxDynamicSharedMemorySize, GEMM_SMEM_DYN);
    cudaFuncSetAttribute(attn_kernel, cudaFuncAttributeMaxDynamicSharedMemorySize, ATTN_SMEM_BYTES);

    dim3 t32(32, 8);

    // weight transposes + splits
    tconv_kernel<<<dim3(32, 32, 1), t32>>>(Wa,  (bf16*)WaTh,  (bf16*)WaTl,  DIM_,     DIM_,  0, 0, 0);
    tconv_kernel<<<dim3(32, 32, 1), t32>>>(Wvid,(bf16*)WvTh,  (bf16*)WvTl,  DIM_,     DIM_,  0, 0, 0);
    tconv_kernel<<<dim3(32, 16, 1), t32>>>(Wq,  (bf16*)WqTh,  (bf16*)WqTl,  INNER_,   DIM_,  0, 0, 0);
    tconv_kernel<<<dim3(32, 32, 1), t32>>>(Wkv, (bf16*)WkvTh, (bf16*)WkvTl, 2*INNER_, DIM_,  0, 0, 0);
    tconv_kernel<<<dim3(16, 32, 1), t32>>>(Wo,  (bf16*)WoTh,  (bf16*)WoTl,  DIM_,     INNER_,0, 0, 0);
    tconv_kernel<<<dim3(32, 128,1), t32>>>(W1,  (bf16*)W1Th,  (bf16*)W1Tl,  FF_,      DIM_,  0, 0, 0);
    tconv_kernel<<<dim3(128,32, 1), t32>>>(W2,  (bf16*)W2Th,  (bf16*)W2Tl,  DIM_,     FF_,   0, 0, 0);
    // input splits
    conv_kernel<<<BN_*DIM_/1024, 256>>>(audio, (bf16*)audH, (bf16*)audL, BN_*DIM_);
    conv_kernel<<<BN_*DIM_/1024, 256>>>(video, (bf16*)vidH, (bf16*)vidL, BN_*DIM_);

    // 1) adapters
    gemm_wmma<EPI_BIAS><<<dim3(DIM_/128, BN_/128, 1), 256, GEMM_SMEM_DYN>>>(
        (bf16*)audH, (bf16*)audL, (bf16*)WaTh, (bf16*)WaTl, (float*)at, ba, nullptr,
        nullptr, nullptr, DIM_, DIM_, DIM_, DIM_, 1.f, 1, 0,0,0,0,0,0);
    gemm_wmma<EPI_BIAS><<<dim3(DIM_/128, BN_/128, 1), 256, GEMM_SMEM_DYN>>>(
        (bf16*)vidH, (bf16*)vidL, (bf16*)WvTh, (bf16*)WvTl, (float*)vt, bvid, nullptr,
        nullptr, nullptr, DIM_, DIM_, DIM_, DIM_, 1.f, 1, 0,0,0,0,0,0);
    ln_kernel<<<BN_, 256>>>((float*)at, (float*)at, lna_g, lna_b, DIM_);
    ln_kernel<<<BN_, 256>>>((float*)vt, (float*)vt, lnv_g, lnv_b, DIM_);

    // 2) rotary + padded layouts; v transposed per batch with front pad
    prep_kernel<<<B_ * NP_, 256>>>(text, (float*)at,
        (bf16*)qh, (bf16*)ql, (bf16*)kh, (bf16*)kl);
    tconv_kernel<<<dim3(NP_/32, DIM_/32, B_), t32>>>((float*)vt,
        (bf16*)vTh, (bf16*)vTl, DIM_, NP_, WS_,
        (long long)N_*DIM_, (long long)DIM_*NP_);

    // 3) local attention (8 windows batched)
    gemm_wmma<EPI_NONE><<<dim3((2*WS_)/128, WS_/128, B_*NWIN_), 256, GEMM_SMEM_DYN>>>(
        (bf16*)qh, (bf16*)ql, (bf16*)kh, (bf16*)kl, (float*)probs, nullptr, nullptr,
        nullptr, nullptr, DIM_, DIM_, DIM_, 2*WS_, 0.03125f, NWIN_,
        (long long)N_*DIM_,  (long long)WS_*DIM_,
        (long long)NP_*DIM_, (long long)WS_*DIM_,
        (long long)NWIN_*WS_*2*WS_, (long long)WS_*2*WS_);
    softmax_local_kernel<<<B_*NWIN_*WS_, 256>>>((float*)probs, (bf16*)ph, (bf16*)pl);
    gemm_wmma<EPI_NONE><<<dim3(DIM_/128, WS_/128, B_*NWIN_), 256, GEMM_SMEM_DYN>>>(
        (bf16*)ph, (bf16*)pl, (bf16*)vTh, (bf16*)vTl, (float*)x, nullptr, nullptr,
        nullptr, nullptr, 2*WS_, 2*WS_, NP_, DIM_, 1.f, NWIN_,
        (long long)NWIN_*WS_*2*WS_, (long long)WS_*2*WS_,
        (long long)DIM_*NP_, (long long)WS_,
        (long long)N_*DIM_, (long long)WS_*DIM_);

    // 4) ln1 -> projections -> rmsnorm
    ln_bf_kernel<<<BN_, 256>>>((float*)x, (bf16*)hh, (bf16*)hl, ln1_g, ln1_b, DIM_);
    gemm_wmma<EPI_NONE><<<dim3(INNER_/128, BN_/128, 1), 256, GEMM_SMEM_DYN>>>(
        (bf16*)hh, (bf16*)hl, (bf16*)WqTh, (bf16*)WqTl, (float*)qb, nullptr, nullptr,
        nullptr, nullptr, DIM_, DIM_, DIM_, INNER_, 1.f, 1, 0,0,0,0,0,0);
    gemm_wmma<EPI_NONE><<<dim3((2*INNER_)/128, BN_/128, 1), 256, GEMM_SMEM_DYN>>>(
        (bf16*)hh, (bf16*)hl, (bf16*)WkvTh, (bf16*)WkvTl, (float*)kvb, nullptr, nullptr,
        nullptr, nullptr, DIM_, DIM_, DIM_, 2*INNER_, 1.f, 1, 0,0,0,0,0,0);
    rms_kernel<<<(BN_*HEADS_)/8, 256>>>((float*)qb, qn_g, HEADS_, INNER_, BN_);
    rms_kernel<<<(BN_*HEADS_)/8, 256>>>((float*)kvb, kn_g, HEADS_, 2*INNER_, BN_);

    // 5) causal attention (emits fp32 + bf16 hi/lo)
    attn_kernel<<<dim3(N_/64, B_*HEADS_), 256, ATTN_SMEM_BYTES>>>(
        (float*)qb, (float*)kvb, (float*)ob, (bf16*)obH, (bf16*)obL);

    // 6) x2 = 2*(o @ Wo), epilogue emits x2 fp32 + hi/lo split
    gemm_wmma<EPI_SPLIT><<<dim3(DIM_/128, BN_/128, 1), 256, GEMM_SMEM_DYN>>>(
        (bf16*)obH, (bf16*)obL, (bf16*)WoTh, (bf16*)WoTl, (float*)x2, nullptr, nullptr,
        (bf16*)x2H, (bf16*)x2L, INNER_, INNER_, INNER_, DIM_, 2.f, 1, 0,0,0,0,0,0);

    // 7) FFN
    gemm_wmma<EPI_BIAS_GELU><<<dim3(FF_/128, BN_/128, 1), 256, GEMM_SMEM_DYN>>>(
        (bf16*)x2H, (bf16*)x2L, (bf16*)W1Th, (bf16*)W1Tl, (float*)ff, b1, nullptr,
        nullptr, nullptr, DIM_, DIM_, DIM_, FF_, 1.f, 1, 0,0,0,0,0,0);
    ln_bf_kernel<<<BN_, 256>>>((float*)ff, (bf16*)ffH, (bf16*)ffL, ln2_g, ln2_b, FF_);
    gemm_wmma<EPI_BIAS_RES><<<dim3(DIM_/128, BN_/128, 1), 256, GEMM_SMEM_DYN>>>(
        (bf16*)ffH, (bf16*)ffL, (bf16*)W2Th, (bf16*)W2Tl, out, b2, (float*)x2,
        nullptr, nullptr, FF_, FF_, FF_, DIM_, 1.f, 1, 0,0,0,0,0,0);
}

// round 11
// speedup vs baseline: 1.2516x; 1.2516x over previous
#include <cuda_runtime.h>
#include <cuda_bf16.h>
#include <mma.h>
#include <math.h>
#include <stdint.h>

using namespace nvcuda;
typedef __nv_bfloat16 bf16;

#define B_      2
#define N_      2048
#define DIM_    1024
#define INNER_  512
#define HEADS_  8
#define DHEAD_  64
#define WS_     512
#define FF_     4096
#define BN_     (B_*N_)
#define NP_     (N_+WS_)
#define NWIN_   (N_/WS_)

// ---- fp32 scratch ----
__device__ float g_at [BN_*DIM_];
__device__ float g_vt [BN_*DIM_];
__device__ float g_probs[B_*NWIN_*WS_*2*WS_];
__device__ float g_x  [BN_*DIM_];
__device__ float g_q  [BN_*INNER_];
__device__ float g_kv [BN_*2*INNER_];
__device__ float g_o  [BN_*INNER_];
__device__ float g_x2 [BN_*DIM_];
__device__ float g_ff [BN_*FF_];

// ---- bf16 hi/lo scratch ----
__device__ bf16 g_audH[BN_*DIM_],  g_audL[BN_*DIM_];
__device__ bf16 g_vidH[BN_*DIM_],  g_vidL[BN_*DIM_];
__device__ bf16 g_qh [BN_*DIM_],   g_ql [BN_*DIM_];
__device__ bf16 g_kh [B_*NP_*DIM_],g_kl [B_*NP_*DIM_];
__device__ bf16 g_vTh[B_*DIM_*NP_],g_vTl[B_*DIM_*NP_];
__device__ bf16 g_ph [B_*NWIN_*WS_*2*WS_], g_pl[B_*NWIN_*WS_*2*WS_];
__device__ bf16 g_hh [BN_*DIM_],   g_hl [BN_*DIM_];
__device__ bf16 g_obH[BN_*INNER_], g_obL[BN_*INNER_];
__device__ bf16 g_x2H[BN_*DIM_],   g_x2L[BN_*DIM_];
__device__ bf16 g_ffH[BN_*FF_],    g_ffL[BN_*FF_];
__device__ bf16 g_WaTh [DIM_*DIM_],   g_WaTl [DIM_*DIM_];
__device__ bf16 g_WvTh [DIM_*DIM_],   g_WvTl [DIM_*DIM_];
__device__ bf16 g_WqTh [INNER_*DIM_], g_WqTl [INNER_*DIM_];
__device__ bf16 g_WkvTh[2*INNER_*DIM_],g_WkvTl[2*INNER_*DIM_];
__device__ bf16 g_WoTh [DIM_*INNER_], g_WoTl [DIM_*INNER_];
__device__ bf16 g_W1Th [FF_*DIM_],    g_W1Tl [FF_*DIM_];
__device__ bf16 g_W2Th [DIM_*FF_],    g_W2Tl [DIM_*FF_];

// ---- helpers ----
__device__ __forceinline__ uint32_t s2u(const void* p){
    uint32_t a;
    asm("{ .reg .u64 t; cvta.to.shared.u64 t, %1; cvt.u32.u64 %0, t; }"
        : "=r"(a) : "l"(p));
    return a;
}
__device__ __forceinline__ void cpa16(uint32_t d, const void* s){
    asm volatile("cp.async.cg.shared.global [%0], [%1], 16;" :: "r"(d), "l"(s));
}
__device__ __forceinline__ void cpa_commit(){
    asm volatile("cp.async.commit_group;" ::: "memory");
}
__device__ __forceinline__ void cpa_wait0(){
    asm volatile("cp.async.wait_group 0;" ::: "memory");
}
__device__ __forceinline__ void cpa_wait1(){
    asm volatile("cp.async.wait_group 1;" ::: "memory");
}
__device__ __forceinline__ void split2(float v, bf16& h, bf16& l){
    h = __float2bfloat16(v);
    l = __float2bfloat16(v - __bfloat162float(h));
}
__device__ __forceinline__ float gelu_tanh(float v){
    float c = v + 0.044715f * v * v * v;
    return 0.5f * v * (1.0f + tanhf(0.7978845608028654f * c));
}

// ---- bf16x3 wmma GEMM: 128x128 tile, warp 64x32, BK=32 (R9 config) ----
#define LDSB 40
#define MATB (128*LDSB*2)          // 10240 bytes per matrix per stage
#define AH_OFF 0
#define AL_OFF MATB
#define BH_OFF (2*MATB)
#define BL_OFF (3*MATB)
#define STGB  (4*MATB)             // 40960 per stage
#define GEMM_SMEM_DYN (2*STGB)     // 81920

#define EPI_NONE       0
#define EPI_BIAS       1
#define EPI_BIAS_GELU  2
#define EPI_BIAS_RES   3
#define EPI_SPLIT      4          // alpha, write fp32 C + bf16 hi/lo

template<int EPI>
__global__ void __launch_bounds__(256, 1)
gemm_wmma(const bf16* __restrict__ Ah, const bf16* __restrict__ Al,
          const bf16* __restrict__ Bh, const bf16* __restrict__ Bl,
          float* __restrict__ C, const float* __restrict__ bias,
          const float* __restrict__ res,
          bf16* __restrict__ Ch, bf16* __restrict__ Cl,
          int K, int lda, int ldb, int ldc, float alpha, int wdiv,
          long long sAb, long long sAw, long long sBb, long long sBw,
          long long sCb, long long sCw)
{
    extern __shared__ char dsm[];
    uint32_t sb0 = s2u(dsm);

    int tid = threadIdx.x;
    int wid = tid >> 5;
    int wm = wid >> 2;          // 0..1
    int wn = wid & 3;           // 0..3
    int z = blockIdx.z;
    int zb = z / wdiv, zw = z - zb * wdiv;
    long long aoff = zb * sAb + zw * sAw;
    long long boff = zb * sBb + zw * sBw;
    long long coff = zb * sCb + zw * sCw;
    Ah += aoff; Al += aoff;
    Bh += boff; Bl += boff;
    C  += coff;
    const float* Rp = (EPI == EPI_BIAS_RES) ? (res + coff) : nullptr;

    int m0 = blockIdx.y * 128;
    int n0 = blockIdx.x * 128;

    wmma::fragment<wmma::accumulator, 16, 16, 16, float> acc[4][2];
#pragma unroll
    for (int i = 0; i < 4; i++)
#pragma unroll
        for (int j = 0; j < 2; j++) wmma::fill_fragment(acc[i][j], 0.f);

    auto loadStage = [&](int stg, int kk){
        uint32_t sb = sb0 + stg * STGB;
#pragma unroll
        for (int half = 0; half < 2; half++){
            int i = tid + half * 256;           // 0..511
            int row = i >> 2, ch = i & 3;
            uint32_t d = row * (LDSB*2) + ch * 16;
            long long ga = (long long)(m0 + row) * lda + kk + ch * 8;
            long long gb = (long long)(n0 + row) * ldb + kk + ch * 8;
            cpa16(sb + AH_OFF + d, Ah + ga);
            cpa16(sb + AL_OFF + d, Al + ga);
            cpa16(sb + BH_OFF + d, Bh + gb);
            cpa16(sb + BL_OFF + d, Bl + gb);
        }
    };

    int KT = K >> 5;
    loadStage(0, 0);
    cpa_commit();

    for (int kt = 0; kt < KT; kt++){
        if (kt + 1 < KT){
            loadStage((kt + 1) & 1, (kt + 1) * 32);
            cpa_commit();
            cpa_wait1();
        } else {
            cpa_wait0();
        }
        __syncthreads();

        const bf16* st = (const bf16*)(dsm + (kt & 1) * STGB);
        const bf16* pAh = st + (AH_OFF/2) + (wm*64)*LDSB;
        const bf16* pAl = st + (AL_OFF/2) + (wm*64)*LDSB;
        const bf16* pBh = st + (BH_OFF/2) + (wn*32)*LDSB;
        const bf16* pBl = st + (BL_OFF/2) + (wn*32)*LDSB;
#pragma unroll
        for (int ks = 0; ks < 2; ks++){
            wmma::fragment<wmma::matrix_a, 16,16,16, bf16, wmma::row_major> fAh[4], fAl[4];
            wmma::fragment<wmma::matrix_b, 16,16,16, bf16, wmma::col_major> fBh[2], fBl[2];
#pragma unroll
            for (int i = 0; i < 4; i++){
                wmma::load_matrix_sync(fAh[i], pAh + i*16*LDSB + ks*16, LDSB);
                wmma::load_matrix_sync(fAl[i], pAl + i*16*LDSB + ks*16, LDSB);
            }
#pragma unroll
            for (int j = 0; j < 2; j++){
                wmma::load_matrix_sync(fBh[j], pBh + j*16*LDSB + ks*16, LDSB);
                wmma::load_matrix_sync(fBl[j], pBl + j*16*LDSB + ks*16, LDSB);
            }
#pragma unroll
            for (int i = 0; i < 4; i++)
#pragma unroll
                for (int j = 0; j < 2; j++){
                    wmma::mma_sync(acc[i][j], fAh[i], fBh[j], acc[i][j]);
                    wmma::mma_sync(acc[i][j], fAh[i], fBl[j], acc[i][j]);
                    wmma::mma_sync(acc[i][j], fAl[i], fBh[j], acc[i][j]);
                }
        }
        __syncthreads();
    }

    // ---- block-wide epilogue via smem float staging (R9 shape) ----
    float* sF = (float*)dsm;
#pragma unroll
    for (int i = 0; i < 4; i++)
#pragma unroll
        for (int j = 0; j < 2; j++)
            wmma::store_matrix_sync(
                sF + (wm*64 + i*16) * 128 + wn*32 + j*16,
                acc[i][j], 128, wmma::mem_row_major);
    __syncthreads();

#pragma unroll 1
    for (int t = 0; t < 16; t++){
        int i = tid + t * 256;              // 0..4095 float4s
        int row = i >> 5, c4 = (i & 31) * 4;
        float4 v = *(float4*)&sF[row * 128 + c4];
        v.x *= alpha; v.y *= alpha; v.z *= alpha; v.w *= alpha;
        int gc = n0 + c4;
        if (EPI == EPI_BIAS || EPI == EPI_BIAS_GELU || EPI == EPI_BIAS_RES){
            float4 bb = *(const float4*)&bias[gc];
            v.x += bb.x; v.y += bb.y; v.z += bb.z; v.w += bb.w;
        }
        if (EPI == EPI_BIAS_GELU){
            v.x = gelu_tanh(v.x); v.y = gelu_tanh(v.y);
            v.z = gelu_tanh(v.z); v.w = gelu_tanh(v.w);
        }
        long long crow = (long long)(m0 + row) * ldc + gc;
        if (EPI == EPI_BIAS_RES){
            float4 rr = *(const float4*)&Rp[crow];
            v.x += rr.x; v.y += rr.y; v.z += rr.z; v.w += rr.w;
        }
        *(float4*)&C[crow] = v;
        if (EPI == EPI_SPLIT){
            long long so = coff + crow;
            bf16 hh, ll;
            split2(v.x, hh, ll); Ch[so+0] = hh; Cl[so+0] = ll;
            split2(v.y, hh, ll); Ch[so+1] = hh; Cl[so+1] = ll;
            split2(v.z, hh, ll); Ch[so+2] = hh; Cl[so+2] = ll;
            split2(v.w, hh, ll); Ch[so+3] = hh; Cl[so+3] = ll;
        }
    }
}

// ---- LayerNorm fp32 out ----
__global__ void ln_kernel(const float* __restrict__ x, float* __restrict__ y,
                          const float* __restrict__ g, const float* __restrict__ bv,
                          int L)
{
    __shared__ float buf[4096];
    __shared__ float r1[8], r2[8], st[2];
    long long row = blockIdx.x;
    const float* xr = x + row * L;
    int tid = threadIdx.x;
    float s = 0.f, s2 = 0.f;
    for (int c = tid; c < L; c += 256){ float v = xr[c]; buf[c] = v; s += v; s2 += v*v; }
#pragma unroll
    for (int o = 16; o > 0; o >>= 1){
        s  += __shfl_xor_sync(0xffffffffu, s,  o);
        s2 += __shfl_xor_sync(0xffffffffu, s2, o);
    }
    int lane = tid & 31, w = tid >> 5;
    if (lane == 0){ r1[w] = s; r2[w] = s2; }
    __syncthreads();
    if (tid == 0){
        float ts = 0.f, ts2 = 0.f;
        for (int k = 0; k < 8; k++){ ts += r1[k]; ts2 += r2[k]; }
        float mean = ts / (float)L;
        st[0] = mean; st[1] = rsqrtf(ts2 / (float)L - mean*mean + 1e-5f);
    }
    __syncthreads();
    float mean = st[0], rstd = st[1];
    float* yr = y + row * L;
    for (int c = tid; c < L; c += 256)
        yr[c] = (buf[c] - mean) * rstd * g[c] + bv[c];
}

// ---- LayerNorm -> bf16 hi/lo ----
__global__ void ln_bf_kernel(const float* __restrict__ x, bf16* __restrict__ yh,
                             bf16* __restrict__ yl,
                             const float* __restrict__ g, const float* __restrict__ bv,
                             int L)
{
    __shared__ float buf[4096];
    __shared__ float r1[8], r2[8], st[2];
    long long row = blockIdx.x;
    const float* xr = x + row * L;
    int tid = threadIdx.x;
    float s = 0.f, s2 = 0.f;
    for (int c = tid; c < L; c += 256){ float v = xr[c]; buf[c] = v; s += v; s2 += v*v; }
#pragma unroll
    for (int o = 16; o > 0; o >>= 1){
        s  += __shfl_xor_sync(0xffffffffu, s,  o);
        s2 += __shfl_xor_sync(0xffffffffu, s2, o);
    }
    int lane = tid & 31, w = tid >> 5;
    if (lane == 0){ r1[w] = s; r2[w] = s2; }
    __syncthreads();
    if (tid == 0){
        float ts = 0.f, ts2 = 0.f;
        for (int k = 0; k < 8; k++){ ts += r1[k]; ts2 += r2[k]; }
        float mean = ts / (float)L;
        st[0] = mean; st[1] = rsqrtf(ts2 / (float)L - mean*mean + 1e-5f);
    }
    __syncthreads();
    float mean = st[0], rstd = st[1];
    for (int c = tid; c < L; c += 256){
        float v = (buf[c] - mean) * rstd * g[c] + bv[c];
        bf16 h, l; split2(v, h, l);
        yh[row * L + c] = h; yl[row * L + c] = l;
    }
}

// ---- RMSNorm over 64-dim head vectors ----
__global__ void rms_kernel(float* __restrict__ x, const float* __restrict__ g,
                           int vecs_per_row, int row_stride, int nrows)
{
    int vid = blockIdx.x * 8 + (threadIdx.x >> 5);
    int lane = threadIdx.x & 31;
    int r = vid / vecs_per_row;
    int h = vid - r * vecs_per_row;
    if (r >= nrows) return;
    float* p = x + (long long)r * row_stride + h * DHEAD_;
    float v0 = p[lane], v1 = p[lane + 32];
    float ss = v0*v0 + v1*v1;
#pragma unroll
    for (int o = 16; o > 0; o >>= 1) ss += __shfl_xor_sync(0xffffffffu, ss, o);
    float rs = rsqrtf(ss * (1.0f/64.0f) + 1e-6f);
    p[lane]      = v0 * rs * g[lane];
    p[lane + 32] = v1 * rs * g[lane + 32];
}

// ---- rotary prep -> bf16 hi/lo ----
__global__ void prep_kernel(const float* __restrict__ text,
                            const float* __restrict__ at,
                            bf16* __restrict__ qh, bf16* __restrict__ ql,
                            bf16* __restrict__ kh, bf16* __restrict__ kl)
{
    int row = blockIdx.x;
    int b = row / NP_;
    int pr = row - b * NP_;
    long long kout = (long long)row * DIM_;
    if (pr < WS_){
        bf16 zz = __float2bfloat16(0.f);
        for (int c = threadIdx.x; c < DIM_; c += 256){ kh[kout+c] = zz; kl[kout+c] = zz; }
        return;
    }
    int t = pr - WS_;
    long long src = ((long long)b * N_ + t) * DIM_;
    for (int c = threadIdx.x; c < DIM_; c += 256){
        int j = c & 511;
        float invf = exp2f((float)j * (-13.28771238f * (1.0f/512.0f)));
        float ang = (float)t * invf;
        float cs = cosf(ang), sn = sinf(ang);
        float kx = at[src + c];
        float ko = (c < 512) ? -at[src + c + 512] : at[src + c - 512];
        bf16 h, l;
        split2(kx * cs + ko * sn, h, l);
        kh[kout + c] = h; kl[kout + c] = l;
        float qx = text[src + c];
        float qo = (c < 512) ? -text[src + c + 512] : text[src + c - 512];
        split2(qx * cs + qo * sn, h, l);
        qh[src + c] = h; ql[src + c] = l;
    }
}

// ---- transpose + split ----
__global__ void tconv_kernel(const float* __restrict__ in, bf16* __restrict__ oh,
                             bf16* __restrict__ ol,
                             int inLd, int outLd, int pad,
                             long long inB, long long outB)
{
    __shared__ float t[32][33];
    in += blockIdx.z * inB;
    oh += blockIdx.z * outB;
    ol += blockIdx.z * outB;
    int p0 = blockIdx.x * 32, c0 = blockIdx.y * 32;
    int tx = threadIdx.x, ty = threadIdx.y;
    for (int i = ty; i < 32; i += 8){
        int r = p0 + i - pad;
        t[i][tx] = (r >= 0) ? in[(long long)r * inLd + c0 + tx] : 0.f;
    }
    __syncthreads();
    for (int i = ty; i < 32; i += 8){
        float v = t[tx][i];
        bf16 h, l; split2(v, h, l);
        long long o = (long long)(c0 + i) * outLd + p0 + tx;
        oh[o] = h; ol[o] = l;
    }
}

// ---- elementwise split fp32 -> bf16 hi/lo ----
__global__ void conv_kernel(const float* __restrict__ x, bf16* __restrict__ h,
                            bf16* __restrict__ l, int n)
{
    int i = (blockIdx.x * 256 + threadIdx.x) * 4;
    if (i < n){
        float4 v = *(const float4*)&x[i];
        bf16 hh, ll;
        split2(v.x, hh, ll); h[i+0] = hh; l[i+0] = ll;
        split2(v.y, hh, ll); h[i+1] = hh; l[i+1] = ll;
        split2(v.z, hh, ll); h[i+2] = hh; l[i+2] = ll;
        split2(v.w, hh, ll); h[i+3] = hh; l[i+3] = ll;
    }
}

// ---- local-attention masked softmax -> bf16 hi/lo ----
__global__ void softmax_local_kernel(const float* __restrict__ p,
                                     bf16* __restrict__ ph, bf16* __restrict__ pl)
{
    __shared__ float buf[1024];
    __shared__ float red[8], bc[2];
    int r = blockIdx.x;
    int i = r & (WS_ - 1);
    int z = r >> 9;
    int w = z & (NWIN_ - 1);
    int qp = w * WS_ + i;
    const float* row = p + (long long)r * (2 * WS_);
    int tid = threadIdx.x, lane = tid & 31, wp = tid >> 5;

    float mx = -1e30f;
    for (int j = tid; j < 2*WS_; j += 256){
        int kp = (w - 1) * WS_ + j;
        float v = (kp >= 0 && kp <= qp) ? row[j] : -1e9f;
        buf[j] = v;
        mx = fmaxf(mx, v);
    }
#pragma unroll
    for (int o = 16; o > 0; o >>= 1) mx = fmaxf(mx, __shfl_xor_sync(0xffffffffu, mx, o));
    if (lane == 0) red[wp] = mx;
    __syncthreads();
    if (tid == 0){
        float m = red[0];
        for (int k = 1; k < 8; k++) m = fmaxf(m, red[k]);
        bc[0] = m;
    }
    __syncthreads();
    mx = bc[0];
    float sum = 0.f;
    for (int j = tid; j < 2*WS_; j += 256){
        float e = __expf(buf[j] - mx);
        buf[j] = e; sum += e;
    }
#pragma unroll
    for (int o = 16; o > 0; o >>= 1) sum += __shfl_xor_sync(0xffffffffu, sum, o);
    if (lane == 0) red[wp] = sum;
    __syncthreads();
    if (tid == 0){
        float t = 0.f;
        for (int k = 0; k < 8; k++) t += red[k];
        bc[1] = 1.0f / t;
    }
    __syncthreads();
    float inv = bc[1];
    for (int j = tid; j < 2*WS_; j += 256){
        bf16 h, l; split2(buf[j] * inv, h, l);
        long long o = (long long)r * (2*WS_) + j;
        ph[o] = h; pl[o] = l;
    }
}

// ---- causal flash attention fp32 (per head, D=64), emits hi/lo too ----
#define QP_ 68
#define ATTN_SMEM_BYTES (4 * 64 * QP_ * 4 + 3 * 64 * 4)

__global__ void __launch_bounds__(256)
attn_kernel(const float* __restrict__ q, const float* __restrict__ kv,
            float* __restrict__ o, bf16* __restrict__ oh, bf16* __restrict__ ol)
{
    extern __shared__ float sm[];
    float* QsT = sm;
    float* KsT = QsT + 64 * QP_;
    float* Vs  = KsT + 64 * QP_;
    float* SsT = Vs  + 64 * QP_;
    float* Ms = SsT + 64 * QP_;
    float* Ls = Ms + 64;
    float* Cs = Ls + 64;

    int tid = threadIdx.x;
    int bh = blockIdx.y;
    int b = bh >> 3, h = bh & 7;
    int q0 = blockIdx.x * 64;
    int ty = tid >> 4, tx = tid & 15;

    for (int idx = tid; idx < 4096; idx += 256){
        int r = idx >> 6, c = idx & 63;
        QsT[c * QP_ + r] =
            q[((long long)(b * N_ + q0 + r)) * INNER_ + h * 64 + c] * 0.125f;
    }
    if (tid < 64){ Ms[tid] = -INFINITY; Ls[tid] = 0.f; }
    float oacc[16];
#pragma unroll
    for (int i = 0; i < 16; i++) oacc[i] = 0.f;
    __syncthreads();

    int lastTile = blockIdx.x;
    for (int kt = 0; kt <= lastTile; kt++){
        for (int idx = tid; idx < 4096; idx += 256){
            int r = idx >> 6, c = idx & 63;
            long long base =
                ((long long)(b * N_ + kt * 64 + r)) * (2 * INNER_) + h * 64 + c;
            KsT[c * QP_ + r] = kv[base];
            Vs[r * QP_ + c]  = kv[base + INNER_];
        }
        __syncthreads();

        float sacc[16];
#pragma unroll
        for (int i = 0; i < 16; i++) sacc[i] = 0.f;
#pragma unroll 8
        for (int kk = 0; kk < 64; kk++){
            float4 aq = *(const float4*)&QsT[kk * QP_ + ty * 4];
            float4 bk = *(const float4*)&KsT[kk * QP_ + tx * 4];
            float a4[4] = {aq.x, aq.y, aq.z, aq.w};
            float b4[4] = {bk.x, bk.y, bk.z, bk.w};
#pragma unroll
            for (int i = 0; i < 4; i++)
#pragma unroll
                for (int j = 0; j < 4; j++)
                    sacc[i*4+j] += a4[i] * b4[j];
        }
        bool diag = (kt == lastTile);
#pragma unroll
        for (int i = 0; i < 4; i++)
#pragma unroll
            for (int j = 0; j < 4; j++){
                int qr = ty * 4 + i, kc = tx * 4 + j;
                float s = sacc[i*4+j];
                if (diag && kc > qr) s = -INFINITY;
                SsT[kc * QP_ + qr] = s;
            }
        __syncthreads();

        if (tid < 64){
            int r = tid;
            float mt = -INFINITY;
#pragma unroll 8
            for (int c = 0; c < 64; c++) mt = fmaxf(mt, SsT[c * QP_ + r]);
            float mo = Ms[r];
            float mn = fmaxf(mo, mt);
            float corr = __expf(mo - mn);
            float ls = 0.f;
#pragma unroll 8
            for (int c = 0; c < 64; c++){
                float e = __expf(SsT[c * QP_ + r] - mn);
                SsT[c * QP_ + r] = e;
                ls += e;
            }
            Ls[r] = Ls[r] * corr + ls;
            Ms[r] = mn;
            Cs[r] = corr;
        }
        __syncthreads();

        float cf[4];
#pragma unroll
        for (int i = 0; i < 4; i++) cf[i] = Cs[ty * 4 + i];
#pragma unroll
        for (int i = 0; i < 4; i++)
#pragma unroll
            for (int j = 0; j < 4; j++) oacc[i*4+j] *= cf[i];

#pragma unroll 8
        for (int kk = 0; kk < 64; kk++){
            float4 ap = *(const float4*)&SsT[kk * QP_ + ty * 4];
            float4 vv = *(const float4*)&Vs[kk * QP_ + tx * 4];
            float a4[4] = {ap.x, ap.y, ap.z, ap.w};
            float b4[4] = {vv.x, vv.y, vv.z, vv.w};
#pragma unroll
            for (int i = 0; i < 4; i++)
#pragma unroll
                for (int j = 0; j < 4; j++)
                    oacc[i*4+j] += a4[i] * b4[j];
        }
        __syncthreads();
    }

#pragma unroll
    for (int i = 0; i < 4; i++){
        float inv = 1.0f / Ls[ty * 4 + i];
        long long orow =
            ((long long)(b * N_ + q0 + ty * 4 + i)) * INNER_ + h * 64 + tx * 4;
        float4 vo = make_float4(oacc[i*4+0]*inv, oacc[i*4+1]*inv,
                                oacc[i*4+2]*inv, oacc[i*4+3]*inv);
        *(float4*)&o[orow] = vo;
        bf16 hh, ll;
        split2(vo.x, hh, ll); oh[orow+0] = hh; ol[orow+0] = ll;
        split2(vo.y, hh, ll); oh[orow+1] = hh; ol[orow+1] = ll;
        split2(vo.z, hh, ll); oh[orow+2] = hh; ol[orow+2] = ll;
        split2(vo.w, hh, ll); oh[orow+3] = hh; ol[orow+3] = ll;
    }
}

// ---- launch ----
extern "C" void kernel_launch(void* const* d_in, const int* in_sizes, int n_in,
                              void* d_out, int out_size)
{
    (void)in_sizes; (void)n_in; (void)out_size;
    const float* text  = (const float*)d_in[0];
    const float* audio = (const float*)d_in[1];
    const float* video = (const float*)d_in[2];
    const float* Wa    = (const float*)d_in[3];
    const float* ba    = (const float*)d_in[4];
    const float* lna_g = (const float*)d_in[5];
    const float* lna_b = (const float*)d_in[6];
    const float* Wvid  = (const float*)d_in[7];
    const float* bvid  = (const float*)d_in[8];
    const float* lnv_g = (const float*)d_in[9];
    const float* lnv_b = (const float*)d_in[10];
    const float* ln1_g = (const float*)d_in[11];
    const float* ln1_b = (const float*)d_in[12];
    const float* Wq    = (const float*)d_in[13];
    const float* Wkv   = (const float*)d_in[14];
    const float* qn_g  = (const float*)d_in[15];
    const float* kn_g  = (const float*)d_in[16];
    const float* Wo    = (const float*)d_in[17];
    const float* W1    = (const float*)d_in[18];
    const float* b1    = (const float*)d_in[19];
    const float* ln2_g = (const float*)d_in[20];
    const float* ln2_b = (const float*)d_in[21];
    const float* W2    = (const float*)d_in[22];
    const float* b2    = (const float*)d_in[23];
    float* out = (float*)d_out;

#define SYM(p, s) void* p; cudaGetSymbolAddress(&p, s)
    SYM(at, g_at);   SYM(vt, g_vt);   SYM(probs, g_probs);
    SYM(x, g_x);     SYM(qb, g_q);    SYM(kvb, g_kv);
    SYM(ob, g_o);    SYM(x2, g_x2);   SYM(ff, g_ff);
    SYM(audH, g_audH); SYM(audL, g_audL);
    SYM(vidH, g_vidH); SYM(vidL, g_vidL);
    SYM(qh, g_qh);   SYM(ql, g_ql);
    SYM(kh, g_kh);   SYM(kl, g_kl);
    SYM(vTh, g_vTh); SYM(vTl, g_vTl);
    SYM(ph, g_ph);   SYM(pl, g_pl);
    SYM(hh, g_hh);   SYM(hl, g_hl);
    SYM(obH, g_obH); SYM(obL, g_obL);
    SYM(x2H, g_x2H); SYM(x2L, g_x2L);
    SYM(ffH, g_ffH); SYM(ffL, g_ffL);
    SYM(WaTh, g_WaTh); SYM(WaTl, g_WaTl);
    SYM(WvTh, g_WvTh); SYM(WvTl, g_WvTl);
    SYM(WqTh, g_WqTh); SYM(WqTl, g_WqTl);
    SYM(WkvTh, g_WkvTh); SYM(WkvTl, g_WkvTl);
    SYM(WoTh, g_WoTh); SYM(WoTl, g_WoTl);
    SYM(W1Th, g_W1Th); SYM(W1Tl, g_W1Tl);
    SYM(W2Th, g_W2Th); SYM(W2Tl, g_W2Tl);
#undef SYM

    cudaFuncSetAttribute(gemm_wmma<EPI_NONE>,      cudaFuncAttributeMaxDynamicSharedMemorySize, GEMM_SMEM_DYN);
    cudaFuncSetAttribute(gemm_wmma<EPI_BIAS>,      cudaFuncAttributeMaxDynamicSharedMemorySize, GEMM_SMEM_DYN);
    cudaFuncSetAttribute(gemm_wmma<EPI_BIAS_GELU>, cudaFuncAttributeMaxDynamicSharedMemorySize, GEMM_SMEM_DYN);
    cudaFuncSetAttribute(gemm_wmma<EPI_BIAS_RES>,  cudaFuncAttributeMaxDynamicSharedMemorySize, GEMM_SMEM_DYN);
    cudaFuncSetAttribute(gemm_wmma<EPI_SPLIT>,     cudaFuncAttributeMaxDynamicSharedMemorySize, GEMM_SMEM_DYN);
    cudaFuncSetAttribute(attn_kernel, cudaFuncAttributeMaxDynamicSharedMemorySize, ATTN_SMEM_BYTES);

    dim3 t32(32, 8);

    // weight transposes + splits
    tconv_kernel<<<dim3(32, 32, 1), t32>>>(Wa,  (bf16*)WaTh,  (bf16*)WaTl,  DIM_,     DIM_,  0, 0, 0);
    tconv_kernel<<<dim3(32, 32, 1), t32>>>(Wvid,(bf16*)WvTh,  (bf16*)WvTl,  DIM_,     DIM_,  0, 0, 0);
    tconv_kernel<<<dim3(32, 16, 1), t32>>>(Wq,  (bf16*)WqTh,  (bf16*)WqTl,  INNER_,   DIM_,  0, 0, 0);
    tconv_kernel<<<dim3(32, 32, 1), t32>>>(Wkv, (bf16*)WkvTh, (bf16*)WkvTl, 2*INNER_, DIM_,  0, 0, 0);
    tconv_kernel<<<dim3(16, 32, 1), t32>>>(Wo,  (bf16*)WoTh,  (bf16*)WoTl,  DIM_,     INNER_,0, 0, 0);
    tconv_kernel<<<dim3(32, 128,1), t32>>>(W1,  (bf16*)W1Th,  (bf16*)W1Tl,  FF_,      DIM_,  0, 0, 0);
    tconv_kernel<<<dim3(128,32, 1), t32>>>(W2,  (bf16*)W2Th,  (bf16*)W2Tl,  DIM_,     FF_,   0, 0, 0);
    // input splits
    conv_kernel<<<BN_*DIM_/1024, 256>>>(audio, (bf16*)audH, (bf16*)audL, BN_*DIM_);
    conv_kernel<<<BN_*DIM_/1024, 256>>>(video, (bf16*)vidH, (bf16*)vidL, BN_*DIM_);

    // 1) adapters
    gemm_wmma<EPI_BIAS><<<dim3(DIM_/128, BN_/128, 1), 256, GEMM_SMEM_DYN>>>(
        (bf16*)audH, (bf16*)audL, (bf16*)WaTh, (bf16*)WaTl, (float*)at, ba, nullptr,
        nullptr, nullptr, DIM_, DIM_, DIM_, DIM_, 1.f, 1, 0,0,0,0,0,0);
    gemm_wmma<EPI_BIAS><<<dim3(DIM_/128, BN_/128, 1), 256, GEMM_SMEM_DYN>>>(
        (bf16*)vidH, (bf16*)vidL, (bf16*)WvTh, (bf16*)WvTl, (float*)vt, bvid, nullptr,
        nullptr, nullptr, DIM_, DIM_, DIM_, DIM_, 1.f, 1, 0,0,0,0,0,0);
    ln_kernel<<<BN_, 256>>>((float*)at, (float*)at, lna_g, lna_b, DIM_);
    ln_kernel<<<BN_, 256>>>((float*)vt, (float*)vt, lnv_g, lnv_b, DIM_);

    // 2) rotary + padded layouts; v transposed per batch with front pad
    prep_kernel<<<B_ * NP_, 256>>>(text, (float*)at,
        (bf16*)qh, (bf16*)ql, (bf16*)kh, (bf16*)kl);
    tconv_kernel<<<dim3(NP_/32, DIM_/32, B_), t32>>>((float*)vt,
        (bf16*)vTh, (bf16*)vTl, DIM_, NP_, WS_,
        (long long)N_*DIM_, (long long)DIM_*NP_);

    // 3) local attention (8 windows batched)
    gemm_wmma<EPI_NONE><<<dim3((2*WS_)/128, WS_/128, B_*NWIN_), 256, GEMM_SMEM_DYN>>>(
        (bf16*)qh, (bf16*)ql, (bf16*)kh, (bf16*)kl, (float*)probs, nullptr, nullptr,
        nullptr, nullptr, DIM_, DIM_, DIM_, 2*WS_, 0.03125f, NWIN_,
        (long long)N_*DIM_,  (long long)WS_*DIM_,
        (long long)NP_*DIM_, (long long)WS_*DIM_,
        (long long)NWIN_*WS_*2*WS_, (long long)WS_*2*WS_);
    softmax_local_kernel<<<B_*NWIN_*WS_, 256>>>((float*)probs, (bf16*)ph, (bf16*)pl);
    gemm_wmma<EPI_NONE><<<dim3(DIM_/128, WS_/128, B_*NWIN_), 256, GEMM_SMEM_DYN>>>(
        (bf16*)ph, (bf16*)pl, (bf16*)vTh, (bf16*)vTl, (float*)x, nullptr, nullptr,
        nullptr, nullptr, 2*WS_, 2*WS_, NP_, DIM_, 1.f, NWIN_,
        (long long)NWIN_*WS_*2*WS_, (long long)WS_*2*WS_,
        (long long)DIM_*NP_, (long long)WS_,
        (long long)N_*DIM_, (long long)WS_*DIM_);

    // 4) ln1 -> projections -> rmsnorm
    ln_bf_kernel<<<BN_, 256>>>((float*)x, (bf16*)hh, (bf16*)hl, ln1_g, ln1_b, DIM_);
    gemm_wmma<EPI_NONE><<<dim3(INNER_/128, BN_/128, 1), 256, GEMM_SMEM_DYN>>>(
        (bf16*)hh, (bf16*)hl, (bf16*)WqTh, (bf16*)WqTl, (float*)qb, nullptr, nullptr,
        nullptr, nullptr, DIM_, DIM_, DIM_, INNER_, 1.f, 1, 0,0,0,0,0,0);
    gemm_wmma<EPI_NONE><<<dim3((2*INNER_)/128, BN_/128, 1), 256, GEMM_SMEM_DYN>>>(
        (bf16*)hh, (bf16*)hl, (bf16*)WkvTh, (bf16*)WkvTl, (float*)kvb, nullptr, nullptr,
        nullptr, nullptr, DIM_, DIM_, DIM_, 2*INNER_, 1.f, 1, 0,0,0,0,0,0);
    rms_kernel<<<(BN_*HEADS_)/8, 256>>>((float*)qb, qn_g, HEADS_, INNER_, BN_);
    rms_kernel<<<(BN_*HEADS_)/8, 256>>>((float*)kvb, kn_g, HEADS_, 2*INNER_, BN_);

    // 5) causal attention (emits fp32 + bf16 hi/lo)
    attn_kernel<<<dim3(N_/64, B_*HEADS_), 256, ATTN_SMEM_BYTES>>>(
        (float*)qb, (float*)kvb, (float*)ob, (bf16*)obH, (bf16*)obL);

    // 6) x2 = 2*(o @ Wo), epilogue emits x2 fp32 + hi/lo split
    gemm_wmma<EPI_SPLIT><<<dim3(DIM_/128, BN_/128, 1), 256, GEMM_SMEM_DYN>>>(
        (bf16*)obH, (bf16*)obL, (bf16*)WoTh, (bf16*)WoTl, (float*)x2, nullptr, nullptr,
        (bf16*)x2H, (bf16*)x2L, INNER_, INNER_, INNER_, DIM_, 2.f, 1, 0,0,0,0,0,0);

    // 7) FFN
    gemm_wmma<EPI_BIAS_GELU><<<dim3(FF_/128, BN_/128, 1), 256, GEMM_SMEM_DYN>>>(
        (bf16*)x2H, (bf16*)x2L, (bf16*)W1Th, (bf16*)W1Tl, (float*)ff, b1, nullptr,
        nullptr, nullptr, DIM_, DIM_, DIM_, FF_, 1.f, 1, 0,0,0,0,0,0);
    ln_bf_kernel<<<BN_, 256>>>((float*)ff, (bf16*)ffH, (bf16*)ffL, ln2_g, ln2_b, FF_);
    gemm_wmma<EPI_BIAS_RES><<<dim3(DIM_/128, BN_/128, 1), 256, GEMM_SMEM_DYN>>>(
        (bf16*)ffH, (bf16*)ffL, (bf16*)W2Th, (bf16*)W2Tl, out, b2, (float*)x2,
        nullptr, nullptr, FF_, FF_, FF_, DIM_, 1.f, 1, 0,0,0,0,0,0);
}

// round 12
// speedup vs baseline: 1.2567x; 1.0041x over previous
#include <cuda_runtime.h>
#include <cuda_bf16.h>
#include <mma.h>
#include <math.h>
#include <stdint.h>

using namespace nvcuda;
typedef __nv_bfloat16 bf16;

#define B_      2
#define N_      2048
#define DIM_    1024
#define INNER_  512
#define HEADS_  8
#define DHEAD_  64
#define WS_     512
#define FF_     4096
#define BN_     (B_*N_)
#define NP_     (N_+WS_)
#define NWIN_   (N_/WS_)
#define QKVLD_  1536

// ---- fp32 scratch ----
__device__ float g_atvt[2*BN_*DIM_];      // [audio_t | video_t]
__device__ float g_probs[B_*NWIN_*WS_*2*WS_];
__device__ float g_x  [BN_*DIM_];
__device__ float g_qkv[BN_*QKVLD_];       // [q | k | v] per row
__device__ float g_o  [BN_*INNER_];
__device__ float g_x2 [BN_*DIM_];
__device__ float g_ff [BN_*FF_];
__device__ float g_bias2[2*DIM_];

// ---- bf16 hi/lo scratch ----
__device__ bf16 g_inH [2*BN_*DIM_], g_inL [2*BN_*DIM_];   // [audio | video]
__device__ bf16 g_qh [BN_*DIM_],   g_ql [BN_*DIM_];
__device__ bf16 g_kh [B_*NP_*DIM_],g_kl [B_*NP_*DIM_];
__device__ bf16 g_vTh[B_*DIM_*NP_],g_vTl[B_*DIM_*NP_];
__device__ bf16 g_ph [B_*NWIN_*WS_*2*WS_], g_pl[B_*NWIN_*WS_*2*WS_];
__device__ bf16 g_hh [BN_*DIM_],   g_hl [BN_*DIM_];
__device__ bf16 g_obH[BN_*INNER_], g_obL[BN_*INNER_];
__device__ bf16 g_x2H[BN_*DIM_],   g_x2L[BN_*DIM_];
__device__ bf16 g_ffH[BN_*FF_],    g_ffL[BN_*FF_];
__device__ bf16 g_WavTh[2*DIM_*DIM_],  g_WavTl[2*DIM_*DIM_];      // [WaT | WvT]
__device__ bf16 g_WqkvTh[QKVLD_*DIM_], g_WqkvTl[QKVLD_*DIM_];     // [WqT rows 0..511 | WkvT rows 512..1535]
__device__ bf16 g_WoTh [DIM_*INNER_],  g_WoTl [DIM_*INNER_];
__device__ bf16 g_W1Th [FF_*DIM_],     g_W1Tl [FF_*DIM_];
__device__ bf16 g_W2Th [DIM_*FF_],     g_W2Tl [DIM_*FF_];

// ---- helpers ----
__device__ __forceinline__ uint32_t s2u(const void* p){
    uint32_t a;
    asm("{ .reg .u64 t; cvta.to.shared.u64 t, %1; cvt.u32.u64 %0, t; }"
        : "=r"(a) : "l"(p));
    return a;
}
__device__ __forceinline__ void cpa16(uint32_t d, const void* s){
    asm volatile("cp.async.cg.shared.global [%0], [%1], 16;" :: "r"(d), "l"(s));
}
__device__ __forceinline__ void cpa_commit(){
    asm volatile("cp.async.commit_group;" ::: "memory");
}
__device__ __forceinline__ void cpa_wait0(){
    asm volatile("cp.async.wait_group 0;" ::: "memory");
}
__device__ __forceinline__ void cpa_wait1(){
    asm volatile("cp.async.wait_group 1;" ::: "memory");
}
__device__ __forceinline__ void split2(float v, bf16& h, bf16& l){
    h = __float2bfloat16(v);
    l = __float2bfloat16(v - __bfloat162float(h));
}
__device__ __forceinline__ float gelu_tanh(float v){
    float c = v + 0.044715f * v * v * v;
    return 0.5f * v * (1.0f + tanhf(0.7978845608028654f * c));
}

// ---- bf16x3 wmma GEMM: 128x128 tile, warp 64x32, BK=32 ----
#define LDSB 40
#define MATB (128*LDSB*2)
#define AH_OFF 0
#define AL_OFF MATB
#define BH_OFF (2*MATB)
#define BL_OFF (3*MATB)
#define STGB  (4*MATB)             // 40960 per stage
#define GEMM_SMEM_DYN (2*STGB)     // 81920

#define EPI_NONE       0
#define EPI_BIAS       1
#define EPI_BIAS_GELU  2
#define EPI_BIAS_RES   3
#define EPI_SPLIT      4

template<int EPI>
__global__ void __launch_bounds__(256, 1)
gemm_wmma(const bf16* __restrict__ Ah, const bf16* __restrict__ Al,
          const bf16* __restrict__ Bh, const bf16* __restrict__ Bl,
          float* __restrict__ C, const float* __restrict__ bias,
          const float* __restrict__ res,
          bf16* __restrict__ Ch, bf16* __restrict__ Cl,
          int K, int lda, int ldb, int ldc, float alpha, int wdiv,
          int biasStride,
          long long sAb, long long sAw, long long sBb, long long sBw,
          long long sCb, long long sCw)
{
    extern __shared__ char dsm[];
    uint32_t sb0 = s2u(dsm);

    int tid = threadIdx.x;
    int wid = tid >> 5;
    int wm = wid >> 2;
    int wn = wid & 3;
    int z = blockIdx.z;
    int zb = z / wdiv, zw = z - zb * wdiv;
    long long aoff = zb * sAb + zw * sAw;
    long long boff = zb * sBb + zw * sBw;
    long long coff = zb * sCb + zw * sCw;
    Ah += aoff; Al += aoff;
    Bh += boff; Bl += boff;
    C  += coff;
    if (EPI == EPI_BIAS || EPI == EPI_BIAS_GELU || EPI == EPI_BIAS_RES)
        bias += (long long)zb * biasStride;
    const float* Rp = (EPI == EPI_BIAS_RES) ? (res + coff) : nullptr;

    int m0 = blockIdx.y * 128;
    int n0 = blockIdx.x * 128;

    wmma::fragment<wmma::accumulator, 16, 16, 16, float> acc[4][2];
#pragma unroll
    for (int i = 0; i < 4; i++)
#pragma unroll
        for (int j = 0; j < 2; j++) wmma::fill_fragment(acc[i][j], 0.f);

    auto loadStage = [&](int stg, int kk){
        uint32_t sb = sb0 + stg * STGB;
#pragma unroll
        for (int half = 0; half < 2; half++){
            int i = tid + half * 256;
            int row = i >> 2, ch = i & 3;
            uint32_t d = row * (LDSB*2) + ch * 16;
            long long ga = (long long)(m0 + row) * lda + kk + ch * 8;
            long long gb = (long long)(n0 + row) * ldb + kk + ch * 8;
            cpa16(sb + AH_OFF + d, Ah + ga);
            cpa16(sb + AL_OFF + d, Al + ga);
            cpa16(sb + BH_OFF + d, Bh + gb);
            cpa16(sb + BL_OFF + d, Bl + gb);
        }
    };

    int KT = K >> 5;
    loadStage(0, 0);
    cpa_commit();

    for (int kt = 0; kt < KT; kt++){
        if (kt + 1 < KT){
            loadStage((kt + 1) & 1, (kt + 1) * 32);
            cpa_commit();
            cpa_wait1();
        } else {
            cpa_wait0();
        }
        __syncthreads();

        const bf16* st = (const bf16*)(dsm + (kt & 1) * STGB);
        const bf16* pAh = st + (AH_OFF/2) + (wm*64)*LDSB;
        const bf16* pAl = st + (AL_OFF/2) + (wm*64)*LDSB;
        const bf16* pBh = st + (BH_OFF/2) + (wn*32)*LDSB;
        const bf16* pBl = st + (BL_OFF/2) + (wn*32)*LDSB;
#pragma unroll
        for (int ks = 0; ks < 2; ks++){
            wmma::fragment<wmma::matrix_a, 16,16,16, bf16, wmma::row_major> fAh[4], fAl[4];
            wmma::fragment<wmma::matrix_b, 16,16,16, bf16, wmma::col_major> fBh[2], fBl[2];
#pragma unroll
            for (int i = 0; i < 4; i++){
                wmma::load_matrix_sync(fAh[i], pAh + i*16*LDSB + ks*16, LDSB);
                wmma::load_matrix_sync(fAl[i], pAl + i*16*LDSB + ks*16, LDSB);
            }
#pragma unroll
            for (int j = 0; j < 2; j++){
                wmma::load_matrix_sync(fBh[j], pBh + j*16*LDSB + ks*16, LDSB);
                wmma::load_matrix_sync(fBl[j], pBl + j*16*LDSB + ks*16, LDSB);
            }
#pragma unroll
            for (int i = 0; i < 4; i++)
#pragma unroll
                for (int j = 0; j < 2; j++){
                    wmma::mma_sync(acc[i][j], fAh[i], fBh[j], acc[i][j]);
                    wmma::mma_sync(acc[i][j], fAh[i], fBl[j], acc[i][j]);
                    wmma::mma_sync(acc[i][j], fAl[i], fBh[j], acc[i][j]);
                }
        }
        __syncthreads();
    }

    // ---- block-wide epilogue via smem float staging ----
    float* sF = (float*)dsm;
#pragma unroll
    for (int i = 0; i < 4; i++)
#pragma unroll
        for (int j = 0; j < 2; j++)
            wmma::store_matrix_sync(
                sF + (wm*64 + i*16) * 128 + wn*32 + j*16,
                acc[i][j], 128, wmma::mem_row_major);
    __syncthreads();

#pragma unroll 1
    for (int t = 0; t < 16; t++){
        int i = tid + t * 256;
        int row = i >> 5, c4 = (i & 31) * 4;
        float4 v = *(float4*)&sF[row * 128 + c4];
        v.x *= alpha; v.y *= alpha; v.z *= alpha; v.w *= alpha;
        int gc = n0 + c4;
        if (EPI == EPI_BIAS || EPI == EPI_BIAS_GELU || EPI == EPI_BIAS_RES){
            float4 bb = *(const float4*)&bias[gc];
            v.x += bb.x; v.y += bb.y; v.z += bb.z; v.w += bb.w;
        }
        if (EPI == EPI_BIAS_GELU){
            v.x = gelu_tanh(v.x); v.y = gelu_tanh(v.y);
            v.z = gelu_tanh(v.z); v.w = gelu_tanh(v.w);
        }
        long long crow = (long long)(m0 + row) * ldc + gc;
        if (EPI == EPI_BIAS_RES){
            float4 rr = *(const float4*)&Rp[crow];
            v.x += rr.x; v.y += rr.y; v.z += rr.z; v.w += rr.w;
        }
        *(float4*)&C[crow] = v;
        if (EPI == EPI_SPLIT){
            long long so = coff + crow;
            bf16 hh, ll;
            split2(v.x, hh, ll); Ch[so+0] = hh; Cl[so+0] = ll;
            split2(v.y, hh, ll); Ch[so+1] = hh; Cl[so+1] = ll;
            split2(v.z, hh, ll); Ch[so+2] = hh; Cl[so+2] = ll;
            split2(v.w, hh, ll); Ch[so+3] = hh; Cl[so+3] = ll;
        }
    }
}

// ---- bias pack: g_bias2 = [ba | bvid] ----
__global__ void packbias_kernel(const float* __restrict__ a, const float* __restrict__ b)
{
    int i = blockIdx.x * 256 + threadIdx.x;
    if (i < DIM_){ g_bias2[i] = a[i]; g_bias2[DIM_ + i] = b[i]; }
}

// ---- LayerNorm fp32 out ----
__global__ void ln_kernel(const float* __restrict__ x, float* __restrict__ y,
                          const float* __restrict__ g, const float* __restrict__ bv,
                          int L)
{
    __shared__ float buf[4096];
    __shared__ float r1[8], r2[8], st[2];
    long long row = blockIdx.x;
    const float* xr = x + row * L;
    int tid = threadIdx.x;
    float s = 0.f, s2 = 0.f;
    for (int c = tid; c < L; c += 256){ float v = xr[c]; buf[c] = v; s += v; s2 += v*v; }
#pragma unroll
    for (int o = 16; o > 0; o >>= 1){
        s  += __shfl_xor_sync(0xffffffffu, s,  o);
        s2 += __shfl_xor_sync(0xffffffffu, s2, o);
    }
    int lane = tid & 31, w = tid >> 5;
    if (lane == 0){ r1[w] = s; r2[w] = s2; }
    __syncthreads();
    if (tid == 0){
        float ts = 0.f, ts2 = 0.f;
        for (int k = 0; k < 8; k++){ ts += r1[k]; ts2 += r2[k]; }
        float mean = ts / (float)L;
        st[0] = mean; st[1] = rsqrtf(ts2 / (float)L - mean*mean + 1e-5f);
    }
    __syncthreads();
    float mean = st[0], rstd = st[1];
    float* yr = y + row * L;
    for (int c = tid; c < L; c += 256)
        yr[c] = (buf[c] - mean) * rstd * g[c] + bv[c];
}

// ---- LayerNorm -> bf16 hi/lo ----
__global__ void ln_bf_kernel(const float* __restrict__ x, bf16* __restrict__ yh,
                             bf16* __restrict__ yl,
                             const float* __restrict__ g, const float* __restrict__ bv,
                             int L)
{
    __shared__ float buf[4096];
    __shared__ float r1[8], r2[8], st[2];
    long long row = blockIdx.x;
    const float* xr = x + row * L;
    int tid = threadIdx.x;
    float s = 0.f, s2 = 0.f;
    for (int c = tid; c < L; c += 256){ float v = xr[c]; buf[c] = v; s += v; s2 += v*v; }
#pragma unroll
    for (int o = 16; o > 0; o >>= 1){
        s  += __shfl_xor_sync(0xffffffffu, s,  o);
        s2 += __shfl_xor_sync(0xffffffffu, s2, o);
    }
    int lane = tid & 31, w = tid >> 5;
    if (lane == 0){ r1[w] = s; r2[w] = s2; }
    __syncthreads();
    if (tid == 0){
        float ts = 0.f, ts2 = 0.f;
        for (int k = 0; k < 8; k++){ ts += r1[k]; ts2 += r2[k]; }
        float mean = ts / (float)L;
        st[0] = mean; st[1] = rsqrtf(ts2 / (float)L - mean*mean + 1e-5f);
    }
    __syncthreads();
    float mean = st[0], rstd = st[1];
    for (int c = tid; c < L; c += 256){
        float v = (buf[c] - mean) * rstd * g[c] + bv[c];
        bf16 h, l; split2(v, h, l);
        yh[row * L + c] = h; yl[row * L + c] = l;
    }
}

// ---- RMSNorm over 64-dim head vectors ----
__global__ void rms_kernel(float* __restrict__ x, const float* __restrict__ g,
                           int vecs_per_row, int row_stride, int nrows)
{
    int vid = blockIdx.x * 8 + (threadIdx.x >> 5);
    int lane = threadIdx.x & 31;
    int r = vid / vecs_per_row;
    int h = vid - r * vecs_per_row;
    if (r >= nrows) return;
    float* p = x + (long long)r * row_stride + h * DHEAD_;
    float v0 = p[lane], v1 = p[lane + 32];
    float ss = v0*v0 + v1*v1;
#pragma unroll
    for (int o = 16; o > 0; o >>= 1) ss += __shfl_xor_sync(0xffffffffu, ss, o);
    float rs = rsqrtf(ss * (1.0f/64.0f) + 1e-6f);
    p[lane]      = v0 * rs * g[lane];
    p[lane + 32] = v1 * rs * g[lane + 32];
}

// ---- rotary prep -> bf16 hi/lo ----
__global__ void prep_kernel(const float* __restrict__ text,
                            const float* __restrict__ at,
                            bf16* __restrict__ qh, bf16* __restrict__ ql,
                            bf16* __restrict__ kh, bf16* __restrict__ kl)
{
    int row = blockIdx.x;
    int b = row / NP_;
    int pr = row - b * NP_;
    long long kout = (long long)row * DIM_;
    if (pr < WS_){
        bf16 zz = __float2bfloat16(0.f);
        for (int c = threadIdx.x; c < DIM_; c += 256){ kh[kout+c] = zz; kl[kout+c] = zz; }
        return;
    }
    int t = pr - WS_;
    long long src = ((long long)b * N_ + t) * DIM_;
    for (int c = threadIdx.x; c < DIM_; c += 256){
        int j = c & 511;
        float invf = exp2f((float)j * (-13.28771238f * (1.0f/512.0f)));
        float ang = (float)t * invf;
        float cs = cosf(ang), sn = sinf(ang);
        float kx = at[src + c];
        float ko = (c < 512) ? -at[src + c + 512] : at[src + c - 512];
        bf16 h, l;
        split2(kx * cs + ko * sn, h, l);
        kh[kout + c] = h; kl[kout + c] = l;
        float qx = text[src + c];
        float qo = (c < 512) ? -text[src + c + 512] : text[src + c - 512];
        split2(qx * cs + qo * sn, h, l);
        qh[src + c] = h; ql[src + c] = l;
    }
}

// ---- transpose + split ----
__global__ void tconv_kernel(const float* __restrict__ in, bf16* __restrict__ oh,
                             bf16* __restrict__ ol,
                             int inLd, int outLd, int pad,
                             long long inB, long long outB)
{
    __shared__ float t[32][33];
    in += blockIdx.z * inB;
    oh += blockIdx.z * outB;
    ol += blockIdx.z * outB;
    int p0 = blockIdx.x * 32, c0 = blockIdx.y * 32;
    int tx = threadIdx.x, ty = threadIdx.y;
    for (int i = ty; i < 32; i += 8){
        int r = p0 + i - pad;
        t[i][tx] = (r >= 0) ? in[(long long)r * inLd + c0 + tx] : 0.f;
    }
    __syncthreads();
    for (int i = ty; i < 32; i += 8){
        float v = t[tx][i];
        bf16 h, l; split2(v, h, l);
        long long o = (long long)(c0 + i) * outLd + p0 + tx;
        oh[o] = h; ol[o] = l;
    }
}

// ---- elementwise split fp32 -> bf16 hi/lo ----
__global__ void conv_kernel(const float* __restrict__ x, bf16* __restrict__ h,
                            bf16* __restrict__ l, int n)
{
    int i = (blockIdx.x * 256 + threadIdx.x) * 4;
    if (i < n){
        float4 v = *(const float4*)&x[i];
        bf16 hh, ll;
        split2(v.x, hh, ll); h[i+0] = hh; l[i+0] = ll;
        split2(v.y, hh, ll); h[i+1] = hh; l[i+1] = ll;
        split2(v.z, hh, ll); h[i+2] = hh; l[i+2] = ll;
        split2(v.w, hh, ll); h[i+3] = hh; l[i+3] = ll;
    }
}

// ---- local-attention masked softmax -> bf16 hi/lo ----
__global__ void softmax_local_kernel(const float* __restrict__ p,
                                     bf16* __restrict__ ph, bf16* __restrict__ pl)
{
    __shared__ float buf[1024];
    __shared__ float red[8], bc[2];
    int r = blockIdx.x;
    int i = r & (WS_ - 1);
    int z = r >> 9;
    int w = z & (NWIN_ - 1);
    int qp = w * WS_ + i;
    const float* row = p + (long long)r * (2 * WS_);
    int tid = threadIdx.x, lane = tid & 31, wp = tid >> 5;

    float mx = -1e30f;
    for (int j = tid; j < 2*WS_; j += 256){
        int kp = (w - 1) * WS_ + j;
        float v = (kp >= 0 && kp <= qp) ? row[j] : -1e9f;
        buf[j] = v;
        mx = fmaxf(mx, v);
    }
#pragma unroll
    for (int o = 16; o > 0; o >>= 1) mx = fmaxf(mx, __shfl_xor_sync(0xffffffffu, mx, o));
    if (lane == 0) red[wp] = mx;
    __syncthreads();
    if (tid == 0){
        float m = red[0];
        for (int k = 1; k < 8; k++) m = fmaxf(m, red[k]);
        bc[0] = m;
    }
    __syncthreads();
    mx = bc[0];
    float sum = 0.f;
    for (int j = tid; j < 2*WS_; j += 256){
        float e = __expf(buf[j] - mx);
        buf[j] = e; sum += e;
    }
#pragma unroll
    for (int o = 16; o > 0; o >>= 1) sum += __shfl_xor_sync(0xffffffffu, sum, o);
    if (lane == 0) red[wp] = sum;
    __syncthreads();
    if (tid == 0){
        float t = 0.f;
        for (int k = 0; k < 8; k++) t += red[k];
        bc[1] = 1.0f / t;
    }
    __syncthreads();
    float inv = bc[1];
    for (int j = tid; j < 2*WS_; j += 256){
        bf16 h, l; split2(buf[j] * inv, h, l);
        long long o = (long long)r * (2*WS_) + j;
        ph[o] = h; pl[o] = l;
    }
}

// ---- causal flash attention fp32; q/k/v packed row stride 1536 ----
#define QP_ 68
#define ATTN_SMEM_BYTES (4 * 64 * QP_ * 4 + 3 * 64 * 4)

__global__ void __launch_bounds__(256)
attn_kernel(const float* __restrict__ qkv,
            float* __restrict__ o, bf16* __restrict__ oh, bf16* __restrict__ ol)
{
    extern __shared__ float sm[];
    float* QsT = sm;
    float* KsT = QsT + 64 * QP_;
    float* Vs  = KsT + 64 * QP_;
    float* SsT = Vs  + 64 * QP_;
    float* Ms = SsT + 64 * QP_;
    float* Ls = Ms + 64;
    float* Cs = Ls + 64;

    int tid = threadIdx.x;
    int bh = blockIdx.y;
    int b = bh >> 3, h = bh & 7;
    int q0 = blockIdx.x * 64;
    int ty = tid >> 4, tx = tid & 15;

    for (int idx = tid; idx < 4096; idx += 256){
        int r = idx >> 6, c = idx & 63;
        QsT[c * QP_ + r] =
            qkv[((long long)(b * N_ + q0 + r)) * QKVLD_ + h * 64 + c] * 0.125f;
    }
    if (tid < 64){ Ms[tid] = -INFINITY; Ls[tid] = 0.f; }
    float oacc[16];
#pragma unroll
    for (int i = 0; i < 16; i++) oacc[i] = 0.f;
    __syncthreads();

    int lastTile = blockIdx.x;
    for (int kt = 0; kt <= lastTile; kt++){
        for (int idx = tid; idx < 4096; idx += 256){
            int r = idx >> 6, c = idx & 63;
            long long base =
                ((long long)(b * N_ + kt * 64 + r)) * QKVLD_ + INNER_ + h * 64 + c;
            KsT[c * QP_ + r] = qkv[base];
            Vs[r * QP_ + c]  = qkv[base + INNER_];
        }
        __syncthreads();

        float sacc[16];
#pragma unroll
        for (int i = 0; i < 16; i++) sacc[i] = 0.f;
#pragma unroll 8
        for (int kk = 0; kk < 64; kk++){
            float4 aq = *(const float4*)&QsT[kk * QP_ + ty * 4];
            float4 bk = *(const float4*)&KsT[kk * QP_ + tx * 4];
            float a4[4] = {aq.x, aq.y, aq.z, aq.w};
            float b4[4] = {bk.x, bk.y, bk.z, bk.w};
#pragma unroll
            for (int i = 0; i < 4; i++)
#pragma unroll
                for (int j = 0; j < 4; j++)
                    sacc[i*4+j] += a4[i] * b4[j];
        }
        bool diag = (kt == lastTile);
#pragma unroll
        for (int i = 0; i < 4; i++)
#pragma unroll
            for (int j = 0; j < 4; j++){
                int qr = ty * 4 + i, kc = tx * 4 + j;
                float s = sacc[i*4+j];
                if (diag && kc > qr) s = -INFINITY;
                SsT[kc * QP_ + qr] = s;
            }
        __syncthreads();

        if (tid < 64){
            int r = tid;
            float mt = -INFINITY;
#pragma unroll 8
            for (int c = 0; c < 64; c++) mt = fmaxf(mt, SsT[c * QP_ + r]);
            float mo = Ms[r];
            float mn = fmaxf(mo, mt);
            float corr = __expf(mo - mn);
            float ls = 0.f;
#pragma unroll 8
            for (int c = 0; c < 64; c++){
                float e = __expf(SsT[c * QP_ + r] - mn);
                SsT[c * QP_ + r] = e;
                ls += e;
            }
            Ls[r] = Ls[r] * corr + ls;
            Ms[r] = mn;
            Cs[r] = corr;
        }
        __syncthreads();

        float cf[4];
#pragma unroll
        for (int i = 0; i < 4; i++) cf[i] = Cs[ty * 4 + i];
#pragma unroll
        for (int i = 0; i < 4; i++)
#pragma unroll
            for (int j = 0; j < 4; j++) oacc[i*4+j] *= cf[i];

#pragma unroll 8
        for (int kk = 0; kk < 64; kk++){
            float4 ap = *(const float4*)&SsT[kk * QP_ + ty * 4];
            float4 vv = *(const float4*)&Vs[kk * QP_ + tx * 4];
            float a4[4] = {ap.x, ap.y, ap.z, ap.w};
            float b4[4] = {vv.x, vv.y, vv.z, vv.w};
#pragma unroll
            for (int i = 0; i < 4; i++)
#pragma unroll
                for (int j = 0; j < 4; j++)
                    oacc[i*4+j] += a4[i] * b4[j];
        }
        __syncthreads();
    }

#pragma unroll
    for (int i = 0; i < 4; i++){
        float inv = 1.0f / Ls[ty * 4 + i];
        long long orow =
            ((long long)(b * N_ + q0 + ty * 4 + i)) * INNER_ + h * 64 + tx * 4;
        float4 vo = make_float4(oacc[i*4+0]*inv, oacc[i*4+1]*inv,
                                oacc[i*4+2]*inv, oacc[i*4+3]*inv);
        *(float4*)&o[orow] = vo;
        bf16 hh, ll;
        split2(vo.x, hh, ll); oh[orow+0] = hh; ol[orow+0] = ll;
        split2(vo.y, hh, ll); oh[orow+1] = hh; ol[orow+1] = ll;
        split2(vo.z, hh, ll); oh[orow+2] = hh; ol[orow+2] = ll;
        split2(vo.w, hh, ll); oh[orow+3] = hh; ol[orow+3] = ll;
    }
}

// ---- launch ----
extern "C" void kernel_launch(void* const* d_in, const int* in_sizes, int n_in,
                              void* d_out, int out_size)
{
    (void)in_sizes; (void)n_in; (void)out_size;
    const float* text  = (const float*)d_in[0];
    const float* audio = (const float*)d_in[1];
    const float* video = (const float*)d_in[2];
    const float* Wa    = (const float*)d_in[3];
    const float* ba    = (const float*)d_in[4];
    const float* lna_g = (const float*)d_in[5];
    const float* lna_b = (const float*)d_in[6];
    const float* Wvid  = (const float*)d_in[7];
    const float* bvid  = (const float*)d_in[8];
    const float* lnv_g = (const float*)d_in[9];
    const float* lnv_b = (const float*)d_in[10];
    const float* ln1_g = (const float*)d_in[11];
    const float* ln1_b = (const float*)d_in[12];
    const float* Wq    = (const float*)d_in[13];
    const float* Wkv   = (const float*)d_in[14];
    const float* qn_g  = (const float*)d_in[15];
    const float* kn_g  = (const float*)d_in[16];
    const float* Wo    = (const float*)d_in[17];
    const float* W1    = (const float*)d_in[18];
    const float* b1    = (const float*)d_in[19];
    const float* ln2_g = (const float*)d_in[20];
    const float* ln2_b = (const float*)d_in[21];
    const float* W2    = (const float*)d_in[22];
    const float* b2    = (const float*)d_in[23];
    float* out = (float*)d_out;

#define SYM(p, s) void* p; cudaGetSymbolAddress(&p, s)
    SYM(atvt, g_atvt); SYM(probs, g_probs);
    SYM(x, g_x);     SYM(qkvp, g_qkv);
    SYM(ob, g_o);    SYM(x2, g_x2);   SYM(ff, g_ff);
    SYM(bias2, g_bias2);
    SYM(inH, g_inH); SYM(inL, g_inL);
    SYM(qh, g_qh);   SYM(ql, g_ql);
    SYM(kh, g_kh);   SYM(kl, g_kl);
    SYM(vTh, g_vTh); SYM(vTl, g_vTl);
    SYM(ph, g_ph);   SYM(pl, g_pl);
    SYM(hh, g_hh);   SYM(hl, g_hl);
    SYM(obH, g_obH); SYM(obL, g_obL);
    SYM(x2H, g_x2H); SYM(x2L, g_x2L);
    SYM(ffH, g_ffH); SYM(ffL, g_ffL);
    SYM(WavTh, g_WavTh); SYM(WavTl, g_WavTl);
    SYM(WqkvTh, g_WqkvTh); SYM(WqkvTl, g_WqkvTl);
    SYM(WoTh, g_WoTh); SYM(WoTl, g_WoTl);
    SYM(W1Th, g_W1Th); SYM(W1Tl, g_W1Tl);
    SYM(W2Th, g_W2Th); SYM(W2Tl, g_W2Tl);
#undef SYM

    cudaFuncSetAttribute(gemm_wmma<EPI_NONE>,      cudaFuncAttributeMaxDynamicSharedMemorySize, GEMM_SMEM_DYN);
    cudaFuncSetAttribute(gemm_wmma<EPI_BIAS>,      cudaFuncAttributeMaxDynamicSharedMemorySize, GEMM_SMEM_DYN);
    cudaFuncSetAttribute(gemm_wmma<EPI_BIAS_GELU>, cudaFuncAttributeMaxDynamicSharedMemorySize, GEMM_SMEM_DYN);
    cudaFuncSetAttribute(gemm_wmma<EPI_BIAS_RES>,  cudaFuncAttributeMaxDynamicSharedMemorySize, GEMM_SMEM_DYN);
    cudaFuncSetAttribute(gemm_wmma<EPI_SPLIT>,     cudaFuncAttributeMaxDynamicSharedMemorySize, GEMM_SMEM_DYN);
    cudaFuncSetAttribute(attn_kernel, cudaFuncAttributeMaxDynamicSharedMemorySize, ATTN_SMEM_BYTES);

    dim3 t32(32, 8);
    long long DD = (long long)DIM_ * DIM_;
    long long BD = (long long)BN_ * DIM_;

    // prologue ordered so launch #6 is the merged adapter GEMM (ncu -s 5)
    packbias_kernel<<<4, 256>>>(ba, bvid);                                    // 1
    tconv_kernel<<<dim3(32, 32, 1), t32>>>(Wa,  (bf16*)WavTh,  (bf16*)WavTl,  DIM_, DIM_, 0, 0, 0);  // 2
    tconv_kernel<<<dim3(32, 32, 1), t32>>>(Wvid,(bf16*)WavTh + DD, (bf16*)WavTl + DD, DIM_, DIM_, 0, 0, 0);  // 3
    conv_kernel<<<BN_*DIM_/1024, 256>>>(audio, (bf16*)inH, (bf16*)inL, BN_*DIM_);                    // 4
    conv_kernel<<<BN_*DIM_/1024, 256>>>(video, (bf16*)inH + BD, (bf16*)inL + BD, BN_*DIM_);          // 5

    // 1) merged adapters: z in {audio, video}  (launch #6)
    gemm_wmma<EPI_BIAS><<<dim3(DIM_/128, BN_/128, 2), 256, GEMM_SMEM_DYN>>>(
        (bf16*)inH, (bf16*)inL, (bf16*)WavTh, (bf16*)WavTl, (float*)atvt, (float*)bias2, nullptr,
        nullptr, nullptr, DIM_, DIM_, DIM_, DIM_, 1.f, 1, DIM_,
        BD, 0, DD, 0, BD, 0);

    // remaining weight transposes
    tconv_kernel<<<dim3(32, 16, 1), t32>>>(Wq,  (bf16*)WqkvTh, (bf16*)WqkvTl, INNER_,   DIM_, 0, 0, 0);
    tconv_kernel<<<dim3(32, 32, 1), t32>>>(Wkv, (bf16*)WqkvTh + (long long)INNER_*DIM_,
                                                (bf16*)WqkvTl + (long long)INNER_*DIM_, 2*INNER_, DIM_, 0, 0, 0);
    tconv_kernel<<<dim3(16, 32, 1), t32>>>(Wo,  (bf16*)WoTh,  (bf16*)WoTl,  DIM_, INNER_, 0, 0, 0);
    tconv_kernel<<<dim3(32, 128,1), t32>>>(W1,  (bf16*)W1Th,  (bf16*)W1Tl,  FF_,  DIM_,   0, 0, 0);
    tconv_kernel<<<dim3(128,32, 1), t32>>>(W2,  (bf16*)W2Th,  (bf16*)W2Tl,  DIM_, FF_,    0, 0, 0);

    float* at = (float*)atvt;
    float* vt = (float*)atvt + BD;
    ln_kernel<<<BN_, 256>>>(at, at, lna_g, lna_b, DIM_);
    ln_kernel<<<BN_, 256>>>(vt, vt, lnv_g, lnv_b, DIM_);

    // 2) rotary + padded layouts; v transposed per batch with front pad
    prep_kernel<<<B_ * NP_, 256>>>(text, at,
        (bf16*)qh, (bf16*)ql, (bf16*)kh, (bf16*)kl);
    tconv_kernel<<<dim3(NP_/32, DIM_/32, B_), t32>>>(vt,
        (bf16*)vTh, (bf16*)vTl, DIM_, NP_, WS_,
        (long long)N_*DIM_, (long long)DIM_*NP_);

    // 3) local attention (8 windows batched)
    gemm_wmma<EPI_NONE><<<dim3((2*WS_)/128, WS_/128, B_*NWIN_), 256, GEMM_SMEM_DYN>>>(
        (bf16*)qh, (bf16*)ql, (bf16*)kh, (bf16*)kl, (float*)probs, nullptr, nullptr,
        nullptr, nullptr, DIM_, DIM_, DIM_, 2*WS_, 0.03125f, NWIN_, 0,
        (long long)N_*DIM_,  (long long)WS_*DIM_,
        (long long)NP_*DIM_, (long long)WS_*DIM_,
        (long long)NWIN_*WS_*2*WS_, (long long)WS_*2*WS_);
    softmax_local_kernel<<<B_*NWIN_*WS_, 256>>>((float*)probs, (bf16*)ph, (bf16*)pl);
    gemm_wmma<EPI_NONE><<<dim3(DIM_/128, WS_/128, B_*NWIN_), 256, GEMM_SMEM_DYN>>>(
        (bf16*)ph, (bf16*)pl, (bf16*)vTh, (bf16*)vTl, (float*)x, nullptr, nullptr,
        nullptr, nullptr, 2*WS_, 2*WS_, NP_, DIM_, 1.f, NWIN_, 0,
        (long long)NWIN_*WS_*2*WS_, (long long)WS_*2*WS_,
        (long long)DIM_*NP_, (long long)WS_,
        (long long)N_*DIM_, (long long)WS_*DIM_);

    // 4) ln1 -> merged qkv projection -> rmsnorm
    ln_bf_kernel<<<BN_, 256>>>((float*)x, (bf16*)hh, (bf16*)hl, ln1_g, ln1_b, DIM_);
    gemm_wmma<EPI_NONE><<<dim3(QKVLD_/128, BN_/128, 1), 256, GEMM_SMEM_DYN>>>(
        (bf16*)hh, (bf16*)hl, (bf16*)WqkvTh, (bf16*)WqkvTl, (float*)qkvp, nullptr, nullptr,
        nullptr, nullptr, DIM_, DIM_, DIM_, QKVLD_, 1.f, 1, 0, 0,0,0,0,0,0);
    rms_kernel<<<(BN_*HEADS_)/8, 256>>>((float*)qkvp, qn_g, HEADS_, QKVLD_, BN_);
    rms_kernel<<<(BN_*HEADS_)/8, 256>>>((float*)qkvp + INNER_, kn_g, HEADS_, QKVLD_, BN_);

    // 5) causal attention (emits fp32 + bf16 hi/lo)
    attn_kernel<<<dim3(N_/64, B_*HEADS_), 256, ATTN_SMEM_BYTES>>>(
        (float*)qkvp, (float*)ob, (bf16*)obH, (bf16*)obL);

    // 6) x2 = 2*(o @ Wo), epilogue emits x2 fp32 + hi/lo split
    gemm_wmma<EPI_SPLIT><<<dim3(DIM_/128, BN_/128, 1), 256, GEMM_SMEM_DYN>>>(
        (bf16*)obH, (bf16*)obL, (bf16*)WoTh, (bf16*)WoTl, (float*)x2, nullptr, nullptr,
        (bf16*)x2H, (bf16*)x2L, INNER_, INNER_, INNER_, DIM_, 2.f, 1, 0, 0,0,0,0,0,0);

    // 7) FFN
    gemm_wmma<EPI_BIAS_GELU><<<dim3(FF_/128, BN_/128, 1), 256, GEMM_SMEM_DYN>>>(
        (bf16*)x2H, (bf16*)x2L, (bf16*)W1Th, (bf16*)W1Tl, (float*)ff, b1, nullptr,
        nullptr, nullptr, DIM_, DIM_, DIM_, FF_, 1.f, 1, 0, 0,0,0,0,0,0);
    ln_bf_kernel<<<BN_, 256>>>((float*)ff, (bf16*)ffH, (bf16*)ffL, ln2_g, ln2_b, FF_);
    gemm_wmma<EPI_BIAS_RES><<<dim3(DIM_/128, BN_/128, 1), 256, GEMM_SMEM_DYN>>>(
        (bf16*)ffH, (bf16*)ffL, (bf16*)W2Th, (bf16*)W2Tl, out, b2, (float*)x2,
        nullptr, nullptr, FF_, FF_, FF_, DIM_, 1.f, 1, 0, 0,0,0,0,0,0);
}

// round 13
// speedup vs baseline: 1.7905x; 1.4247x over previous
#include <cuda_runtime.h>
#include <cuda_fp16.h>
#include <mma.h>
#include <math.h>
#include <stdint.h>

using namespace nvcuda;
typedef __half f16;

#define B_      2
#define N_      2048
#define DIM_    1024
#define INNER_  512
#define HEADS_  8
#define DHEAD_  64
#define WS_     512
#define FF_     4096
#define BN_     (B_*N_)
#define NP_     (N_+WS_)
#define NWIN_   (N_/WS_)
#define QKVLD_  1536

// ---- fp32 scratch ----
__device__ float g_atvt[2*BN_*DIM_];
__device__ float g_probs[B_*NWIN_*WS_*2*WS_];
__device__ float g_x  [BN_*DIM_];
__device__ float g_qkv[BN_*QKVLD_];
__device__ float g_o  [BN_*INNER_];
__device__ float g_x2 [BN_*DIM_];
__device__ float g_ff [BN_*FF_];
__device__ float g_bias2[2*DIM_];

// ---- fp16 scratch: A operands split hi/lo, B operands single ----
__device__ f16 g_inH [2*BN_*DIM_], g_inL [2*BN_*DIM_];
__device__ f16 g_qh [BN_*DIM_],   g_ql [BN_*DIM_];
__device__ f16 g_kh [B_*NP_*DIM_];
__device__ f16 g_vTh[B_*DIM_*NP_];
__device__ f16 g_ph [B_*NWIN_*WS_*2*WS_], g_pl[B_*NWIN_*WS_*2*WS_];
__device__ f16 g_hh [BN_*DIM_],   g_hl [BN_*DIM_];
__device__ f16 g_obH[BN_*INNER_], g_obL[BN_*INNER_];
__device__ f16 g_x2H[BN_*DIM_],   g_x2L[BN_*DIM_];
__device__ f16 g_ffH[BN_*FF_],    g_ffL[BN_*FF_];
__device__ f16 g_WavT[2*DIM_*DIM_];
__device__ f16 g_WqkvT[QKVLD_*DIM_];
__device__ f16 g_WoT [DIM_*INNER_];
__device__ f16 g_W1T [FF_*DIM_];
__device__ f16 g_W2T [DIM_*FF_];

// ---- helpers ----
__device__ __forceinline__ uint32_t s2u(const void* p){
    uint32_t a;
    asm("{ .reg .u64 t; cvta.to.shared.u64 t, %1; cvt.u32.u64 %0, t; }"
        : "=r"(a) : "l"(p));
    return a;
}
__device__ __forceinline__ void cpa16(uint32_t d, const void* s){
    asm volatile("cp.async.cg.shared.global [%0], [%1], 16;" :: "r"(d), "l"(s));
}
__device__ __forceinline__ void cpa_commit(){
    asm volatile("cp.async.commit_group;" ::: "memory");
}
__device__ __forceinline__ void cpa_wait0(){
    asm volatile("cp.async.wait_group 0;" ::: "memory");
}
__device__ __forceinline__ void cpa_wait1(){
    asm volatile("cp.async.wait_group 1;" ::: "memory");
}
__device__ __forceinline__ void split2(float v, f16& h, f16& l){
    h = __float2half_rn(v);
    l = __float2half_rn(v - __half2float(h));
}
__device__ __forceinline__ float gelu_tanh(float v){
    float c = v + 0.044715f * v * v * v;
    return 0.5f * v * (1.0f + tanhf(0.7978845608028654f * c));
}

// ---- fp16 split-A GEMM: C = alpha*(Ah+Al)*Bh^T (+epi). 128x128, BK=32 ----
#define LDSB 40
#define MATB (128*LDSB*2)          // 10240 B per matrix per stage
#define AH_OFF 0
#define AL_OFF MATB
#define BH_OFF (2*MATB)
#define STGB  (3*MATB)             // 30720 per stage
#define GEMM_SMEM_DYN 65536        // max(2*STGB=61440, epilogue 64KB)

#define EPI_NONE       0
#define EPI_BIAS       1
#define EPI_BIAS_GELU  2
#define EPI_BIAS_RES   3
#define EPI_SPLIT      4

template<int EPI>
__global__ void __launch_bounds__(256, 1)
gemm_wmma(const f16* __restrict__ Ah, const f16* __restrict__ Al,
          const f16* __restrict__ Bh,
          float* __restrict__ C, const float* __restrict__ bias,
          const float* __restrict__ res,
          f16* __restrict__ Ch, f16* __restrict__ Cl,
          int K, int lda, int ldb, int ldc, float alpha, int wdiv,
          int biasStride,
          long long sAb, long long sAw, long long sBb, long long sBw,
          long long sCb, long long sCw)
{
    extern __shared__ char dsm[];
    uint32_t sb0 = s2u(dsm);

    int tid = threadIdx.x;
    int wid = tid >> 5;
    int wm = wid >> 2;
    int wn = wid & 3;
    int z = blockIdx.z;
    int zb = z / wdiv, zw = z - zb * wdiv;
    long long aoff = zb * sAb + zw * sAw;
    long long boff = zb * sBb + zw * sBw;
    long long coff = zb * sCb + zw * sCw;
    Ah += aoff; Al += aoff;
    Bh += boff;
    C  += coff;
    if (EPI == EPI_BIAS || EPI == EPI_BIAS_GELU || EPI == EPI_BIAS_RES)
        bias += (long long)zb * biasStride;
    const float* Rp = (EPI == EPI_BIAS_RES) ? (res + coff) : nullptr;

    int m0 = blockIdx.y * 128;
    int n0 = blockIdx.x * 128;

    wmma::fragment<wmma::accumulator, 16, 16, 16, float> acc[4][2];
#pragma unroll
    for (int i = 0; i < 4; i++)
#pragma unroll
        for (int j = 0; j < 2; j++) wmma::fill_fragment(acc[i][j], 0.f);

    auto loadStage = [&](int stg, int kk){
        uint32_t sb = sb0 + stg * STGB;
#pragma unroll
        for (int half = 0; half < 2; half++){
            int i = tid + half * 256;           // 0..511
            int row = i >> 2, ch = i & 3;
            uint32_t d = row * (LDSB*2) + ch * 16;
            long long ga = (long long)(m0 + row) * lda + kk + ch * 8;
            long long gb = (long long)(n0 + row) * ldb + kk + ch * 8;
            cpa16(sb + AH_OFF + d, Ah + ga);
            cpa16(sb + AL_OFF + d, Al + ga);
            cpa16(sb + BH_OFF + d, Bh + gb);
        }
    };

    int KT = K >> 5;
    loadStage(0, 0);
    cpa_commit();

    for (int kt = 0; kt < KT; kt++){
        if (kt + 1 < KT){
            loadStage((kt + 1) & 1, (kt + 1) * 32);
            cpa_commit();
            cpa_wait1();
        } else {
            cpa_wait0();
        }
        __syncthreads();

        const f16* st = (const f16*)(dsm + (kt & 1) * STGB);
        const f16* pAh = st + (AH_OFF/2) + (wm*64)*LDSB;
        const f16* pAl = st + (AL_OFF/2) + (wm*64)*LDSB;
        const f16* pBh = st + (BH_OFF/2) + (wn*32)*LDSB;
#pragma unroll
        for (int ks = 0; ks < 2; ks++){
            wmma::fragment<wmma::matrix_a, 16,16,16, f16, wmma::row_major> fAh[4], fAl[4];
            wmma::fragment<wmma::matrix_b, 16,16,16, f16, wmma::col_major> fBh[2];
#pragma unroll
            for (int i = 0; i < 4; i++){
                wmma::load_matrix_sync(fAh[i], pAh + i*16*LDSB + ks*16, LDSB);
                wmma::load_matrix_sync(fAl[i], pAl + i*16*LDSB + ks*16, LDSB);
            }
#pragma unroll
            for (int j = 0; j < 2; j++)
                wmma::load_matrix_sync(fBh[j], pBh + j*16*LDSB + ks*16, LDSB);
#pragma unroll
            for (int i = 0; i < 4; i++)
#pragma unroll
                for (int j = 0; j < 2; j++){
                    wmma::mma_sync(acc[i][j], fAh[i], fBh[j], acc[i][j]);
                    wmma::mma_sync(acc[i][j], fAl[i], fBh[j], acc[i][j]);
                }
        }
        __syncthreads();
    }

    // ---- block-wide epilogue via smem float staging ----
    float* sF = (float*)dsm;
#pragma unroll
    for (int i = 0; i < 4; i++)
#pragma unroll
        for (int j = 0; j < 2; j++)
            wmma::store_matrix_sync(
                sF + (wm*64 + i*16) * 128 + wn*32 + j*16,
                acc[i][j], 128, wmma::mem_row_major);
    __syncthreads();

#pragma unroll 1
    for (int t = 0; t < 16; t++){
        int i = tid + t * 256;
        int row = i >> 5, c4 = (i & 31) * 4;
        float4 v = *(float4*)&sF[row * 128 + c4];
        v.x *= alpha; v.y *= alpha; v.z *= alpha; v.w *= alpha;
        int gc = n0 + c4;
        if (EPI == EPI_BIAS || EPI == EPI_BIAS_GELU || EPI == EPI_BIAS_RES){
            float4 bb = *(const float4*)&bias[gc];
            v.x += bb.x; v.y += bb.y; v.z += bb.z; v.w += bb.w;
        }
        if (EPI == EPI_BIAS_GELU){
            v.x = gelu_tanh(v.x); v.y = gelu_tanh(v.y);
            v.z = gelu_tanh(v.z); v.w = gelu_tanh(v.w);
        }
        long long crow = (long long)(m0 + row) * ldc + gc;
        if (EPI == EPI_BIAS_RES){
            float4 rr = *(const float4*)&Rp[crow];
            v.x += rr.x; v.y += rr.y; v.z += rr.z; v.w += rr.w;
        }
        *(float4*)&C[crow] = v;
        if (EPI == EPI_SPLIT){
            long long so = coff + crow;
            f16 hh, ll;
            split2(v.x, hh, ll); Ch[so+0] = hh; Cl[so+0] = ll;
            split2(v.y, hh, ll); Ch[so+1] = hh; Cl[so+1] = ll;
            split2(v.z, hh, ll); Ch[so+2] = hh; Cl[so+2] = ll;
            split2(v.w, hh, ll); Ch[so+3] = hh; Cl[so+3] = ll;
        }
    }
}

// ---- bias pack ----
__global__ void packbias_kernel(const float* __restrict__ a, const float* __restrict__ b)
{
    int i = blockIdx.x * 256 + threadIdx.x;
    if (i < DIM_){ g_bias2[i] = a[i]; g_bias2[DIM_ + i] = b[i]; }
}

// ---- LayerNorm fp32 out ----
__global__ void ln_kernel(const float* __restrict__ x, float* __restrict__ y,
                          const float* __restrict__ g, const float* __restrict__ bv,
                          int L)
{
    __shared__ float buf[4096];
    __shared__ float r1[8], r2[8], st[2];
    long long row = blockIdx.x;
    const float* xr = x + row * L;
    int tid = threadIdx.x;
    float s = 0.f, s2 = 0.f;
    for (int c = tid; c < L; c += 256){ float v = xr[c]; buf[c] = v; s += v; s2 += v*v; }
#pragma unroll
    for (int o = 16; o > 0; o >>= 1){
        s  += __shfl_xor_sync(0xffffffffu, s,  o);
        s2 += __shfl_xor_sync(0xffffffffu, s2, o);
    }
    int lane = tid & 31, w = tid >> 5;
    if (lane == 0){ r1[w] = s; r2[w] = s2; }
    __syncthreads();
    if (tid == 0){
        float ts = 0.f, ts2 = 0.f;
        for (int k = 0; k < 8; k++){ ts += r1[k]; ts2 += r2[k]; }
        float mean = ts / (float)L;
        st[0] = mean; st[1] = rsqrtf(ts2 / (float)L - mean*mean + 1e-5f);
    }
    __syncthreads();
    float mean = st[0], rstd = st[1];
    float* yr = y + row * L;
    for (int c = tid; c < L; c += 256)
        yr[c] = (buf[c] - mean) * rstd * g[c] + bv[c];
}

// ---- LayerNorm -> fp16 hi/lo ----
__global__ void ln_bf_kernel(const float* __restrict__ x, f16* __restrict__ yh,
                             f16* __restrict__ yl,
                             const float* __restrict__ g, const float* __restrict__ bv,
                             int L)
{
    __shared__ float buf[4096];
    __shared__ float r1[8], r2[8], st[2];
    long long row = blockIdx.x;
    const float* xr = x + row * L;
    int tid = threadIdx.x;
    float s = 0.f, s2 = 0.f;
    for (int c = tid; c < L; c += 256){ float v = xr[c]; buf[c] = v; s += v; s2 += v*v; }
#pragma unroll
    for (int o = 16; o > 0; o >>= 1){
        s  += __shfl_xor_sync(0xffffffffu, s,  o);
        s2 += __shfl_xor_sync(0xffffffffu, s2, o);
    }
    int lane = tid & 31, w = tid >> 5;
    if (lane == 0){ r1[w] = s; r2[w] = s2; }
    __syncthreads();
    if (tid == 0){
        float ts = 0.f, ts2 = 0.f;
        for (int k = 0; k < 8; k++){ ts += r1[k]; ts2 += r2[k]; }
        float mean = ts / (float)L;
        st[0] = mean; st[1] = rsqrtf(ts2 / (float)L - mean*mean + 1e-5f);
    }
    __syncthreads();
    float mean = st[0], rstd = st[1];
    for (int c = tid; c < L; c += 256){
        float v = (buf[c] - mean) * rstd * g[c] + bv[c];
        f16 h, l; split2(v, h, l);
        yh[row * L + c] = h; yl[row * L + c] = l;
    }
}

// ---- RMSNorm over 64-dim head vectors ----
__global__ void rms_kernel(float* __restrict__ x, const float* __restrict__ g,
                           int vecs_per_row, int row_stride, int nrows)
{
    int vid = blockIdx.x * 8 + (threadIdx.x >> 5);
    int lane = threadIdx.x & 31;
    int r = vid / vecs_per_row;
    int h = vid - r * vecs_per_row;
    if (r >= nrows) return;
    float* p = x + (long long)r * row_stride + h * DHEAD_;
    float v0 = p[lane], v1 = p[lane + 32];
    float ss = v0*v0 + v1*v1;
#pragma unroll
    for (int o = 16; o > 0; o >>= 1) ss += __shfl_xor_sync(0xffffffffu, ss, o);
    float rs = rsqrtf(ss * (1.0f/64.0f) + 1e-6f);
    p[lane]      = v0 * rs * g[lane];
    p[lane + 32] = v1 * rs * g[lane + 32];
}

// ---- rotary prep: q split fp16, k single fp16 (padded layout) ----
__global__ void prep_kernel(const float* __restrict__ text,
                            const float* __restrict__ at,
                            f16* __restrict__ qh, f16* __restrict__ ql,
                            f16* __restrict__ kh)
{
    int row = blockIdx.x;
    int b = row / NP_;
    int pr = row - b * NP_;
    long long kout = (long long)row * DIM_;
    if (pr < WS_){
        f16 zz = __float2half(0.f);
        for (int c = threadIdx.x; c < DIM_; c += 256) kh[kout+c] = zz;
        return;
    }
    int t = pr - WS_;
    long long src = ((long long)b * N_ + t) * DIM_;
    for (int c = threadIdx.x; c < DIM_; c += 256){
        int j = c & 511;
        float invf = exp2f((float)j * (-13.28771238f * (1.0f/512.0f)));
        float ang = (float)t * invf;
        float cs = cosf(ang), sn = sinf(ang);
        float kx = at[src + c];
        float ko = (c < 512) ? -at[src + c + 512] : at[src + c - 512];
        kh[kout + c] = __float2half_rn(kx * cs + ko * sn);
        float qx = text[src + c];
        float qo = (c < 512) ? -text[src + c + 512] : text[src + c - 512];
        f16 h, l;
        split2(qx * cs + qo * sn, h, l);
        qh[src + c] = h; ql[src + c] = l;
    }
}

// ---- transpose to single fp16: out[c][p] = (p>=pad) ? in[p-pad][c] : 0 ----
__global__ void tconv_kernel(const float* __restrict__ in, f16* __restrict__ oh,
                             int inLd, int outLd, int pad,
                             long long inB, long long outB)
{
    __shared__ float t[32][33];
    in += blockIdx.z * inB;
    oh += blockIdx.z * outB;
    int p0 = blockIdx.x * 32, c0 = blockIdx.y * 32;
    int tx = threadIdx.x, ty = threadIdx.y;
    for (int i = ty; i < 32; i += 8){
        int r = p0 + i - pad;
        t[i][tx] = (r >= 0) ? in[(long long)r * inLd + c0 + tx] : 0.f;
    }
    __syncthreads();
    for (int i = ty; i < 32; i += 8){
        long long o = (long long)(c0 + i) * outLd + p0 + tx;
        oh[o] = __float2half_rn(t[tx][i]);
    }
}

// ---- elementwise split fp32 -> fp16 hi/lo ----
__global__ void conv_kernel(const float* __restrict__ x, f16* __restrict__ h,
                            f16* __restrict__ l, int n)
{
    int i = (blockIdx.x * 256 + threadIdx.x) * 4;
    if (i < n){
        float4 v = *(const float4*)&x[i];
        f16 hh, ll;
        split2(v.x, hh, ll); h[i+0] = hh; l[i+0] = ll;
        split2(v.y, hh, ll); h[i+1] = hh; l[i+1] = ll;
        split2(v.z, hh, ll); h[i+2] = hh; l[i+2] = ll;
        split2(v.w, hh, ll); h[i+3] = hh; l[i+3] = ll;
    }
}

// ---- local-attention masked softmax -> fp16 hi/lo ----
__global__ void softmax_local_kernel(const float* __restrict__ p,
                                     f16* __restrict__ ph, f16* __restrict__ pl)
{
    __shared__ float buf[1024];
    __shared__ float red[8], bc[2];
    int r = blockIdx.x;
    int i = r & (WS_ - 1);
    int z = r >> 9;
    int w = z & (NWIN_ - 1);
    int qp = w * WS_ + i;
    const float* row = p + (long long)r * (2 * WS_);
    int tid = threadIdx.x, lane = tid & 31, wp = tid >> 5;

    float mx = -1e30f;
    for (int j = tid; j < 2*WS_; j += 256){
        int kp = (w - 1) * WS_ + j;
        float v = (kp >= 0 && kp <= qp) ? row[j] : -1e9f;
        buf[j] = v;
        mx = fmaxf(mx, v);
    }
#pragma unroll
    for (int o = 16; o > 0; o >>= 1) mx = fmaxf(mx, __shfl_xor_sync(0xffffffffu, mx, o));
    if (lane == 0) red[wp] = mx;
    __syncthreads();
    if (tid == 0){
        float m = red[0];
        for (int k = 1; k < 8; k++) m = fmaxf(m, red[k]);
        bc[0] = m;
    }
    __syncthreads();
    mx = bc[0];
    float sum = 0.f;
    for (int j = tid; j < 2*WS_; j += 256){
        float e = __expf(buf[j] - mx);
        buf[j] = e; sum += e;
    }
#pragma unroll
    for (int o = 16; o > 0; o >>= 1) sum += __shfl_xor_sync(0xffffffffu, sum, o);
    if (lane == 0) red[wp] = sum;
    __syncthreads();
    if (tid == 0){
        float t = 0.f;
        for (int k = 0; k < 8; k++) t += red[k];
        bc[1] = 1.0f / t;
    }
    __syncthreads();
    float inv = bc[1];
    for (int j = tid; j < 2*WS_; j += 256){
        f16 h, l; split2(buf[j] * inv, h, l);
        long long o = (long long)r * (2*WS_) + j;
        ph[o] = h; pl[o] = l;
    }
}

// ---- causal flash attention fp32; packed qkv (ld 1536); emits fp16 hi/lo ----
#define QP_ 68
#define ATTN_SMEM_BYTES (4 * 64 * QP_ * 4 + 3 * 64 * 4)

__global__ void __launch_bounds__(256)
attn_kernel(const float* __restrict__ qkv,
            float* __restrict__ o, f16* __restrict__ oh, f16* __restrict__ ol)
{
    extern __shared__ float sm[];
    float* QsT = sm;
    float* KsT = QsT + 64 * QP_;
    float* Vs  = KsT + 64 * QP_;
    float* SsT = Vs  + 64 * QP_;
    float* Ms = SsT + 64 * QP_;
    float* Ls = Ms + 64;
    float* Cs = Ls + 64;

    int tid = threadIdx.x;
    int bh = blockIdx.y;
    int b = bh >> 3, h = bh & 7;
    int q0 = blockIdx.x * 64;
    int ty = tid >> 4, tx = tid & 15;

    for (int idx = tid; idx < 4096; idx += 256){
        int r = idx >> 6, c = idx & 63;
        QsT[c * QP_ + r] =
            qkv[((long long)(b * N_ + q0 + r)) * QKVLD_ + h * 64 + c] * 0.125f;
    }
    if (tid < 64){ Ms[tid] = -INFINITY; Ls[tid] = 0.f; }
    float oacc[16];
#pragma unroll
    for (int i = 0; i < 16; i++) oacc[i] = 0.f;
    __syncthreads();

    int lastTile = blockIdx.x;
    for (int kt = 0; kt <= lastTile; kt++){
        for (int idx = tid; idx < 4096; idx += 256){
            int r = idx >> 6, c = idx & 63;
            long long base =
                ((long long)(b * N_ + kt * 64 + r)) * QKVLD_ + INNER_ + h * 64 + c;
            KsT[c * QP_ + r] = qkv[base];
            Vs[r * QP_ + c]  = qkv[base + INNER_];
        }
        __syncthreads();

        float sacc[16];
#pragma unroll
        for (int i = 0; i < 16; i++) sacc[i] = 0.f;
#pragma unroll 8
        for (int kk = 0; kk < 64; kk++){
            float4 aq = *(const float4*)&QsT[kk * QP_ + ty * 4];
            float4 bk = *(const float4*)&KsT[kk * QP_ + tx * 4];
            float a4[4] = {aq.x, aq.y, aq.z, aq.w};
            float b4[4] = {bk.x, bk.y, bk.z, bk.w};
#pragma unroll
            for (int i = 0; i < 4; i++)
#pragma unroll
                for (int j = 0; j < 4; j++)
                    sacc[i*4+j] += a4[i] * b4[j];
        }
        bool diag = (kt == lastTile);
#pragma unroll
        for (int i = 0; i < 4; i++)
#pragma unroll
            for (int j = 0; j < 4; j++){
                int qr = ty * 4 + i, kc = tx * 4 + j;
                float s = sacc[i*4+j];
                if (diag && kc > qr) s = -INFINITY;
                SsT[kc * QP_ + qr] = s;
            }
        __syncthreads();

        if (tid < 64){
            int r = tid;
            float mt = -INFINITY;
#pragma unroll 8
            for (int c = 0; c < 64; c++) mt = fmaxf(mt, SsT[c * QP_ + r]);
            float mo = Ms[r];
            float mn = fmaxf(mo, mt);
            float corr = __expf(mo - mn);
            float ls = 0.f;
#pragma unroll 8
            for (int c = 0; c < 64; c++){
                float e = __expf(SsT[c * QP_ + r] - mn);
                SsT[c * QP_ + r] = e;
                ls += e;
            }
            Ls[r] = Ls[r] * corr + ls;
            Ms[r] = mn;
            Cs[r] = corr;
        }
        __syncthreads();

        float cf[4];
#pragma unroll
        for (int i = 0; i < 4; i++) cf[i] = Cs[ty * 4 + i];
#pragma unroll
        for (int i = 0; i < 4; i++)
#pragma unroll
            for (int j = 0; j < 4; j++) oacc[i*4+j] *= cf[i];

#pragma unroll 8
        for (int kk = 0; kk < 64; kk++){
            float4 ap = *(const float4*)&SsT[kk * QP_ + ty * 4];
            float4 vv = *(const float4*)&Vs[kk * QP_ + tx * 4];
            float a4[4] = {ap.x, ap.y, ap.z, ap.w};
            float b4[4] = {vv.x, vv.y, vv.z, vv.w};
#pragma unroll
            for (int i = 0; i < 4; i++)
#pragma unroll
                for (int j = 0; j < 4; j++)
                    oacc[i*4+j] += a4[i] * b4[j];
        }
        __syncthreads();
    }

#pragma unroll
    for (int i = 0; i < 4; i++){
        float inv = 1.0f / Ls[ty * 4 + i];
        long long orow =
            ((long long)(b * N_ + q0 + ty * 4 + i)) * INNER_ + h * 64 + tx * 4;
        float4 vo = make_float4(oacc[i*4+0]*inv, oacc[i*4+1]*inv,
                                oacc[i*4+2]*inv, oacc[i*4+3]*inv);
        *(float4*)&o[orow] = vo;
        f16 hh, ll;
        split2(vo.x, hh, ll); oh[orow+0] = hh; ol[orow+0] = ll;
        split2(vo.y, hh, ll); oh[orow+1] = hh; ol[orow+1] = ll;
        split2(vo.z, hh, ll); oh[orow+2] = hh; ol[orow+2] = ll;
        split2(vo.w, hh, ll); oh[orow+3] = hh; ol[orow+3] = ll;
    }
}

// ---- launch ----
extern "C" void kernel_launch(void* const* d_in, const int* in_sizes, int n_in,
                              void* d_out, int out_size)
{
    (void)in_sizes; (void)n_in; (void)out_size;
    const float* text  = (const float*)d_in[0];
    const float* audio = (const float*)d_in[1];
    const float* video = (const float*)d_in[2];
    const float* Wa    = (const float*)d_in[3];
    const float* ba    = (const float*)d_in[4];
    const float* lna_g = (const float*)d_in[5];
    const float* lna_b = (const float*)d_in[6];
    const float* Wvid  = (const float*)d_in[7];
    const float* bvid  = (const float*)d_in[8];
    const float* lnv_g = (const float*)d_in[9];
    const float* lnv_b = (const float*)d_in[10];
    const float* ln1_g = (const float*)d_in[11];
    const float* ln1_b = (const float*)d_in[12];
    const float* Wq    = (const float*)d_in[13];
    const float* Wkv   = (const float*)d_in[14];
    const float* qn_g  = (const float*)d_in[15];
    const float* kn_g  = (const float*)d_in[16];
    const float* Wo    = (const float*)d_in[17];
    const float* W1    = (const float*)d_in[18];
    const float* b1    = (const float*)d_in[19];
    const float* ln2_g = (const float*)d_in[20];
    const float* ln2_b = (const float*)d_in[21];
    const float* W2    = (const float*)d_in[22];
    const float* b2    = (const float*)d_in[23];
    float* out = (float*)d_out;

#define SYM(p, s) void* p; cudaGetSymbolAddress(&p, s)
    SYM(atvt, g_atvt); SYM(probs, g_probs);
    SYM(x, g_x);     SYM(qkvp, g_qkv);
    SYM(ob, g_o);    SYM(x2, g_x2);   SYM(ff, g_ff);
    SYM(bias2, g_bias2);
    SYM(inH, g_inH); SYM(inL, g_inL);
    SYM(qh, g_qh);   SYM(ql, g_ql);
    SYM(kh, g_kh);   SYM(vTh, g_vTh);
    SYM(ph, g_ph);   SYM(pl, g_pl);
    SYM(hh, g_hh);   SYM(hl, g_hl);
    SYM(obH, g_obH); SYM(obL, g_obL);
    SYM(x2H, g_x2H); SYM(x2L, g_x2L);
    SYM(ffH, g_ffH); SYM(ffL, g_ffL);
    SYM(WavT, g_WavT); SYM(WqkvT, g_WqkvT);
    SYM(WoT, g_WoT); SYM(W1T, g_W1T); SYM(W2T, g_W2T);
#undef SYM

    cudaFuncSetAttribute(gemm_wmma<EPI_NONE>,      cudaFuncAttributeMaxDynamicSharedMemorySize, GEMM_SMEM_DYN);
    cudaFuncSetAttribute(gemm_wmma<EPI_BIAS>,      cudaFuncAttributeMaxDynamicSharedMemorySize, GEMM_SMEM_DYN);
    cudaFuncSetAttribute(gemm_wmma<EPI_BIAS_GELU>, cudaFuncAttributeMaxDynamicSharedMemorySize, GEMM_SMEM_DYN);
    cudaFuncSetAttribute(gemm_wmma<EPI_BIAS_RES>,  cudaFuncAttributeMaxDynamicSharedMemorySize, GEMM_SMEM_DYN);
    cudaFuncSetAttribute(gemm_wmma<EPI_SPLIT>,     cudaFuncAttributeMaxDynamicSharedMemorySize, GEMM_SMEM_DYN);
    cudaFuncSetAttribute(attn_kernel, cudaFuncAttributeMaxDynamicSharedMemorySize, ATTN_SMEM_BYTES);

    dim3 t32(32, 8);
    long long DD = (long long)DIM_ * DIM_;
    long long BD = (long long)BN_ * DIM_;

    packbias_kernel<<<4, 256>>>(ba, bvid);
    tconv_kernel<<<dim3(32, 32, 1), t32>>>(Wa,  (f16*)WavT,      DIM_, DIM_, 0, 0, 0);
    tconv_kernel<<<dim3(32, 32, 1), t32>>>(Wvid,(f16*)WavT + DD, DIM_, DIM_, 0, 0, 0);
    conv_kernel<<<BN_*DIM_/1024, 256>>>(audio, (f16*)inH, (f16*)inL, BN_*DIM_);
    conv_kernel<<<BN_*DIM_/1024, 256>>>(video, (f16*)inH + BD, (f16*)inL + BD, BN_*DIM_);

    // 1) merged adapters (batched over audio/video)
    gemm_wmma<EPI_BIAS><<<dim3(DIM_/128, BN_/128, 2), 256, GEMM_SMEM_DYN>>>(
        (f16*)inH, (f16*)inL, (f16*)WavT, (float*)atvt, (float*)bias2, nullptr,
        nullptr, nullptr, DIM_, DIM_, DIM_, DIM_, 1.f, 1, DIM_,
        BD, 0, DD, 0, BD, 0);

    tconv_kernel<<<dim3(32, 16, 1), t32>>>(Wq,  (f16*)WqkvT, INNER_, DIM_, 0, 0, 0);
    tconv_kernel<<<dim3(32, 32, 1), t32>>>(Wkv, (f16*)WqkvT + (long long)INNER_*DIM_, 2*INNER_, DIM_, 0, 0, 0);
    tconv_kernel<<<dim3(16, 32, 1), t32>>>(Wo,  (f16*)WoT, DIM_, INNER_, 0, 0, 0);
    tconv_kernel<<<dim3(32, 128,1), t32>>>(W1,  (f16*)W1T, FF_,  DIM_,   0, 0, 0);
    tconv_kernel<<<dim3(128,32, 1), t32>>>(W2,  (f16*)W2T, DIM_, FF_,    0, 0, 0);

    float* at = (float*)atvt;
    float* vt = (float*)atvt + BD;
    ln_kernel<<<BN_, 256>>>(at, at, lna_g, lna_b, DIM_);
    ln_kernel<<<BN_, 256>>>(vt, vt, lnv_g, lnv_b, DIM_);

    // 2) rotary + padded layouts
    prep_kernel<<<B_ * NP_, 256>>>(text, at, (f16*)qh, (f16*)ql, (f16*)kh);
    tconv_kernel<<<dim3(NP_/32, DIM_/32, B_), t32>>>(vt,
        (f16*)vTh, DIM_, NP_, WS_,
        (long long)N_*DIM_, (long long)DIM_*NP_);

    // 3) local attention (8 windows batched)
    gemm_wmma<EPI_NONE><<<dim3((2*WS_)/128, WS_/128, B_*NWIN_), 256, GEMM_SMEM_DYN>>>(
        (f16*)qh, (f16*)ql, (f16*)kh, (float*)probs, nullptr, nullptr,
        nullptr, nullptr, DIM_, DIM_, DIM_, 2*WS_, 0.03125f, NWIN_, 0,
        (long long)N_*DIM_,  (long long)WS_*DIM_,
        (long long)NP_*DIM_, (long long)WS_*DIM_,
        (long long)NWIN_*WS_*2*WS_, (long long)WS_*2*WS_);
    softmax_local_kernel<<<B_*NWIN_*WS_, 256>>>((float*)probs, (f16*)ph, (f16*)pl);
    gemm_wmma<EPI_NONE><<<dim3(DIM_/128, WS_/128, B_*NWIN_), 256, GEMM_SMEM_DYN>>>(
        (f16*)ph, (f16*)pl, (f16*)vTh, (float*)x, nullptr, nullptr,
        nullptr, nullptr, 2*WS_, 2*WS_, NP_, DIM_, 1.f, NWIN_, 0,
        (long long)NWIN_*WS_*2*WS_, (long long)WS_*2*WS_,
        (long long)DIM_*NP_, (long long)WS_,
        (long long)N_*DIM_, (long long)WS_*DIM_);

    // 4) ln1 -> merged qkv projection -> rmsnorm
    ln_bf_kernel<<<BN_, 256>>>((float*)x, (f16*)hh, (f16*)hl, ln1_g, ln1_b, DIM_);
    gemm_wmma<EPI_NONE><<<dim3(QKVLD_/128, BN_/128, 1), 256, GEMM_SMEM_DYN>>>(
        (f16*)hh, (f16*)hl, (f16*)WqkvT, (float*)qkvp, nullptr, nullptr,
        nullptr, nullptr, DIM_, DIM_, DIM_, QKVLD_, 1.f, 1, 0, 0,0,0,0,0,0);
    rms_kernel<<<(BN_*HEADS_)/8, 256>>>((float*)qkvp, qn_g, HEADS_, QKVLD_, BN_);
    rms_kernel<<<(BN_*HEADS_)/8, 256>>>((float*)qkvp + INNER_, kn_g, HEADS_, QKVLD_, BN_);

    // 5) causal attention
    attn_kernel<<<dim3(N_/64, B_*HEADS_), 256, ATTN_SMEM_BYTES>>>(
        (float*)qkvp, (float*)ob, (f16*)obH, (f16*)obL);

    // 6) x2 = 2*(o @ Wo), emits fp32 + fp16 split
    gemm_wmma<EPI_SPLIT><<<dim3(DIM_/128, BN_/128, 1), 256, GEMM_SMEM_DYN>>>(
        (f16*)obH, (f16*)obL, (f16*)WoT, (float*)x2, nullptr, nullptr,
        (f16*)x2H, (f16*)x2L, INNER_, INNER_, INNER_, DIM_, 2.f, 1, 0, 0,0,0,0,0,0);

    // 7) FFN
    gemm_wmma<EPI_BIAS_GELU><<<dim3(FF_/128, BN_/128, 1), 256, GEMM_SMEM_DYN>>>(
        (f16*)x2H, (f16*)x2L, (f16*)W1T, (float*)ff, b1, nullptr,
        nullptr, nullptr, DIM_, DIM_, DIM_, FF_, 1.f, 1, 0, 0,0,0,0,0,0);
    ln_bf_kernel<<<BN_, 256>>>((float*)ff, (f16*)ffH, (f16*)ffL, ln2_g, ln2_b, FF_);
    gemm_wmma<EPI_BIAS_RES><<<dim3(DIM_/128, BN_/128, 1), 256, GEMM_SMEM_DYN>>>(
        (f16*)ffH, (f16*)ffL, (f16*)W2T, out, b2, (float*)x2,
        nullptr, nullptr, FF_, FF_, FF_, DIM_, 1.f, 1, 0, 0,0,0,0,0,0);
}

// round 14
// speedup vs baseline: 1.9811x; 1.1065x over previous
#include <cuda_runtime.h>
#include <cuda_fp16.h>
#include <mma.h>
#include <math.h>
#include <stdint.h>

using namespace nvcuda;
typedef __half f16;

#define B_      2
#define N_      2048
#define DIM_    1024
#define INNER_  512
#define HEADS_  8
#define DHEAD_  64
#define WS_     512
#define FF_     4096
#define BN_     (B_*N_)
#define NP_     (N_+WS_)
#define NWIN_   (N_/WS_)
#define QKVLD_  1536

// ---- fp32 scratch ----
__device__ float g_atvt[2*BN_*DIM_];
__device__ float g_probs[B_*NWIN_*WS_*2*WS_];
__device__ float g_x  [BN_*DIM_];
__device__ float g_qkv[BN_*QKVLD_];
__device__ float g_o  [BN_*INNER_];
__device__ float g_x2 [BN_*DIM_];
__device__ float g_ff [BN_*FF_];
__device__ float g_bias2[2*DIM_];

// ---- fp16 scratch ----
__device__ f16 g_inH [2*BN_*DIM_], g_inL [2*BN_*DIM_];
__device__ f16 g_qh [BN_*DIM_],   g_ql [BN_*DIM_];
__device__ f16 g_kh [B_*NP_*DIM_];
__device__ f16 g_vTh[B_*DIM_*NP_];
__device__ f16 g_ph [B_*NWIN_*WS_*2*WS_], g_pl[B_*NWIN_*WS_*2*WS_];
__device__ f16 g_hh [BN_*DIM_],   g_hl [BN_*DIM_];
__device__ f16 g_obH[BN_*INNER_], g_obL[BN_*INNER_];
__device__ f16 g_x2H[BN_*DIM_],   g_x2L[BN_*DIM_];
__device__ f16 g_ffH[BN_*FF_],    g_ffL[BN_*FF_];
__device__ f16 g_WavT[2*DIM_*DIM_];
__device__ f16 g_WqkvT[QKVLD_*DIM_];
__device__ f16 g_WoT [DIM_*INNER_];
__device__ f16 g_W1T [FF_*DIM_];
__device__ f16 g_W2T [DIM_*FF_];

// ---- helpers ----
__device__ __forceinline__ uint32_t s2u(const void* p){
    uint32_t a;
    asm("{ .reg .u64 t; cvta.to.shared.u64 t, %1; cvt.u32.u64 %0, t; }"
        : "=r"(a) : "l"(p));
    return a;
}
__device__ __forceinline__ void cpa16(uint32_t d, const void* s){
    asm volatile("cp.async.cg.shared.global [%0], [%1], 16;" :: "r"(d), "l"(s));
}
__device__ __forceinline__ void cpa_commit(){
    asm volatile("cp.async.commit_group;" ::: "memory");
}
__device__ __forceinline__ void cpa_wait0(){
    asm volatile("cp.async.wait_group 0;" ::: "memory");
}
__device__ __forceinline__ void cpa_wait1(){
    asm volatile("cp.async.wait_group 1;" ::: "memory");
}
__device__ __forceinline__ void split2(float v, f16& h, f16& l){
    h = __float2half_rn(v);
    l = __float2half_rn(v - __half2float(h));
}
__device__ __forceinline__ float gelu_tanh(float v){
    float c = v + 0.044715f * v * v * v;
    return 0.5f * v * (1.0f + tanhf(0.7978845608028654f * c));
}

// ---- fp16 split-A GEMM: C = alpha*(Ah+Al)*Bh^T (+epi). 128x128, BK=32 ----
// Register-lean mainloop: hold 2 B-frags, stream A row-by-row -> <=128 regs,
// 2 CTAs/SM (launch_bounds(256,2)).
#define LDSB 40
#define MATB (128*LDSB*2)
#define AH_OFF 0
#define AL_OFF MATB
#define BH_OFF (2*MATB)
#define STGB  (3*MATB)             // 30720 per stage
#define GEMM_SMEM_DYN 65536        // max(2*STGB, 64KB epilogue)

#define EPI_NONE       0
#define EPI_BIAS       1
#define EPI_BIAS_GELU  2
#define EPI_BIAS_RES   3
#define EPI_SPLIT      4

template<int EPI>
__global__ void __launch_bounds__(256, 2)
gemm_wmma(const f16* __restrict__ Ah, const f16* __restrict__ Al,
          const f16* __restrict__ Bh,
          float* __restrict__ C, const float* __restrict__ bias,
          const float* __restrict__ res,
          f16* __restrict__ Ch, f16* __restrict__ Cl,
          int K, int lda, int ldb, int ldc, float alpha, int wdiv,
          int biasStride,
          long long sAb, long long sAw, long long sBb, long long sBw,
          long long sCb, long long sCw)
{
    extern __shared__ char dsm[];
    uint32_t sb0 = s2u(dsm);

    int tid = threadIdx.x;
    int wid = tid >> 5;
    int wm = wid >> 2;
    int wn = wid & 3;
    int z = blockIdx.z;
    int zb = z / wdiv, zw = z - zb * wdiv;
    long long aoff = zb * sAb + zw * sAw;
    long long boff = zb * sBb + zw * sBw;
    long long coff = zb * sCb + zw * sCw;
    Ah += aoff; Al += aoff;
    Bh += boff;
    C  += coff;
    if (EPI == EPI_BIAS || EPI == EPI_BIAS_GELU || EPI == EPI_BIAS_RES)
        bias += (long long)zb * biasStride;
    const float* Rp = (EPI == EPI_BIAS_RES) ? (res + coff) : nullptr;

    int m0 = blockIdx.y * 128;
    int n0 = blockIdx.x * 128;

    wmma::fragment<wmma::accumulator, 16, 16, 16, float> acc[4][2];
#pragma unroll
    for (int i = 0; i < 4; i++)
#pragma unroll
        for (int j = 0; j < 2; j++) wmma::fill_fragment(acc[i][j], 0.f);

    auto loadStage = [&](int stg, int kk){
        uint32_t sb = sb0 + stg * STGB;
#pragma unroll
        for (int half = 0; half < 2; half++){
            int i = tid + half * 256;
            int row = i >> 2, ch = i & 3;
            uint32_t d = row * (LDSB*2) + ch * 16;
            long long ga = (long long)(m0 + row) * lda + kk + ch * 8;
            long long gb = (long long)(n0 + row) * ldb + kk + ch * 8;
            cpa16(sb + AH_OFF + d, Ah + ga);
            cpa16(sb + AL_OFF + d, Al + ga);
            cpa16(sb + BH_OFF + d, Bh + gb);
        }
    };

    int KT = K >> 5;
    loadStage(0, 0);
    cpa_commit();

    for (int kt = 0; kt < KT; kt++){
        if (kt + 1 < KT){
            loadStage((kt + 1) & 1, (kt + 1) * 32);
            cpa_commit();
            cpa_wait1();
        } else {
            cpa_wait0();
        }
        __syncthreads();

        const f16* st = (const f16*)(dsm + (kt & 1) * STGB);
        const f16* pAh = st + (AH_OFF/2) + (wm*64)*LDSB;
        const f16* pAl = st + (AL_OFF/2) + (wm*64)*LDSB;
        const f16* pBh = st + (BH_OFF/2) + (wn*32)*LDSB;
#pragma unroll
        for (int ks = 0; ks < 2; ks++){
            wmma::fragment<wmma::matrix_b, 16,16,16, f16, wmma::col_major> fBh[2];
#pragma unroll
            for (int j = 0; j < 2; j++)
                wmma::load_matrix_sync(fBh[j], pBh + j*16*LDSB + ks*16, LDSB);
#pragma unroll
            for (int i = 0; i < 4; i++){
                wmma::fragment<wmma::matrix_a, 16,16,16, f16, wmma::row_major> fAh, fAl;
                wmma::load_matrix_sync(fAh, pAh + i*16*LDSB + ks*16, LDSB);
                wmma::load_matrix_sync(fAl, pAl + i*16*LDSB + ks*16, LDSB);
#pragma unroll
                for (int j = 0; j < 2; j++){
                    wmma::mma_sync(acc[i][j], fAh, fBh[j], acc[i][j]);
                    wmma::mma_sync(acc[i][j], fAl, fBh[j], acc[i][j]);
                }
            }
        }
        __syncthreads();
    }

    // ---- block-wide epilogue via smem float staging ----
    float* sF = (float*)dsm;
#pragma unroll
    for (int i = 0; i < 4; i++)
#pragma unroll
        for (int j = 0; j < 2; j++)
            wmma::store_matrix_sync(
                sF + (wm*64 + i*16) * 128 + wn*32 + j*16,
                acc[i][j], 128, wmma::mem_row_major);
    __syncthreads();

#pragma unroll 1
    for (int t = 0; t < 16; t++){
        int i = tid + t * 256;
        int row = i >> 5, c4 = (i & 31) * 4;
        float4 v = *(float4*)&sF[row * 128 + c4];
        v.x *= alpha; v.y *= alpha; v.z *= alpha; v.w *= alpha;
        int gc = n0 + c4;
        if (EPI == EPI_BIAS || EPI == EPI_BIAS_GELU || EPI == EPI_BIAS_RES){
            float4 bb = *(const float4*)&bias[gc];
            v.x += bb.x; v.y += bb.y; v.z += bb.z; v.w += bb.w;
        }
        if (EPI == EPI_BIAS_GELU){
            v.x = gelu_tanh(v.x); v.y = gelu_tanh(v.y);
            v.z = gelu_tanh(v.z); v.w = gelu_tanh(v.w);
        }
        long long crow = (long long)(m0 + row) * ldc + gc;
        if (EPI == EPI_BIAS_RES){
            float4 rr = *(const float4*)&Rp[crow];
            v.x += rr.x; v.y += rr.y; v.z += rr.z; v.w += rr.w;
        }
        *(float4*)&C[crow] = v;
        if (EPI == EPI_SPLIT){
            long long so = coff + crow;
            f16 hh, ll;
            split2(v.x, hh, ll); Ch[so+0] = hh; Cl[so+0] = ll;
            split2(v.y, hh, ll); Ch[so+1] = hh; Cl[so+1] = ll;
            split2(v.z, hh, ll); Ch[so+2] = hh; Cl[so+2] = ll;
            split2(v.w, hh, ll); Ch[so+3] = hh; Cl[so+3] = ll;
        }
    }
}

// ---- bias pack ----
__global__ void packbias_kernel(const float* __restrict__ a, const float* __restrict__ b)
{
    int i = blockIdx.x * 256 + threadIdx.x;
    if (i < DIM_){ g_bias2[i] = a[i]; g_bias2[DIM_ + i] = b[i]; }
}

// ---- LayerNorm fp32 out ----
__global__ void ln_kernel(const float* __restrict__ x, float* __restrict__ y,
                          const float* __restrict__ g, const float* __restrict__ bv,
                          int L)
{
    __shared__ float buf[4096];
    __shared__ float r1[8], r2[8], st[2];
    long long row = blockIdx.x;
    const float* xr = x + row * L;
    int tid = threadIdx.x;
    float s = 0.f, s2 = 0.f;
    for (int c = tid; c < L; c += 256){ float v = xr[c]; buf[c] = v; s += v; s2 += v*v; }
#pragma unroll
    for (int o = 16; o > 0; o >>= 1){
        s  += __shfl_xor_sync(0xffffffffu, s,  o);
        s2 += __shfl_xor_sync(0xffffffffu, s2, o);
    }
    int lane = tid & 31, w = tid >> 5;
    if (lane == 0){ r1[w] = s; r2[w] = s2; }
    __syncthreads();
    if (tid == 0){
        float ts = 0.f, ts2 = 0.f;
        for (int k = 0; k < 8; k++){ ts += r1[k]; ts2 += r2[k]; }
        float mean = ts / (float)L;
        st[0] = mean; st[1] = rsqrtf(ts2 / (float)L - mean*mean + 1e-5f);
    }
    __syncthreads();
    float mean = st[0], rstd = st[1];
    float* yr = y + row * L;
    for (int c = tid; c < L; c += 256)
        yr[c] = (buf[c] - mean) * rstd * g[c] + bv[c];
}

// ---- LayerNorm -> fp16 hi/lo ----
__global__ void ln_bf_kernel(const float* __restrict__ x, f16* __restrict__ yh,
                             f16* __restrict__ yl,
                             const float* __restrict__ g, const float* __restrict__ bv,
                             int L)
{
    __shared__ float buf[4096];
    __shared__ float r1[8], r2[8], st[2];
    long long row = blockIdx.x;
    const float* xr = x + row * L;
    int tid = threadIdx.x;
    float s = 0.f, s2 = 0.f;
    for (int c = tid; c < L; c += 256){ float v = xr[c]; buf[c] = v; s += v; s2 += v*v; }
#pragma unroll
    for (int o = 16; o > 0; o >>= 1){
        s  += __shfl_xor_sync(0xffffffffu, s,  o);
        s2 += __shfl_xor_sync(0xffffffffu, s2, o);
    }
    int lane = tid & 31, w = tid >> 5;
    if (lane == 0){ r1[w] = s; r2[w] = s2; }
    __syncthreads();
    if (tid == 0){
        float ts = 0.f, ts2 = 0.f;
        for (int k = 0; k < 8; k++){ ts += r1[k]; ts2 += r2[k]; }
        float mean = ts / (float)L;
        st[0] = mean; st[1] = rsqrtf(ts2 / (float)L - mean*mean + 1e-5f);
    }
    __syncthreads();
    float mean = st[0], rstd = st[1];
    for (int c = tid; c < L; c += 256){
        float v = (buf[c] - mean) * rstd * g[c] + bv[c];
        f16 h, l; split2(v, h, l);
        yh[row * L + c] = h; yl[row * L + c] = l;
    }
}

// ---- RMSNorm over 64-dim head vectors ----
__global__ void rms_kernel(float* __restrict__ x, const float* __restrict__ g,
                           int vecs_per_row, int row_stride, int nrows)
{
    int vid = blockIdx.x * 8 + (threadIdx.x >> 5);
    int lane = threadIdx.x & 31;
    int r = vid / vecs_per_row;
    int h = vid - r * vecs_per_row;
    if (r >= nrows) return;
    float* p = x + (long long)r * row_stride + h * DHEAD_;
    float v0 = p[lane], v1 = p[lane + 32];
    float ss = v0*v0 + v1*v1;
#pragma unroll
    for (int o = 16; o > 0; o >>= 1) ss += __shfl_xor_sync(0xffffffffu, ss, o);
    float rs = rsqrtf(ss * (1.0f/64.0f) + 1e-6f);
    p[lane]      = v0 * rs * g[lane];
    p[lane + 32] = v1 * rs * g[lane + 32];
}

// ---- rotary prep: q split fp16, k single fp16 ----
__global__ void prep_kernel(const float* __restrict__ text,
                            const float* __restrict__ at,
                            f16* __restrict__ qh, f16* __restrict__ ql,
                            f16* __restrict__ kh)
{
    int row = blockIdx.x;
    int b = row / NP_;
    int pr = row - b * NP_;
    long long kout = (long long)row * DIM_;
    if (pr < WS_){
        f16 zz = __float2half(0.f);
        for (int c = threadIdx.x; c < DIM_; c += 256) kh[kout+c] = zz;
        return;
    }
    int t = pr - WS_;
    long long src = ((long long)b * N_ + t) * DIM_;
    for (int c = threadIdx.x; c < DIM_; c += 256){
        int j = c & 511;
        float invf = exp2f((float)j * (-13.28771238f * (1.0f/512.0f)));
        float ang = (float)t * invf;
        float cs = cosf(ang), sn = sinf(ang);
        float kx = at[src + c];
        float ko = (c < 512) ? -at[src + c + 512] : at[src + c - 512];
        kh[kout + c] = __float2half_rn(kx * cs + ko * sn);
        float qx = text[src + c];
        float qo = (c < 512) ? -text[src + c + 512] : text[src + c - 512];
        f16 h, l;
        split2(qx * cs + qo * sn, h, l);
        qh[src + c] = h; ql[src + c] = l;
    }
}

// ---- transpose to single fp16 ----
__global__ void tconv_kernel(const float* __restrict__ in, f16* __restrict__ oh,
                             int inLd, int outLd, int pad,
                             long long inB, long long outB)
{
    __shared__ float t[32][33];
    in += blockIdx.z * inB;
    oh += blockIdx.z * outB;
    int p0 = blockIdx.x * 32, c0 = blockIdx.y * 32;
    int tx = threadIdx.x, ty = threadIdx.y;
    for (int i = ty; i < 32; i += 8){
        int r = p0 + i - pad;
        t[i][tx] = (r >= 0) ? in[(long long)r * inLd + c0 + tx] : 0.f;
    }
    __syncthreads();
    for (int i = ty; i < 32; i += 8){
        long long o = (long long)(c0 + i) * outLd + p0 + tx;
        oh[o] = __float2half_rn(t[tx][i]);
    }
}

// ---- elementwise split fp32 -> fp16 hi/lo ----
__global__ void conv_kernel(const float* __restrict__ x, f16* __restrict__ h,
                            f16* __restrict__ l, int n)
{
    int i = (blockIdx.x * 256 + threadIdx.x) * 4;
    if (i < n){
        float4 v = *(const float4*)&x[i];
        f16 hh, ll;
        split2(v.x, hh, ll); h[i+0] = hh; l[i+0] = ll;
        split2(v.y, hh, ll); h[i+1] = hh; l[i+1] = ll;
        split2(v.z, hh, ll); h[i+2] = hh; l[i+2] = ll;
        split2(v.w, hh, ll); h[i+3] = hh; l[i+3] = ll;
    }
}

// ---- local-attention masked softmax -> fp16 hi/lo ----
__global__ void softmax_local_kernel(const float* __restrict__ p,
                                     f16* __restrict__ ph, f16* __restrict__ pl)
{
    __shared__ float buf[1024];
    __shared__ float red[8], bc[2];
    int r = blockIdx.x;
    int i = r & (WS_ - 1);
    int z = r >> 9;
    int w = z & (NWIN_ - 1);
    int qp = w * WS_ + i;
    const float* row = p + (long long)r * (2 * WS_);
    int tid = threadIdx.x, lane = tid & 31, wp = tid >> 5;

    float mx = -1e30f;
    for (int j = tid; j < 2*WS_; j += 256){
        int kp = (w - 1) * WS_ + j;
        float v = (kp >= 0 && kp <= qp) ? row[j] : -1e9f;
        buf[j] = v;
        mx = fmaxf(mx, v);
    }
#pragma unroll
    for (int o = 16; o > 0; o >>= 1) mx = fmaxf(mx, __shfl_xor_sync(0xffffffffu, mx, o));
    if (lane == 0) red[wp] = mx;
    __syncthreads();
    if (tid == 0){
        float m = red[0];
        for (int k = 1; k < 8; k++) m = fmaxf(m, red[k]);
        bc[0] = m;
    }
    __syncthreads();
    mx = bc[0];
    float sum = 0.f;
    for (int j = tid; j < 2*WS_; j += 256){
        float e = __expf(buf[j] - mx);
        buf[j] = e; sum += e;
    }
#pragma unroll
    for (int o = 16; o > 0; o >>= 1) sum += __shfl_xor_sync(0xffffffffu, sum, o);
    if (lane == 0) red[wp] = sum;
    __syncthreads();
    if (tid == 0){
        float t = 0.f;
        for (int k = 0; k < 8; k++) t += red[k];
        bc[1] = 1.0f / t;
    }
    __syncthreads();
    float inv = bc[1];
    for (int j = tid; j < 2*WS_; j += 256){
        f16 h, l; split2(buf[j] * inv, h, l);
        long long o = (long long)r * (2*WS_) + j;
        ph[o] = h; pl[o] = l;
    }
}

// ---- causal flash attention fp32; packed qkv (ld 1536); emits fp16 hi/lo ----
#define QP_ 68
#define ATTN_SMEM_BYTES (4 * 64 * QP_ * 4 + 3 * 64 * 4)

__global__ void __launch_bounds__(256)
attn_kernel(const float* __restrict__ qkv,
            float* __restrict__ o, f16* __restrict__ oh, f16* __restrict__ ol)
{
    extern __shared__ float sm[];
    float* QsT = sm;
    float* KsT = QsT + 64 * QP_;
    float* Vs  = KsT + 64 * QP_;
    float* SsT = Vs  + 64 * QP_;
    float* Ms = SsT + 64 * QP_;
    float* Ls = Ms + 64;
    float* Cs = Ls + 64;

    int tid = threadIdx.x;
    int bh = blockIdx.y;
    int b = bh >> 3, h = bh & 7;
    int q0 = blockIdx.x * 64;
    int ty = tid >> 4, tx = tid & 15;

    for (int idx = tid; idx < 4096; idx += 256){
        int r = idx >> 6, c = idx & 63;
        QsT[c * QP_ + r] =
            qkv[((long long)(b * N_ + q0 + r)) * QKVLD_ + h * 64 + c] * 0.125f;
    }
    if (tid < 64){ Ms[tid] = -INFINITY; Ls[tid] = 0.f; }
    float oacc[16];
#pragma unroll
    for (int i = 0; i < 16; i++) oacc[i] = 0.f;
    __syncthreads();

    int lastTile = blockIdx.x;
    for (int kt = 0; kt <= lastTile; kt++){
        for (int idx = tid; idx < 4096; idx += 256){
            int r = idx >> 6, c = idx & 63;
            long long base =
                ((long long)(b * N_ + kt * 64 + r)) * QKVLD_ + INNER_ + h * 64 + c;
            KsT[c * QP_ + r] = qkv[base];
            Vs[r * QP_ + c]  = qkv[base + INNER_];
        }
        __syncthreads();

        float sacc[16];
#pragma unroll
        for (int i = 0; i < 16; i++) sacc[i] = 0.f;
#pragma unroll 8
        for (int kk = 0; kk < 64; kk++){
            float4 aq = *(const float4*)&QsT[kk * QP_ + ty * 4];
            float4 bk = *(const float4*)&KsT[kk * QP_ + tx * 4];
            float a4[4] = {aq.x, aq.y, aq.z, aq.w};
            float b4[4] = {bk.x, bk.y, bk.z, bk.w};
#pragma unroll
            for (int i = 0; i < 4; i++)
#pragma unroll
                for (int j = 0; j < 4; j++)
                    sacc[i*4+j] += a4[i] * b4[j];
        }
        bool diag = (kt == lastTile);
#pragma unroll
        for (int i = 0; i < 4; i++)
#pragma unroll
            for (int j = 0; j < 4; j++){
                int qr = ty * 4 + i, kc = tx * 4 + j;
                float s = sacc[i*4+j];
                if (diag && kc > qr) s = -INFINITY;
                SsT[kc * QP_ + qr] = s;
            }
        __syncthreads();

        if (tid < 64){
            int r = tid;
            float mt = -INFINITY;
#pragma unroll 8
            for (int c = 0; c < 64; c++) mt = fmaxf(mt, SsT[c * QP_ + r]);
            float mo = Ms[r];
            float mn = fmaxf(mo, mt);
            float corr = __expf(mo - mn);
            float ls = 0.f;
#pragma unroll 8
            for (int c = 0; c < 64; c++){
                float e = __expf(SsT[c * QP_ + r] - mn);
                SsT[c * QP_ + r] = e;
                ls += e;
            }
            Ls[r] = Ls[r] * corr + ls;
            Ms[r] = mn;
            Cs[r] = corr;
        }
        __syncthreads();

        float cf[4];
#pragma unroll
        for (int i = 0; i < 4; i++) cf[i] = Cs[ty * 4 + i];
#pragma unroll
        for (int i = 0; i < 4; i++)
#pragma unroll
            for (int j = 0; j < 4; j++) oacc[i*4+j] *= cf[i];

#pragma unroll 8
        for (int kk = 0; kk < 64; kk++){
            float4 ap = *(const float4*)&SsT[kk * QP_ + ty * 4];
            float4 vv = *(const float4*)&Vs[kk * QP_ + tx * 4];
            float a4[4] = {ap.x, ap.y, ap.z, ap.w};
            float b4[4] = {vv.x, vv.y, vv.z, vv.w};
#pragma unroll
            for (int i = 0; i < 4; i++)
#pragma unroll
                for (int j = 0; j < 4; j++)
                    oacc[i*4+j] += a4[i] * b4[j];
        }
        __syncthreads();
    }

#pragma unroll
    for (int i = 0; i < 4; i++){
        float inv = 1.0f / Ls[ty * 4 + i];
        long long orow =
            ((long long)(b * N_ + q0 + ty * 4 + i)) * INNER_ + h * 64 + tx * 4;
        float4 vo = make_float4(oacc[i*4+0]*inv, oacc[i*4+1]*inv,
                                oacc[i*4+2]*inv, oacc[i*4+3]*inv);
        *(float4*)&o[orow] = vo;
        f16 hh, ll;
        split2(vo.x, hh, ll); oh[orow+0] = hh; ol[orow+0] = ll;
        split2(vo.y, hh, ll); oh[orow+1] = hh; ol[orow+1] = ll;
        split2(vo.z, hh, ll); oh[orow+2] = hh; ol[orow+2] = ll;
        split2(vo.w, hh, ll); oh[orow+3] = hh; ol[orow+3] = ll;
    }
}

// ---- launch ----
extern "C" void kernel_launch(void* const* d_in, const int* in_sizes, int n_in,
                              void* d_out, int out_size)
{
    (void)in_sizes; (void)n_in; (void)out_size;
    const float* text  = (const float*)d_in[0];
    const float* audio = (const float*)d_in[1];
    const float* video = (const float*)d_in[2];
    const float* Wa    = (const float*)d_in[3];
    const float* ba    = (const float*)d_in[4];
    const float* lna_g = (const float*)d_in[5];
    const float* lna_b = (const float*)d_in[6];
    const float* Wvid  = (const float*)d_in[7];
    const float* bvid  = (const float*)d_in[8];
    const float* lnv_g = (const float*)d_in[9];
    const float* lnv_b = (const float*)d_in[10];
    const float* ln1_g = (const float*)d_in[11];
    const float* ln1_b = (const float*)d_in[12];
    const float* Wq    = (const float*)d_in[13];
    const float* Wkv   = (const float*)d_in[14];
    const float* qn_g  = (const float*)d_in[15];
    const float* kn_g  = (const float*)d_in[16];
    const float* Wo    = (const float*)d_in[17];
    const float* W1    = (const float*)d_in[18];
    const float* b1    = (const float*)d_in[19];
    const float* ln2_g = (const float*)d_in[20];
    const float* ln2_b = (const float*)d_in[21];
    const float* W2    = (const float*)d_in[22];
    const float* b2    = (const float*)d_in[23];
    float* out = (float*)d_out;

#define SYM(p, s) void* p; cudaGetSymbolAddress(&p, s)
    SYM(atvt, g_atvt); SYM(probs, g_probs);
    SYM(x, g_x);     SYM(qkvp, g_qkv);
    SYM(ob, g_o);    SYM(x2, g_x2);   SYM(ff, g_ff);
    SYM(bias2, g_bias2);
    SYM(inH, g_inH); SYM(inL, g_inL);
    SYM(qh, g_qh);   SYM(ql, g_ql);
    SYM(kh, g_kh);   SYM(vTh, g_vTh);
    SYM(ph, g_ph);   SYM(pl, g_pl);
    SYM(hh, g_hh);   SYM(hl, g_hl);
    SYM(obH, g_obH); SYM(obL, g_obL);
    SYM(x2H, g_x2H); SYM(x2L, g_x2L);
    SYM(ffH, g_ffH); SYM(ffL, g_ffL);
    SYM(WavT, g_WavT); SYM(WqkvT, g_WqkvT);
    SYM(WoT, g_WoT); SYM(W1T, g_W1T); SYM(W2T, g_W2T);
#undef SYM

    cudaFuncSetAttribute(gemm_wmma<EPI_NONE>,      cudaFuncAttributeMaxDynamicSharedMemorySize, GEMM_SMEM_DYN);
    cudaFuncSetAttribute(gemm_wmma<EPI_BIAS>,      cudaFuncAttributeMaxDynamicSharedMemorySize, GEMM_SMEM_DYN);
    cudaFuncSetAttribute(gemm_wmma<EPI_BIAS_GELU>, cudaFuncAttributeMaxDynamicSharedMemorySize, GEMM_SMEM_DYN);
    cudaFuncSetAttribute(gemm_wmma<EPI_BIAS_RES>,  cudaFuncAttributeMaxDynamicSharedMemorySize, GEMM_SMEM_DYN);
    cudaFuncSetAttribute(gemm_wmma<EPI_SPLIT>,     cudaFuncAttributeMaxDynamicSharedMemorySize, GEMM_SMEM_DYN);
    cudaFuncSetAttribute(attn_kernel, cudaFuncAttributeMaxDynamicSharedMemorySize, ATTN_SMEM_BYTES);

    dim3 t32(32, 8);
    long long DD = (long long)DIM_ * DIM_;
    long long BD = (long long)BN_ * DIM_;

    packbias_kernel<<<4, 256>>>(ba, bvid);
    tconv_kernel<<<dim3(32, 32, 1), t32>>>(Wa,  (f16*)WavT,      DIM_, DIM_, 0, 0, 0);
    tconv_kernel<<<dim3(32, 32, 1), t32>>>(Wvid,(f16*)WavT + DD, DIM_, DIM_, 0, 0, 0);
    conv_kernel<<<BN_*DIM_/1024, 256>>>(audio, (f16*)inH, (f16*)inL, BN_*DIM_);
    conv_kernel<<<BN_*DIM_/1024, 256>>>(video, (f16*)inH + BD, (f16*)inL + BD, BN_*DIM_);

    // 1) merged adapters (batched over audio/video)
    gemm_wmma<EPI_BIAS><<<dim3(DIM_/128, BN_/128, 2), 256, GEMM_SMEM_DYN>>>(
        (f16*)inH, (f16*)inL, (f16*)WavT, (float*)atvt, (float*)bias2, nullptr,
        nullptr, nullptr, DIM_, DIM_, DIM_, DIM_, 1.f, 1, DIM_,
        BD, 0, DD, 0, BD, 0);

    tconv_kernel<<<dim3(32, 16, 1), t32>>>(Wq,  (f16*)WqkvT, INNER_, DIM_, 0, 0, 0);
    tconv_kernel<<<dim3(32, 32, 1), t32>>>(Wkv, (f16*)WqkvT + (long long)INNER_*DIM_, 2*INNER_, DIM_, 0, 0, 0);
    tconv_kernel<<<dim3(16, 32, 1), t32>>>(Wo,  (f16*)WoT, DIM_, INNER_, 0, 0, 0);
    tconv_kernel<<<dim3(32, 128,1), t32>>>(W1,  (f16*)W1T, FF_,  DIM_,   0, 0, 0);
    tconv_kernel<<<dim3(128,32, 1), t32>>>(W2,  (f16*)W2T, DIM_, FF_,    0, 0, 0);

    float* at = (float*)atvt;
    float* vt = (float*)atvt + BD;
    ln_kernel<<<BN_, 256>>>(at, at, lna_g, lna_b, DIM_);
    ln_kernel<<<BN_, 256>>>(vt, vt, lnv_g, lnv_b, DIM_);

    // 2) rotary + padded layouts
    prep_kernel<<<B_ * NP_, 256>>>(text, at, (f16*)qh, (f16*)ql, (f16*)kh);
    tconv_kernel<<<dim3(NP_/32, DIM_/32, B_), t32>>>(vt,
        (f16*)vTh, DIM_, NP_, WS_,
        (long long)N_*DIM_, (long long)DIM_*NP_);

    // 3) local attention (8 windows batched)
    gemm_wmma<EPI_NONE><<<dim3((2*WS_)/128, WS_/128, B_*NWIN_), 256, GEMM_SMEM_DYN>>>(
        (f16*)qh, (f16*)ql, (f16*)kh, (float*)probs, nullptr, nullptr,
        nullptr, nullptr, DIM_, DIM_, DIM_, 2*WS_, 0.03125f, NWIN_, 0,
        (long long)N_*DIM_,  (long long)WS_*DIM_,
        (long long)NP_*DIM_, (long long)WS_*DIM_,
        (long long)NWIN_*WS_*2*WS_, (long long)WS_*2*WS_);
    softmax_local_kernel<<<B_*NWIN_*WS_, 256>>>((float*)probs, (f16*)ph, (f16*)pl);
    gemm_wmma<EPI_NONE><<<dim3(DIM_/128, WS_/128, B_*NWIN_), 256, GEMM_SMEM_DYN>>>(
        (f16*)ph, (f16*)pl, (f16*)vTh, (float*)x, nullptr, nullptr,
        nullptr, nullptr, 2*WS_, 2*WS_, NP_, DIM_, 1.f, NWIN_, 0,
        (long long)NWIN_*WS_*2*WS_, (long long)WS_*2*WS_,
        (long long)DIM_*NP_, (long long)WS_,
        (long long)N_*DIM_, (long long)WS_*DIM_);

    // 4) ln1 -> merged qkv projection -> rmsnorm
    ln_bf_kernel<<<BN_, 256>>>((float*)x, (f16*)hh, (f16*)hl, ln1_g, ln1_b, DIM_);
    gemm_wmma<EPI_NONE><<<dim3(QKVLD_/128, BN_/128, 1), 256, GEMM_SMEM_DYN>>>(
        (f16*)hh, (f16*)hl, (f16*)WqkvT, (float*)qkvp, nullptr, nullptr,
        nullptr, nullptr, DIM_, DIM_, DIM_, QKVLD_, 1.f, 1, 0, 0,0,0,0,0,0);
    rms_kernel<<<(BN_*HEADS_)/8, 256>>>((float*)qkvp, qn_g, HEADS_, QKVLD_, BN_);
    rms_kernel<<<(BN_*HEADS_)/8, 256>>>((float*)qkvp + INNER_, kn_g, HEADS_, QKVLD_, BN_);

    // 5) causal attention
    attn_kernel<<<dim3(N_/64, B_*HEADS_), 256, ATTN_SMEM_BYTES>>>(
        (float*)qkvp, (float*)ob, (f16*)obH, (f16*)obL);

    // 6) x2 = 2*(o @ Wo), emits fp32 + fp16 split
    gemm_wmma<EPI_SPLIT><<<dim3(DIM_/128, BN_/128, 1), 256, GEMM_SMEM_DYN>>>(
        (f16*)obH, (f16*)obL, (f16*)WoT, (float*)x2, nullptr, nullptr,
        (f16*)x2H, (f16*)x2L, INNER_, INNER_, INNER_, DIM_, 2.f, 1, 0, 0,0,0,0,0,0);

    // 7) FFN
    gemm_wmma<EPI_BIAS_GELU><<<dim3(FF_/128, BN_/128, 1), 256, GEMM_SMEM_DYN>>>(
        (f16*)x2H, (f16*)x2L, (f16*)W1T, (float*)ff, b1, nullptr,
        nullptr, nullptr, DIM_, DIM_, DIM_, FF_, 1.f, 1, 0, 0,0,0,0,0,0);
    ln_bf_kernel<<<BN_, 256>>>((float*)ff, (f16*)ffH, (f16*)ffL, ln2_g, ln2_b, FF_);
    gemm_wmma<EPI_BIAS_RES><<<dim3(DIM_/128, BN_/128, 1), 256, GEMM_SMEM_DYN>>>(
        (f16*)ffH, (f16*)ffL, (f16*)W2T, out, b2, (float*)x2,
        nullptr, nullptr, FF_, FF_, FF_, DIM_, 1.f, 1, 0, 0,0,0,0,0,0);
}

// round 15
// speedup vs baseline: 2.0658x; 1.0427x over previous
#include <cuda_runtime.h>
#include <cuda_fp16.h>
#include <mma.h>
#include <math.h>
#include <stdint.h>

using namespace nvcuda;
typedef __half f16;

#define B_      2
#define N_      2048
#define DIM_    1024
#define INNER_  512
#define HEADS_  8
#define DHEAD_  64
#define WS_     512
#define FF_     4096
#define BN_     (B_*N_)
#define NP_     (N_+WS_)
#define NWIN_   (N_/WS_)
#define QKVLD_  1536

// ---- fp32 scratch ----
__device__ float g_atvt[2*BN_*DIM_];
__device__ float g_probs[B_*NWIN_*WS_*2*WS_];
__device__ float g_x  [BN_*DIM_];
__device__ float g_qkv[BN_*QKVLD_];
__device__ float g_o  [BN_*INNER_];
__device__ float g_x2 [BN_*DIM_];
__device__ float g_ff [BN_*FF_];
__device__ float g_bias2[2*DIM_];

// ---- fp16 scratch ----
__device__ f16 g_inH [2*BN_*DIM_], g_inL [2*BN_*DIM_];
__device__ f16 g_qh [BN_*DIM_],   g_ql [BN_*DIM_];
__device__ f16 g_kh [B_*NP_*DIM_];
__device__ f16 g_vTh[B_*DIM_*NP_];
__device__ f16 g_ph [B_*NWIN_*WS_*2*WS_], g_pl[B_*NWIN_*WS_*2*WS_];
__device__ f16 g_hh [BN_*DIM_],   g_hl [BN_*DIM_];
__device__ f16 g_obH[BN_*INNER_], g_obL[BN_*INNER_];
__device__ f16 g_x2H[BN_*DIM_],   g_x2L[BN_*DIM_];
__device__ f16 g_ffH[BN_*FF_],    g_ffL[BN_*FF_];
__device__ f16 g_WavT[2*DIM_*DIM_];
__device__ f16 g_WqkvT[QKVLD_*DIM_];
__device__ f16 g_WoT [DIM_*INNER_];
__device__ f16 g_W1T [FF_*DIM_];
__device__ f16 g_W2T [DIM_*FF_];

// ---- helpers ----
__device__ __forceinline__ uint32_t s2u(const void* p){
    uint32_t a;
    asm("{ .reg .u64 t; cvta.to.shared.u64 t, %1; cvt.u32.u64 %0, t; }"
        : "=r"(a) : "l"(p));
    return a;
}
__device__ __forceinline__ void cpa16(uint32_t d, const void* s){
    asm volatile("cp.async.cg.shared.global [%0], [%1], 16;" :: "r"(d), "l"(s));
}
__device__ __forceinline__ void cpa_commit(){
    asm volatile("cp.async.commit_group;" ::: "memory");
}
__device__ __forceinline__ void cpa_wait0(){
    asm volatile("cp.async.wait_group 0;" ::: "memory");
}
__device__ __forceinline__ void cpa_wait1(){
    asm volatile("cp.async.wait_group 1;" ::: "memory");
}
__device__ __forceinline__ void split2(float v, f16& h, f16& l){
    h = __float2half_rn(v);
    l = __float2half_rn(v - __half2float(h));
}
__device__ __forceinline__ float gelu_tanh(float v){
    float c = v + 0.044715f * v * v * v;
    return 0.5f * v * (1.0f + tanhf(0.7978845608028654f * c));
}

// ---- fp16 split-A GEMM: C = alpha*(Ah+Al)*Bh^T (+epi). 128x128, BK=64 ----
// LDSB=72 -> 144B rows: ldmatrix start banks (r*36)%32 all-distinct, 16B-aligned
// cp.async dsts. 2 stages x 55296B = 110592B smem; 2 CTAs/SM = 216KB <= 227KB.
#define LDSB 72
#define MATB (128*LDSB*2)          // 18432 B per matrix per stage
#define AH_OFF 0
#define AL_OFF MATB
#define BH_OFF (2*MATB)
#define STGB  (3*MATB)             // 55296 per stage
#define GEMM_SMEM_DYN (2*STGB)     // 110592 (>= 64KB epilogue)

#define EPI_NONE       0
#define EPI_BIAS       1
#define EPI_BIAS_GELU  2
#define EPI_BIAS_RES   3
#define EPI_SPLIT      4

template<int EPI>
__global__ void __launch_bounds__(256, 2)
gemm_wmma(const f16* __restrict__ Ah, const f16* __restrict__ Al,
          const f16* __restrict__ Bh,
          float* __restrict__ C, const float* __restrict__ bias,
          const float* __restrict__ res,
          f16* __restrict__ Ch, f16* __restrict__ Cl,
          int K, int lda, int ldb, int ldc, float alpha, int wdiv,
          int biasStride,
          long long sAb, long long sAw, long long sBb, long long sBw,
          long long sCb, long long sCw)
{
    extern __shared__ char dsm[];
    uint32_t sb0 = s2u(dsm);

    int tid = threadIdx.x;
    int wid = tid >> 5;
    int wm = wid >> 2;
    int wn = wid & 3;
    int z = blockIdx.z;
    int zb = z / wdiv, zw = z - zb * wdiv;
    long long aoff = zb * sAb + zw * sAw;
    long long boff = zb * sBb + zw * sBw;
    long long coff = zb * sCb + zw * sCw;
    Ah += aoff; Al += aoff;
    Bh += boff;
    C  += coff;
    if (EPI == EPI_BIAS || EPI == EPI_BIAS_GELU || EPI == EPI_BIAS_RES)
        bias += (long long)zb * biasStride;
    const float* Rp = (EPI == EPI_BIAS_RES) ? (res + coff) : nullptr;

    int m0 = blockIdx.y * 128;
    int n0 = blockIdx.x * 128;

    wmma::fragment<wmma::accumulator, 16, 16, 16, float> acc[4][2];
#pragma unroll
    for (int i = 0; i < 4; i++)
#pragma unroll
        for (int j = 0; j < 2; j++) wmma::fill_fragment(acc[i][j], 0.f);

    // stage loader: 3 matrices x 128 rows x 8 chunks (16B) = 12 cpa16/thread
    auto loadStage = [&](int stg, int kk){
        uint32_t sb = sb0 + stg * STGB;
#pragma unroll
        for (int h = 0; h < 4; h++){
            int i = tid + h * 256;              // 0..1023
            int row = i >> 3, ch = i & 7;
            uint32_t d = row * (LDSB*2) + ch * 16;
            long long ga = (long long)(m0 + row) * lda + kk + ch * 8;
            long long gb = (long long)(n0 + row) * ldb + kk + ch * 8;
            cpa16(sb + AH_OFF + d, Ah + ga);
            cpa16(sb + AL_OFF + d, Al + ga);
            cpa16(sb + BH_OFF + d, Bh + gb);
        }
    };

    int KT = K >> 6;
    loadStage(0, 0);
    cpa_commit();

    for (int kt = 0; kt < KT; kt++){
        if (kt + 1 < KT){
            loadStage((kt + 1) & 1, (kt + 1) * 64);
            cpa_commit();
            cpa_wait1();
        } else {
            cpa_wait0();
        }
        __syncthreads();

        const f16* st = (const f16*)(dsm + (kt & 1) * STGB);
        const f16* pAh = st + (AH_OFF/2) + (wm*64)*LDSB;
        const f16* pAl = st + (AL_OFF/2) + (wm*64)*LDSB;
        const f16* pBh = st + (BH_OFF/2) + (wn*32)*LDSB;
#pragma unroll
        for (int ks = 0; ks < 4; ks++){
            wmma::fragment<wmma::matrix_b, 16,16,16, f16, wmma::col_major> fBh[2];
#pragma unroll
            for (int j = 0; j < 2; j++)
                wmma::load_matrix_sync(fBh[j], pBh + j*16*LDSB + ks*16, LDSB);
#pragma unroll
            for (int i = 0; i < 4; i++){
                wmma::fragment<wmma::matrix_a, 16,16,16, f16, wmma::row_major> fAh, fAl;
                wmma::load_matrix_sync(fAh, pAh + i*16*LDSB + ks*16, LDSB);
                wmma::load_matrix_sync(fAl, pAl + i*16*LDSB + ks*16, LDSB);
#pragma unroll
                for (int j = 0; j < 2; j++){
                    wmma::mma_sync(acc[i][j], fAh, fBh[j], acc[i][j]);
                    wmma::mma_sync(acc[i][j], fAl, fBh[j], acc[i][j]);
                }
            }
        }
        __syncthreads();
    }

    // ---- block-wide epilogue via smem float staging ----
    float* sF = (float*)dsm;
#pragma unroll
    for (int i = 0; i < 4; i++)
#pragma unroll
        for (int j = 0; j < 2; j++)
            wmma::store_matrix_sync(
                sF + (wm*64 + i*16) * 128 + wn*32 + j*16,
                acc[i][j], 128, wmma::mem_row_major);
    __syncthreads();

#pragma unroll 1
    for (int t = 0; t < 16; t++){
        int i = tid + t * 256;
        int row = i >> 5, c4 = (i & 31) * 4;
        float4 v = *(float4*)&sF[row * 128 + c4];
        v.x *= alpha; v.y *= alpha; v.z *= alpha; v.w *= alpha;
        int gc = n0 + c4;
        if (EPI == EPI_BIAS || EPI == EPI_BIAS_GELU || EPI == EPI_BIAS_RES){
            float4 bb = *(const float4*)&bias[gc];
            v.x += bb.x; v.y += bb.y; v.z += bb.z; v.w += bb.w;
        }
        if (EPI == EPI_BIAS_GELU){
            v.x = gelu_tanh(v.x); v.y = gelu_tanh(v.y);
            v.z = gelu_tanh(v.z); v.w = gelu_tanh(v.w);
        }
        long long crow = (long long)(m0 + row) * ldc + gc;
        if (EPI == EPI_BIAS_RES){
            float4 rr = *(const float4*)&Rp[crow];
            v.x += rr.x; v.y += rr.y; v.z += rr.z; v.w += rr.w;
        }
        *(float4*)&C[crow] = v;
        if (EPI == EPI_SPLIT){
            long long so = coff + crow;
            f16 hh, ll;
            split2(v.x, hh, ll); Ch[so+0] = hh; Cl[so+0] = ll;
            split2(v.y, hh, ll); Ch[so+1] = hh; Cl[so+1] = ll;
            split2(v.z, hh, ll); Ch[so+2] = hh; Cl[so+2] = ll;
            split2(v.w, hh, ll); Ch[so+3] = hh; Cl[so+3] = ll;
        }
    }
}

// ---- bias pack ----
__global__ void packbias_kernel(const float* __restrict__ a, const float* __restrict__ b)
{
    int i = blockIdx.x * 256 + threadIdx.x;
    if (i < DIM_){ g_bias2[i] = a[i]; g_bias2[DIM_ + i] = b[i]; }
}

// ---- merged dual LayerNorm (rows 0..BN-1: params0, BN..2BN-1: params1) ----
__global__ void ln2_kernel(float* __restrict__ x,
                           const float* __restrict__ g0, const float* __restrict__ b0,
                           const float* __restrict__ g1, const float* __restrict__ b1v,
                           int L)
{
    __shared__ float buf[4096];
    __shared__ float r1[8], r2[8], st[2];
    long long row = blockIdx.x;
    const float* g = (row < BN_) ? g0 : g1;
    const float* bv = (row < BN_) ? b0 : b1v;
    float* xr = x + row * L;
    int tid = threadIdx.x;
    float s = 0.f, s2 = 0.f;
    for (int c = tid; c < L; c += 256){ float v = xr[c]; buf[c] = v; s += v; s2 += v*v; }
#pragma unroll
    for (int o = 16; o > 0; o >>= 1){
        s  += __shfl_xor_sync(0xffffffffu, s,  o);
        s2 += __shfl_xor_sync(0xffffffffu, s2, o);
    }
    int lane = tid & 31, w = tid >> 5;
    if (lane == 0){ r1[w] = s; r2[w] = s2; }
    __syncthreads();
    if (tid == 0){
        float ts = 0.f, ts2 = 0.f;
        for (int k = 0; k < 8; k++){ ts += r1[k]; ts2 += r2[k]; }
        float mean = ts / (float)L;
        st[0] = mean; st[1] = rsqrtf(ts2 / (float)L - mean*mean + 1e-5f);
    }
    __syncthreads();
    float mean = st[0], rstd = st[1];
    for (int c = tid; c < L; c += 256)
        xr[c] = (buf[c] - mean) * rstd * g[c] + bv[c];
}

// ---- LayerNorm -> fp16 hi/lo ----
__global__ void ln_bf_kernel(const float* __restrict__ x, f16* __restrict__ yh,
                             f16* __restrict__ yl,
                             const float* __restrict__ g, const float* __restrict__ bv,
                             int L)
{
    __shared__ float buf[4096];
    __shared__ float r1[8], r2[8], st[2];
    long long row = blockIdx.x;
    const float* xr = x + row * L;
    int tid = threadIdx.x;
    float s = 0.f, s2 = 0.f;
    for (int c = tid; c < L; c += 256){ float v = xr[c]; buf[c] = v; s += v; s2 += v*v; }
#pragma unroll
    for (int o = 16; o > 0; o >>= 1){
        s  += __shfl_xor_sync(0xffffffffu, s,  o);
        s2 += __shfl_xor_sync(0xffffffffu, s2, o);
    }
    int lane = tid & 31, w = tid >> 5;
    if (lane == 0){ r1[w] = s; r2[w] = s2; }
    __syncthreads();
    if (tid == 0){
        float ts = 0.f, ts2 = 0.f;
        for (int k = 0; k < 8; k++){ ts += r1[k]; ts2 += r2[k]; }
        float mean = ts / (float)L;
        st[0] = mean; st[1] = rsqrtf(ts2 / (float)L - mean*mean + 1e-5f);
    }
    __syncthreads();
    float mean = st[0], rstd = st[1];
    for (int c = tid; c < L; c += 256){
        float v = (buf[c] - mean) * rstd * g[c] + bv[c];
        f16 h, l; split2(v, h, l);
        yh[row * L + c] = h; yl[row * L + c] = l;
    }
}

// ---- RMSNorm over 64-dim head vectors ----
__global__ void rms_kernel(float* __restrict__ x, const float* __restrict__ g,
                           int vecs_per_row, int row_stride, int nrows)
{
    int vid = blockIdx.x * 8 + (threadIdx.x >> 5);
    int lane = threadIdx.x & 31;
    int r = vid / vecs_per_row;
    int h = vid - r * vecs_per_row;
    if (r >= nrows) return;
    float* p = x + (long long)r * row_stride + h * DHEAD_;
    float v0 = p[lane], v1 = p[lane + 32];
    float ss = v0*v0 + v1*v1;
#pragma unroll
    for (int o = 16; o > 0; o >>= 1) ss += __shfl_xor_sync(0xffffffffu, ss, o);
    float rs = rsqrtf(ss * (1.0f/64.0f) + 1e-6f);
    p[lane]      = v0 * rs * g[lane];
    p[lane + 32] = v1 * rs * g[lane + 32];
}

// ---- rotary prep: q split fp16, k single fp16 ----
__global__ void prep_kernel(const float* __restrict__ text,
                            const float* __restrict__ at,
                            f16* __restrict__ qh, f16* __restrict__ ql,
                            f16* __restrict__ kh)
{
    int row = blockIdx.x;
    int b = row / NP_;
    int pr = row - b * NP_;
    long long kout = (long long)row * DIM_;
    if (pr < WS_){
        f16 zz = __float2half(0.f);
        for (int c = threadIdx.x; c < DIM_; c += 256) kh[kout+c] = zz;
        return;
    }
    int t = pr - WS_;
    long long src = ((long long)b * N_ + t) * DIM_;
    for (int c = threadIdx.x; c < DIM_; c += 256){
        int j = c & 511;
        float invf = exp2f((float)j * (-13.28771238f * (1.0f/512.0f)));
        float ang = (float)t * invf;
        float cs = cosf(ang), sn = sinf(ang);
        float kx = at[src + c];
        float ko = (c < 512) ? -at[src + c + 512] : at[src + c - 512];
        kh[kout + c] = __float2half_rn(kx * cs + ko * sn);
        float qx = text[src + c];
        float qo = (c < 512) ? -text[src + c + 512] : text[src + c - 512];
        f16 h, l;
        split2(qx * cs + qo * sn, h, l);
        qh[src + c] = h; ql[src + c] = l;
    }
}

// ---- transpose to single fp16 ----
__global__ void tconv_kernel(const float* __restrict__ in, f16* __restrict__ oh,
                             int inLd, int outLd, int pad,
                             long long inB, long long outB)
{
    __shared__ float t[32][33];
    in += blockIdx.z * inB;
    oh += blockIdx.z * outB;
    int p0 = blockIdx.x * 32, c0 = blockIdx.y * 32;
    int tx = threadIdx.x, ty = threadIdx.y;
    for (int i = ty; i < 32; i += 8){
        int r = p0 + i - pad;
        t[i][tx] = (r >= 0) ? in[(long long)r * inLd + c0 + tx] : 0.f;
    }
    __syncthreads();
    for (int i = ty; i < 32; i += 8){
        long long o = (long long)(c0 + i) * outLd + p0 + tx;
        oh[o] = __float2half_rn(t[tx][i]);
    }
}

// ---- elementwise split fp32 -> fp16 hi/lo ----
__global__ void conv_kernel(const float* __restrict__ x, f16* __restrict__ h,
                            f16* __restrict__ l, int n)
{
    int i = (blockIdx.x * 256 + threadIdx.x) * 4;
    if (i < n){
        float4 v = *(const float4*)&x[i];
        f16 hh, ll;
        split2(v.x, hh, ll); h[i+0] = hh; l[i+0] = ll;
        split2(v.y, hh, ll); h[i+1] = hh; l[i+1] = ll;
        split2(v.z, hh, ll); h[i+2] = hh; l[i+2] = ll;
        split2(v.w, hh, ll); h[i+3] = hh; l[i+3] = ll;
    }
}

// ---- local-attention masked softmax -> fp16 hi/lo ----
__global__ void softmax_local_kernel(const float* __restrict__ p,
                                     f16* __restrict__ ph, f16* __restrict__ pl)
{
    __shared__ float buf[1024];
    __shared__ float red[8], bc[2];
    int r = blockIdx.x;
    int i = r & (WS_ - 1);
    int z = r >> 9;
    int w = z & (NWIN_ - 1);
    int qp = w * WS_ + i;
    const float* row = p + (long long)r * (2 * WS_);
    int tid = threadIdx.x, lane = tid & 31, wp = tid >> 5;

    float mx = -1e30f;
    for (int j = tid; j < 2*WS_; j += 256){
        int kp = (w - 1) * WS_ + j;
        float v = (kp >= 0 && kp <= qp) ? row[j] : -1e9f;
        buf[j] = v;
        mx = fmaxf(mx, v);
    }
#pragma unroll
    for (int o = 16; o > 0; o >>= 1) mx = fmaxf(mx, __shfl_xor_sync(0xffffffffu, mx, o));
    if (lane == 0) red[wp] = mx;
    __syncthreads();
    if (tid == 0){
        float m = red[0];
        for (int k = 1; k < 8; k++) m = fmaxf(m, red[k]);
        bc[0] = m;
    }
    __syncthreads();
    mx = bc[0];
    float sum = 0.f;
    for (int j = tid; j < 2*WS_; j += 256){
        float e = __expf(buf[j] - mx);
        buf[j] = e; sum += e;
    }
#pragma unroll
    for (int o = 16; o > 0; o >>= 1) sum += __shfl_xor_sync(0xffffffffu, sum, o);
    if (lane == 0) red[wp] = sum;
    __syncthreads();
    if (tid == 0){
        float t = 0.f;
        for (int k = 0; k < 8; k++) t += red[k];
        bc[1] = 1.0f / t;
    }
    __syncthreads();
    float inv = bc[1];
    for (int j = tid; j < 2*WS_; j += 256){
        f16 h, l; split2(buf[j] * inv, h, l);
        long long o = (long long)r * (2*WS_) + j;
        ph[o] = h; pl[o] = l;
    }
}

// ---- causal flash attention fp32; packed qkv (ld 1536); emits fp16 hi/lo ----
#define QP_ 68
#define ATTN_SMEM_BYTES (4 * 64 * QP_ * 4 + 3 * 64 * 4)

__global__ void __launch_bounds__(256)
attn_kernel(const float* __restrict__ qkv,
            float* __restrict__ o, f16* __restrict__ oh, f16* __restrict__ ol)
{
    extern __shared__ float sm[];
    float* QsT = sm;
    float* KsT = QsT + 64 * QP_;
    float* Vs  = KsT + 64 * QP_;
    float* SsT = Vs  + 64 * QP_;
    float* Ms = SsT + 64 * QP_;
    float* Ls = Ms + 64;
    float* Cs = Ls + 64;

    int tid = threadIdx.x;
    int bh = blockIdx.y;
    int b = bh >> 3, h = bh & 7;
    int q0 = blockIdx.x * 64;
    int ty = tid >> 4, tx = tid & 15;

    for (int idx = tid; idx < 4096; idx += 256){
        int r = idx >> 6, c = idx & 63;
        QsT[c * QP_ + r] =
            qkv[((long long)(b * N_ + q0 + r)) * QKVLD_ + h * 64 + c] * 0.125f;
    }
    if (tid < 64){ Ms[tid] = -INFINITY; Ls[tid] = 0.f; }
    float oacc[16];
#pragma unroll
    for (int i = 0; i < 16; i++) oacc[i] = 0.f;
    __syncthreads();

    int lastTile = blockIdx.x;
    for (int kt = 0; kt <= lastTile; kt++){
        for (int idx = tid; idx < 4096; idx += 256){
            int r = idx >> 6, c = idx & 63;
            long long base =
                ((long long)(b * N_ + kt * 64 + r)) * QKVLD_ + INNER_ + h * 64 + c;
            KsT[c * QP_ + r] = qkv[base];
            Vs[r * QP_ + c]  = qkv[base + INNER_];
        }
        __syncthreads();

        float sacc[16];
#pragma unroll
        for (int i = 0; i < 16; i++) sacc[i] = 0.f;
#pragma unroll 8
        for (int kk = 0; kk < 64; kk++){
            float4 aq = *(const float4*)&QsT[kk * QP_ + ty * 4];
            float4 bk = *(const float4*)&KsT[kk * QP_ + tx * 4];
            float a4[4] = {aq.x, aq.y, aq.z, aq.w};
            float b4[4] = {bk.x, bk.y, bk.z, bk.w};
#pragma unroll
            for (int i = 0; i < 4; i++)
#pragma unroll
                for (int j = 0; j < 4; j++)
                    sacc[i*4+j] += a4[i] * b4[j];
        }
        bool diag = (kt == lastTile);
#pragma unroll
        for (int i = 0; i < 4; i++)
#pragma unroll
            for (int j = 0; j < 4; j++){
                int qr = ty * 4 + i, kc = tx * 4 + j;
                float s = sacc[i*4+j];
                if (diag && kc > qr) s = -INFINITY;
                SsT[kc * QP_ + qr] = s;
            }
        __syncthreads();

        if (tid < 64){
            int r = tid;
            float mt = -INFINITY;
#pragma unroll 8
            for (int c = 0; c < 64; c++) mt = fmaxf(mt, SsT[c * QP_ + r]);
            float mo = Ms[r];
            float mn = fmaxf(mo, mt);
            float corr = __expf(mo - mn);
            float ls = 0.f;
#pragma unroll 8
            for (int c = 0; c < 64; c++){
                float e = __expf(SsT[c * QP_ + r] - mn);
                SsT[c * QP_ + r] = e;
                ls += e;
            }
            Ls[r] = Ls[r] * corr + ls;
            Ms[r] = mn;
            Cs[r] = corr;
        }
        __syncthreads();

        float cf[4];
#pragma unroll
        for (int i = 0; i < 4; i++) cf[i] = Cs[ty * 4 + i];
#pragma unroll
        for (int i = 0; i < 4; i++)
#pragma unroll
            for (int j = 0; j < 4; j++) oacc[i*4+j] *= cf[i];

#pragma unroll 8
        for (int kk = 0; kk < 64; kk++){
            float4 ap = *(const float4*)&SsT[kk * QP_ + ty * 4];
            float4 vv = *(const float4*)&Vs[kk * QP_ + tx * 4];
            float a4[4] = {ap.x, ap.y, ap.z, ap.w};
            float b4[4] = {vv.x, vv.y, vv.z, vv.w};
#pragma unroll
            for (int i = 0; i < 4; i++)
#pragma unroll
                for (int j = 0; j < 4; j++)
                    oacc[i*4+j] += a4[i] * b4[j];
        }
        __syncthreads();
    }

#pragma unroll
    for (int i = 0; i < 4; i++){
        float inv = 1.0f / Ls[ty * 4 + i];
        long long orow =
            ((long long)(b * N_ + q0 + ty * 4 + i)) * INNER_ + h * 64 + tx * 4;
        float4 vo = make_float4(oacc[i*4+0]*inv, oacc[i*4+1]*inv,
                                oacc[i*4+2]*inv, oacc[i*4+3]*inv);
        *(float4*)&o[orow] = vo;
        f16 hh, ll;
        split2(vo.x, hh, ll); oh[orow+0] = hh; ol[orow+0] = ll;
        split2(vo.y, hh, ll); oh[orow+1] = hh; ol[orow+1] = ll;
        split2(vo.z, hh, ll); oh[orow+2] = hh; ol[orow+2] = ll;
        split2(vo.w, hh, ll); oh[orow+3] = hh; ol[orow+3] = ll;
    }
}

// ---- launch ----
extern "C" void kernel_launch(void* const* d_in, const int* in_sizes, int n_in,
                              void* d_out, int out_size)
{
    (void)in_sizes; (void)n_in; (void)out_size;
    const float* text  = (const float*)d_in[0];
    const float* audio = (const float*)d_in[1];
    const float* video = (const float*)d_in[2];
    const float* Wa    = (const float*)d_in[3];
    const float* ba    = (const float*)d_in[4];
    const float* lna_g = (const float*)d_in[5];
    const float* lna_b = (const float*)d_in[6];
    const float* Wvid  = (const float*)d_in[7];
    const float* bvid  = (const float*)d_in[8];
    const float* lnv_g = (const float*)d_in[9];
    const float* lnv_b = (const float*)d_in[10];
    const float* ln1_g = (const float*)d_in[11];
    const float* ln1_b = (const float*)d_in[12];
    const float* Wq    = (const float*)d_in[13];
    const float* Wkv   = (const float*)d_in[14];
    const float* qn_g  = (const float*)d_in[15];
    const float* kn_g  = (const float*)d_in[16];
    const float* Wo    = (const float*)d_in[17];
    const float* W1    = (const float*)d_in[18];
    const float* b1    = (const float*)d_in[19];
    const float* ln2_g = (const float*)d_in[20];
    const float* ln2_b = (const float*)d_in[21];
    const float* W2    = (const float*)d_in[22];
    const float* b2    = (const float*)d_in[23];
    float* out = (float*)d_out;

#define SYM(p, s) void* p; cudaGetSymbolAddress(&p, s)
    SYM(atvt, g_atvt); SYM(probs, g_probs);
    SYM(x, g_x);     SYM(qkvp, g_qkv);
    SYM(ob, g_o);    SYM(x2, g_x2);   SYM(ff, g_ff);
    SYM(bias2, g_bias2);
    SYM(inH, g_inH); SYM(inL, g_inL);
    SYM(qh, g_qh);   SYM(ql, g_ql);
    SYM(kh, g_kh);   SYM(vTh, g_vTh);
    SYM(ph, g_ph);   SYM(pl, g_pl);
    SYM(hh, g_hh);   SYM(hl, g_hl);
    SYM(obH, g_obH); SYM(obL, g_obL);
    SYM(x2H, g_x2H); SYM(x2L, g_x2L);
    SYM(ffH, g_ffH); SYM(ffL, g_ffL);
    SYM(WavT, g_WavT); SYM(WqkvT, g_WqkvT);
    SYM(WoT, g_WoT); SYM(W1T, g_W1T); SYM(W2T, g_W2T);
#undef SYM

    cudaFuncSetAttribute(gemm_wmma<EPI_NONE>,      cudaFuncAttributeMaxDynamicSharedMemorySize, GEMM_SMEM_DYN);
    cudaFuncSetAttribute(gemm_wmma<EPI_BIAS>,      cudaFuncAttributeMaxDynamicSharedMemorySize, GEMM_SMEM_DYN);
    cudaFuncSetAttribute(gemm_wmma<EPI_BIAS_GELU>, cudaFuncAttributeMaxDynamicSharedMemorySize, GEMM_SMEM_DYN);
    cudaFuncSetAttribute(gemm_wmma<EPI_BIAS_RES>,  cudaFuncAttributeMaxDynamicSharedMemorySize, GEMM_SMEM_DYN);
    cudaFuncSetAttribute(gemm_wmma<EPI_SPLIT>,     cudaFuncAttributeMaxDynamicSharedMemorySize, GEMM_SMEM_DYN);
    cudaFuncSetAttribute(attn_kernel, cudaFuncAttributeMaxDynamicSharedMemorySize, ATTN_SMEM_BYTES);

    dim3 t32(32, 8);
    long long DD = (long long)DIM_ * DIM_;
    long long BD = (long long)BN_ * DIM_;

    packbias_kernel<<<4, 256>>>(ba, bvid);
    tconv_kernel<<<dim3(32, 32, 1), t32>>>(Wa,  (f16*)WavT,      DIM_, DIM_, 0, 0, 0);
    tconv_kernel<<<dim3(32, 32, 1), t32>>>(Wvid,(f16*)WavT + DD, DIM_, DIM_, 0, 0, 0);
    conv_kernel<<<BN_*DIM_/1024, 256>>>(audio, (f16*)inH, (f16*)inL, BN_*DIM_);
    conv_kernel<<<BN_*DIM_/1024, 256>>>(video, (f16*)inH + BD, (f16*)inL + BD, BN_*DIM_);

    // 1) merged adapters (batched over audio/video)
    gemm_wmma<EPI_BIAS><<<dim3(DIM_/128, BN_/128, 2), 256, GEMM_SMEM_DYN>>>(
        (f16*)inH, (f16*)inL, (f16*)WavT, (float*)atvt, (float*)bias2, nullptr,
        nullptr, nullptr, DIM_, DIM_, DIM_, DIM_, 1.f, 1, DIM_,
        BD, 0, DD, 0, BD, 0);

    tconv_kernel<<<dim3(32, 16, 1), t32>>>(Wq,  (f16*)WqkvT, INNER_, DIM_, 0, 0, 0);
    tconv_kernel<<<dim3(32, 32, 1), t32>>>(Wkv, (f16*)WqkvT + (long long)INNER_*DIM_, 2*INNER_, DIM_, 0, 0, 0);
    tconv_kernel<<<dim3(16, 32, 1), t32>>>(Wo,  (f16*)WoT, DIM_, INNER_, 0, 0, 0);
    tconv_kernel<<<dim3(32, 128,1), t32>>>(W1,  (f16*)W1T, FF_,  DIM_,   0, 0, 0);
    tconv_kernel<<<dim3(128,32, 1), t32>>>(W2,  (f16*)W2T, DIM_, FF_,    0, 0, 0);

    float* at = (float*)atvt;
    float* vt = (float*)atvt + BD;
    // merged adapter LayerNorms (in place over both halves)
    ln2_kernel<<<2*BN_, 256>>>((float*)atvt, lna_g, lna_b, lnv_g, lnv_b, DIM_);

    // 2) rotary + padded layouts
    prep_kernel<<<B_ * NP_, 256>>>(text, at, (f16*)qh, (f16*)ql, (f16*)kh);
    tconv_kernel<<<dim3(NP_/32, DIM_/32, B_), t32>>>(vt,
        (f16*)vTh, DIM_, NP_, WS_,
        (long long)N_*DIM_, (long long)DIM_*NP_);

    // 3) local attention (8 windows batched)
    gemm_wmma<EPI_NONE><<<dim3((2*WS_)/128, WS_/128, B_*NWIN_), 256, GEMM_SMEM_DYN>>>(
        (f16*)qh, (f16*)ql, (f16*)kh, (float*)probs, nullptr, nullptr,
        nullptr, nullptr, DIM_, DIM_, DIM_, 2*WS_, 0.03125f, NWIN_, 0,
        (long long)N_*DIM_,  (long long)WS_*DIM_,
        (long long)NP_*DIM_, (long long)WS_*DIM_,
        (long long)NWIN_*WS_*2*WS_, (long long)WS_*2*WS_);
    softmax_local_kernel<<<B_*NWIN_*WS_, 256>>>((float*)probs, (f16*)ph, (f16*)pl);
    gemm_wmma<EPI_NONE><<<dim3(DIM_/128, WS_/128, B_*NWIN_), 256, GEMM_SMEM_DYN>>>(
        (f16*)ph, (f16*)pl, (f16*)vTh, (float*)x, nullptr, nullptr,
        nullptr, nullptr, 2*WS_, 2*WS_, NP_, DIM_, 1.f, NWIN_, 0,
        (long long)NWIN_*WS_*2*WS_, (long long)WS_*2*WS_,
        (long long)DIM_*NP_, (long long)WS_,
        (long long)N_*DIM_, (long long)WS_*DIM_);

    // 4) ln1 -> merged qkv projection -> rmsnorm
    ln_bf_kernel<<<BN_, 256>>>((float*)x, (f16*)hh, (f16*)hl, ln1_g, ln1_b, DIM_);
    gemm_wmma<EPI_NONE><<<dim3(QKVLD_/128, BN_/128, 1), 256, GEMM_SMEM_DYN>>>(
        (f16*)hh, (f16*)hl, (f16*)WqkvT, (float*)qkvp, nullptr, nullptr,
        nullptr, nullptr, DIM_, DIM_, DIM_, QKVLD_, 1.f, 1, 0, 0,0,0,0,0,0);
    rms_kernel<<<(BN_*HEADS_)/8, 256>>>((float*)qkvp, qn_g, HEADS_, QKVLD_, BN_);
    rms_kernel<<<(BN_*HEADS_)/8, 256>>>((float*)qkvp + INNER_, kn_g, HEADS_, QKVLD_, BN_);

    // 5) causal attention
    attn_kernel<<<dim3(N_/64, B_*HEADS_), 256, ATTN_SMEM_BYTES>>>(
        (float*)qkvp, (float*)ob, (f16*)obH, (f16*)obL);

    // 6) x2 = 2*(o @ Wo), emits fp32 + fp16 split
    gemm_wmma<EPI_SPLIT><<<dim3(DIM_/128, BN_/128, 1), 256, GEMM_SMEM_DYN>>>(
        (f16*)obH, (f16*)obL, (f16*)WoT, (float*)x2, nullptr, nullptr,
        (f16*)x2H, (f16*)x2L, INNER_, INNER_, INNER_, DIM_, 2.f, 1, 0, 0,0,0,0,0,0);

    // 7) FFN
    gemm_wmma<EPI_BIAS_GELU><<<dim3(FF_/128, BN_/128, 1), 256, GEMM_SMEM_DYN>>>(
        (f16*)x2H, (f16*)x2L, (f16*)W1T, (float*)ff, b1, nullptr,
        nullptr, nullptr, DIM_, DIM_, DIM_, FF_, 1.f, 1, 0, 0,0,0,0,0,0);
    ln_bf_kernel<<<BN_, 256>>>((float*)ff, (f16*)ffH, (f16*)ffL, ln2_g, ln2_b, FF_);
    gemm_wmma<EPI_BIAS_RES><<<dim3(DIM_/128, BN_/128, 1), 256, GEMM_SMEM_DYN>>>(
        (f16*)ffH, (f16*)ffL, (f16*)W2T, out, b2, (float*)x2,
        nullptr, nullptr, FF_, FF_, FF_, DIM_, 1.f, 1, 0, 0,0,0,0,0,0);
}

// round 16
// speedup vs baseline: 2.1027x; 1.0179x over previous
#include <cuda_runtime.h>
#include <cuda_fp16.h>
#include <mma.h>
#include <math.h>
#include <stdint.h>

using namespace nvcuda;
typedef __half f16;

#define B_      2
#define N_      2048
#define DIM_    1024
#define INNER_  512
#define HEADS_  8
#define DHEAD_  64
#define WS_     512
#define FF_     4096
#define BN_     (B_*N_)
#define NP_     (N_+WS_)
#define NWIN_   (N_/WS_)
#define QKVLD_  1536

// ---- fp32 scratch ----
__device__ float g_atvt[2*BN_*DIM_];
__device__ float g_probs[B_*NWIN_*WS_*2*WS_];
__device__ float g_x  [BN_*DIM_];
__device__ float g_qkv[BN_*QKVLD_];
__device__ float g_o  [BN_*INNER_];
__device__ float g_x2 [BN_*DIM_];
__device__ float g_ff [BN_*FF_];
__device__ float g_bias2[2*DIM_];

// ---- fp16 scratch ----
__device__ f16 g_inH [2*BN_*DIM_], g_inL [2*BN_*DIM_];
__device__ f16 g_qh [BN_*DIM_],   g_ql [BN_*DIM_];
__device__ f16 g_kh [B_*NP_*DIM_];
__device__ f16 g_vTh[B_*DIM_*NP_];
__device__ f16 g_ph [B_*NWIN_*WS_*2*WS_], g_pl[B_*NWIN_*WS_*2*WS_];
__device__ f16 g_hh [BN_*DIM_],   g_hl [BN_*DIM_];
__device__ f16 g_obH[BN_*INNER_], g_obL[BN_*INNER_];
__device__ f16 g_x2H[BN_*DIM_],   g_x2L[BN_*DIM_];
__device__ f16 g_ffH[BN_*FF_],    g_ffL[BN_*FF_];
__device__ f16 g_WavT[2*DIM_*DIM_];
__device__ f16 g_WqkvT[QKVLD_*DIM_];
__device__ f16 g_WoT [DIM_*INNER_];
__device__ f16 g_W1T [FF_*DIM_];
__device__ f16 g_W2T [DIM_*FF_];

// ---- helpers ----
__device__ __forceinline__ uint32_t s2u(const void* p){
    uint32_t a;
    asm("{ .reg .u64 t; cvta.to.shared.u64 t, %1; cvt.u32.u64 %0, t; }"
        : "=r"(a) : "l"(p));
    return a;
}
__device__ __forceinline__ void cpa16(uint32_t d, const void* s){
    asm volatile("cp.async.cg.shared.global [%0], [%1], 16;" :: "r"(d), "l"(s));
}
__device__ __forceinline__ void cpa_commit(){
    asm volatile("cp.async.commit_group;" ::: "memory");
}
__device__ __forceinline__ void cpa_wait0(){
    asm volatile("cp.async.wait_group 0;" ::: "memory");
}
__device__ __forceinline__ void cpa_wait1(){
    asm volatile("cp.async.wait_group 1;" ::: "memory");
}
__device__ __forceinline__ void split2(float v, f16& h, f16& l){
    h = __float2half_rn(v);
    l = __float2half_rn(v - __half2float(h));
}
__device__ __forceinline__ float gelu_tanh(float v){
    float c = v + 0.044715f * v * v * v;
    return 0.5f * v * (1.0f + tanhf(0.7978845608028654f * c));
}

// ---- fp16 split-A GEMM: C = alpha*(Ah+Al)*Bh^T (+epi). 128x128, BK=64 ----
#define LDSB 72
#define MATB (128*LDSB*2)
#define AH_OFF 0
#define AL_OFF MATB
#define BH_OFF (2*MATB)
#define STGB  (3*MATB)             // 55296 per stage
#define GEMM_SMEM_DYN (2*STGB)     // 110592

#define EPI_NONE       0
#define EPI_BIAS       1
#define EPI_BIAS_GELU  2
#define EPI_BIAS_RES   3
#define EPI_SPLIT      4

template<int EPI>
__global__ void __launch_bounds__(256, 2)
gemm_wmma(const f16* __restrict__ Ah, const f16* __restrict__ Al,
          const f16* __restrict__ Bh,
          float* __restrict__ C, const float* __restrict__ bias,
          const float* __restrict__ res,
          f16* __restrict__ Ch, f16* __restrict__ Cl,
          int K, int lda, int ldb, int ldc, float alpha, int wdiv,
          int biasStride,
          long long sAb, long long sAw, long long sBb, long long sBw,
          long long sCb, long long sCw)
{
    extern __shared__ char dsm[];
    uint32_t sb0 = s2u(dsm);

    int tid = threadIdx.x;
    int wid = tid >> 5;
    int wm = wid >> 2;
    int wn = wid & 3;
    int z = blockIdx.z;
    int zb = z / wdiv, zw = z - zb * wdiv;
    long long aoff = zb * sAb + zw * sAw;
    long long boff = zb * sBb + zw * sBw;
    long long coff = zb * sCb + zw * sCw;
    Ah += aoff; Al += aoff;
    Bh += boff;
    C  += coff;
    if (EPI == EPI_BIAS || EPI == EPI_BIAS_GELU || EPI == EPI_BIAS_RES)
        bias += (long long)zb * biasStride;
    const float* Rp = (EPI == EPI_BIAS_RES) ? (res + coff) : nullptr;

    int m0 = blockIdx.y * 128;
    int n0 = blockIdx.x * 128;

    wmma::fragment<wmma::accumulator, 16, 16, 16, float> acc[4][2];
#pragma unroll
    for (int i = 0; i < 4; i++)
#pragma unroll
        for (int j = 0; j < 2; j++) wmma::fill_fragment(acc[i][j], 0.f);

    auto loadStage = [&](int stg, int kk){
        uint32_t sb = sb0 + stg * STGB;
#pragma unroll
        for (int h = 0; h < 4; h++){
            int i = tid + h * 256;
            int row = i >> 3, ch = i & 7;
            uint32_t d = row * (LDSB*2) + ch * 16;
            long long ga = (long long)(m0 + row) * lda + kk + ch * 8;
            long long gb = (long long)(n0 + row) * ldb + kk + ch * 8;
            cpa16(sb + AH_OFF + d, Ah + ga);
            cpa16(sb + AL_OFF + d, Al + ga);
            cpa16(sb + BH_OFF + d, Bh + gb);
        }
    };

    int KT = K >> 6;
    loadStage(0, 0);
    cpa_commit();

    for (int kt = 0; kt < KT; kt++){
        if (kt + 1 < KT){
            loadStage((kt + 1) & 1, (kt + 1) * 64);
            cpa_commit();
            cpa_wait1();
        } else {
            cpa_wait0();
        }
        __syncthreads();

        const f16* st = (const f16*)(dsm + (kt & 1) * STGB);
        const f16* pAh = st + (AH_OFF/2) + (wm*64)*LDSB;
        const f16* pAl = st + (AL_OFF/2) + (wm*64)*LDSB;
        const f16* pBh = st + (BH_OFF/2) + (wn*32)*LDSB;
#pragma unroll
        for (int ks = 0; ks < 4; ks++){
            wmma::fragment<wmma::matrix_b, 16,16,16, f16, wmma::col_major> fBh[2];
#pragma unroll
            for (int j = 0; j < 2; j++)
                wmma::load_matrix_sync(fBh[j], pBh + j*16*LDSB + ks*16, LDSB);
#pragma unroll
            for (int i = 0; i < 4; i++){
                wmma::fragment<wmma::matrix_a, 16,16,16, f16, wmma::row_major> fAh, fAl;
                wmma::load_matrix_sync(fAh, pAh + i*16*LDSB + ks*16, LDSB);
                wmma::load_matrix_sync(fAl, pAl + i*16*LDSB + ks*16, LDSB);
#pragma unroll
                for (int j = 0; j < 2; j++){
                    wmma::mma_sync(acc[i][j], fAh, fBh[j], acc[i][j]);
                    wmma::mma_sync(acc[i][j], fAl, fBh[j], acc[i][j]);
                }
            }
        }
        __syncthreads();
    }

    // ---- block-wide epilogue via smem float staging ----
    float* sF = (float*)dsm;
#pragma unroll
    for (int i = 0; i < 4; i++)
#pragma unroll
        for (int j = 0; j < 2; j++)
            wmma::store_matrix_sync(
                sF + (wm*64 + i*16) * 128 + wn*32 + j*16,
                acc[i][j], 128, wmma::mem_row_major);
    __syncthreads();

#pragma unroll 1
    for (int t = 0; t < 16; t++){
        int i = tid + t * 256;
        int row = i >> 5, c4 = (i & 31) * 4;
        float4 v = *(float4*)&sF[row * 128 + c4];
        v.x *= alpha; v.y *= alpha; v.z *= alpha; v.w *= alpha;
        int gc = n0 + c4;
        if (EPI == EPI_BIAS || EPI == EPI_BIAS_GELU || EPI == EPI_BIAS_RES){
            float4 bb = *(const float4*)&bias[gc];
            v.x += bb.x; v.y += bb.y; v.z += bb.z; v.w += bb.w;
        }
        if (EPI == EPI_BIAS_GELU){
            v.x = gelu_tanh(v.x); v.y = gelu_tanh(v.y);
            v.z = gelu_tanh(v.z); v.w = gelu_tanh(v.w);
        }
        long long crow = (long long)(m0 + row) * ldc + gc;
        if (EPI == EPI_BIAS_RES){
            float4 rr = *(const float4*)&Rp[crow];
            v.x += rr.x; v.y += rr.y; v.z += rr.z; v.w += rr.w;
        }
        *(float4*)&C[crow] = v;
        if (EPI == EPI_SPLIT){
            long long so = coff + crow;
            f16 hh, ll;
            split2(v.x, hh, ll); Ch[so+0] = hh; Cl[so+0] = ll;
            split2(v.y, hh, ll); Ch[so+1] = hh; Cl[so+1] = ll;
            split2(v.z, hh, ll); Ch[so+2] = hh; Cl[so+2] = ll;
            split2(v.w, hh, ll); Ch[so+3] = hh; Cl[so+3] = ll;
        }
    }
}

// ---- bias pack ----
__global__ void packbias_kernel(const float* __restrict__ a, const float* __restrict__ b)
{
    int i = blockIdx.x * 256 + threadIdx.x;
    if (i < DIM_){ g_bias2[i] = a[i]; g_bias2[DIM_ + i] = b[i]; }
}

// ---- merged dual LayerNorm ----
__global__ void ln2_kernel(float* __restrict__ x,
                           const float* __restrict__ g0, const float* __restrict__ b0,
                           const float* __restrict__ g1, const float* __restrict__ b1v,
                           int L)
{
    __shared__ float buf[4096];
    __shared__ float r1[8], r2[8], st[2];
    long long row = blockIdx.x;
    const float* g = (row < BN_) ? g0 : g1;
    const float* bv = (row < BN_) ? b0 : b1v;
    float* xr = x + row * L;
    int tid = threadIdx.x;
    float s = 0.f, s2 = 0.f;
    for (int c = tid; c < L; c += 256){ float v = xr[c]; buf[c] = v; s += v; s2 += v*v; }
#pragma unroll
    for (int o = 16; o > 0; o >>= 1){
        s  += __shfl_xor_sync(0xffffffffu, s,  o);
        s2 += __shfl_xor_sync(0xffffffffu, s2, o);
    }
    int lane = tid & 31, w = tid >> 5;
    if (lane == 0){ r1[w] = s; r2[w] = s2; }
    __syncthreads();
    if (tid == 0){
        float ts = 0.f, ts2 = 0.f;
        for (int k = 0; k < 8; k++){ ts += r1[k]; ts2 += r2[k]; }
        float mean = ts / (float)L;
        st[0] = mean; st[1] = rsqrtf(ts2 / (float)L - mean*mean + 1e-5f);
    }
    __syncthreads();
    float mean = st[0], rstd = st[1];
    for (int c = tid; c < L; c += 256)
        xr[c] = (buf[c] - mean) * rstd * g[c] + bv[c];
}

// ---- LayerNorm -> fp16 hi/lo ----
__global__ void ln_bf_kernel(const float* __restrict__ x, f16* __restrict__ yh,
                             f16* __restrict__ yl,
                             const float* __restrict__ g, const float* __restrict__ bv,
                             int L)
{
    __shared__ float buf[4096];
    __shared__ float r1[8], r2[8], st[2];
    long long row = blockIdx.x;
    const float* xr = x + row * L;
    int tid = threadIdx.x;
    float s = 0.f, s2 = 0.f;
    for (int c = tid; c < L; c += 256){ float v = xr[c]; buf[c] = v; s += v; s2 += v*v; }
#pragma unroll
    for (int o = 16; o > 0; o >>= 1){
        s  += __shfl_xor_sync(0xffffffffu, s,  o);
        s2 += __shfl_xor_sync(0xffffffffu, s2, o);
    }
    int lane = tid & 31, w = tid >> 5;
    if (lane == 0){ r1[w] = s; r2[w] = s2; }
    __syncthreads();
    if (tid == 0){
        float ts = 0.f, ts2 = 0.f;
        for (int k = 0; k < 8; k++){ ts += r1[k]; ts2 += r2[k]; }
        float mean = ts / (float)L;
        st[0] = mean; st[1] = rsqrtf(ts2 / (float)L - mean*mean + 1e-5f);
    }
    __syncthreads();
    float mean = st[0], rstd = st[1];
    for (int c = tid; c < L; c += 256){
        float v = (buf[c] - mean) * rstd * g[c] + bv[c];
        f16 h, l; split2(v, h, l);
        yh[row * L + c] = h; yl[row * L + c] = l;
    }
}

// ---- RMSNorm over 64-dim head vectors ----
__global__ void rms_kernel(float* __restrict__ x, const float* __restrict__ g,
                           int vecs_per_row, int row_stride, int nrows)
{
    int vid = blockIdx.x * 8 + (threadIdx.x >> 5);
    int lane = threadIdx.x & 31;
    int r = vid / vecs_per_row;
    int h = vid - r * vecs_per_row;
    if (r >= nrows) return;
    float* p = x + (long long)r * row_stride + h * DHEAD_;
    float v0 = p[lane], v1 = p[lane + 32];
    float ss = v0*v0 + v1*v1;
#pragma unroll
    for (int o = 16; o > 0; o >>= 1) ss += __shfl_xor_sync(0xffffffffu, ss, o);
    float rs = rsqrtf(ss * (1.0f/64.0f) + 1e-6f);
    p[lane]      = v0 * rs * g[lane];
    p[lane + 32] = v1 * rs * g[lane + 32];
}

// ---- rotary prep ----
__global__ void prep_kernel(const float* __restrict__ text,
                            const float* __restrict__ at,
                            f16* __restrict__ qh, f16* __restrict__ ql,
                            f16* __restrict__ kh)
{
    int row = blockIdx.x;
    int b = row / NP_;
    int pr = row - b * NP_;
    long long kout = (long long)row * DIM_;
    if (pr < WS_){
        f16 zz = __float2half(0.f);
        for (int c = threadIdx.x; c < DIM_; c += 256) kh[kout+c] = zz;
        return;
    }
    int t = pr - WS_;
    long long src = ((long long)b * N_ + t) * DIM_;
    for (int c = threadIdx.x; c < DIM_; c += 256){
        int j = c & 511;
        float invf = exp2f((float)j * (-13.28771238f * (1.0f/512.0f)));
        float ang = (float)t * invf;
        float cs = cosf(ang), sn = sinf(ang);
        float kx = at[src + c];
        float ko = (c < 512) ? -at[src + c + 512] : at[src + c - 512];
        kh[kout + c] = __float2half_rn(kx * cs + ko * sn);
        float qx = text[src + c];
        float qo = (c < 512) ? -text[src + c + 512] : text[src + c - 512];
        f16 h, l;
        split2(qx * cs + qo * sn, h, l);
        qh[src + c] = h; ql[src + c] = l;
    }
}

// ---- transpose to single fp16 ----
__global__ void tconv_kernel(const float* __restrict__ in, f16* __restrict__ oh,
                             int inLd, int outLd, int pad,
                             long long inB, long long outB)
{
    __shared__ float t[32][33];
    in += blockIdx.z * inB;
    oh += blockIdx.z * outB;
    int p0 = blockIdx.x * 32, c0 = blockIdx.y * 32;
    int tx = threadIdx.x, ty = threadIdx.y;
    for (int i = ty; i < 32; i += 8){
        int r = p0 + i - pad;
        t[i][tx] = (r >= 0) ? in[(long long)r * inLd + c0 + tx] : 0.f;
    }
    __syncthreads();
    for (int i = ty; i < 32; i += 8){
        long long o = (long long)(c0 + i) * outLd + p0 + tx;
        oh[o] = __float2half_rn(t[tx][i]);
    }
}

// ---- elementwise split fp32 -> fp16 hi/lo ----
__global__ void conv_kernel(const float* __restrict__ x, f16* __restrict__ h,
                            f16* __restrict__ l, int n)
{
    int i = (blockIdx.x * 256 + threadIdx.x) * 4;
    if (i < n){
        float4 v = *(const float4*)&x[i];
        f16 hh, ll;
        split2(v.x, hh, ll); h[i+0] = hh; l[i+0] = ll;
        split2(v.y, hh, ll); h[i+1] = hh; l[i+1] = ll;
        split2(v.z, hh, ll); h[i+2] = hh; l[i+2] = ll;
        split2(v.w, hh, ll); h[i+3] = hh; l[i+3] = ll;
    }
}

// ---- local-attention masked softmax -> fp16 hi/lo ----
__global__ void softmax_local_kernel(const float* __restrict__ p,
                                     f16* __restrict__ ph, f16* __restrict__ pl)
{
    __shared__ float buf[1024];
    __shared__ float red[8], bc[2];
    int r = blockIdx.x;
    int i = r & (WS_ - 1);
    int z = r >> 9;
    int w = z & (NWIN_ - 1);
    int qp = w * WS_ + i;
    const float* row = p + (long long)r * (2 * WS_);
    int tid = threadIdx.x, lane = tid & 31, wp = tid >> 5;

    float mx = -1e30f;
    for (int j = tid; j < 2*WS_; j += 256){
        int kp = (w - 1) * WS_ + j;
        float v = (kp >= 0 && kp <= qp) ? row[j] : -1e9f;
        buf[j] = v;
        mx = fmaxf(mx, v);
    }
#pragma unroll
    for (int o = 16; o > 0; o >>= 1) mx = fmaxf(mx, __shfl_xor_sync(0xffffffffu, mx, o));
    if (lane == 0) red[wp] = mx;
    __syncthreads();
    if (tid == 0){
        float m = red[0];
        for (int k = 1; k < 8; k++) m = fmaxf(m, red[k]);
        bc[0] = m;
    }
    __syncthreads();
    mx = bc[0];
    float sum = 0.f;
    for (int j = tid; j < 2*WS_; j += 256){
        float e = __expf(buf[j] - mx);
        buf[j] = e; sum += e;
    }
#pragma unroll
    for (int o = 16; o > 0; o >>= 1) sum += __shfl_xor_sync(0xffffffffu, sum, o);
    if (lane == 0) red[wp] = sum;
    __syncthreads();
    if (tid == 0){
        float t = 0.f;
        for (int k = 0; k < 8; k++) t += red[k];
        bc[1] = 1.0f / t;
    }
    __syncthreads();
    float inv = bc[1];
    for (int j = tid; j < 2*WS_; j += 256){
        f16 h, l; split2(buf[j] * inv, h, l);
        long long o = (long long)r * (2*WS_) + j;
        ph[o] = h; pl[o] = l;
    }
}

// ---- causal flash attention fp32; heavy-CTA-first scheduling ----
#define QP_ 68
#define ATTN_SMEM_BYTES (4 * 64 * QP_ * 4 + 3 * 64 * 4)

__global__ void __launch_bounds__(256)
attn_kernel(const float* __restrict__ qkv,
            float* __restrict__ o, f16* __restrict__ oh, f16* __restrict__ ol)
{
    extern __shared__ float sm[];
    float* QsT = sm;
    float* KsT = QsT + 64 * QP_;
    float* Vs  = KsT + 64 * QP_;
    float* SsT = Vs  + 64 * QP_;
    float* Ms = SsT + 64 * QP_;
    float* Ls = Ms + 64;
    float* Cs = Ls + 64;

    int tid = threadIdx.x;
    int bh = blockIdx.y;
    int b = bh >> 3, h = bh & 7;
    int qt = gridDim.x - 1 - blockIdx.x;      // heavy CTAs scheduled first
    int q0 = qt * 64;
    int ty = tid >> 4, tx = tid & 15;

    for (int idx = tid; idx < 4096; idx += 256){
        int r = idx >> 6, c = idx & 63;
        QsT[c * QP_ + r] =
            qkv[((long long)(b * N_ + q0 + r)) * QKVLD_ + h * 64 + c] * 0.125f;
    }
    if (tid < 64){ Ms[tid] = -INFINITY; Ls[tid] = 0.f; }
    float oacc[16];
#pragma unroll
    for (int i = 0; i < 16; i++) oacc[i] = 0.f;
    __syncthreads();

    int lastTile = qt;
    for (int kt = 0; kt <= lastTile; kt++){
        for (int idx = tid; idx < 4096; idx += 256){
            int r = idx >> 6, c = idx & 63;
            long long base =
                ((long long)(b * N_ + kt * 64 + r)) * QKVLD_ + INNER_ + h * 64 + c;
            KsT[c * QP_ + r] = qkv[base];
            Vs[r * QP_ + c]  = qkv[base + INNER_];
        }
        __syncthreads();

        float sacc[16];
#pragma unroll
        for (int i = 0; i < 16; i++) sacc[i] = 0.f;
#pragma unroll 8
        for (int kk = 0; kk < 64; kk++){
            float4 aq = *(const float4*)&QsT[kk * QP_ + ty * 4];
            float4 bk = *(const float4*)&KsT[kk * QP_ + tx * 4];
            float a4[4] = {aq.x, aq.y, aq.z, aq.w};
            float b4[4] = {bk.x, bk.y, bk.z, bk.w};
#pragma unroll
            for (int i = 0; i < 4; i++)
#pragma unroll
                for (int j = 0; j < 4; j++)
                    sacc[i*4+j] += a4[i] * b4[j];
        }
        bool diag = (kt == lastTile);
#pragma unroll
        for (int i = 0; i < 4; i++)
#pragma unroll
            for (int j = 0; j < 4; j++){
                int qr = ty * 4 + i, kc = tx * 4 + j;
                float s = sacc[i*4+j];
                if (diag && kc > qr) s = -INFINITY;
                SsT[kc * QP_ + qr] = s;
            }
        __syncthreads();

        if (tid < 64){
            int r = tid;
            float mt = -INFINITY;
#pragma unroll 8
            for (int c = 0; c < 64; c++) mt = fmaxf(mt, SsT[c * QP_ + r]);
            float mo = Ms[r];
            float mn = fmaxf(mo, mt);
            float corr = __expf(mo - mn);
            float ls = 0.f;
#pragma unroll 8
            for (int c = 0; c < 64; c++){
                float e = __expf(SsT[c * QP_ + r] - mn);
                SsT[c * QP_ + r] = e;
                ls += e;
            }
            Ls[r] = Ls[r] * corr + ls;
            Ms[r] = mn;
            Cs[r] = corr;
        }
        __syncthreads();

        float cf[4];
#pragma unroll
        for (int i = 0; i < 4; i++) cf[i] = Cs[ty * 4 + i];
#pragma unroll
        for (int i = 0; i < 4; i++)
#pragma unroll
            for (int j = 0; j < 4; j++) oacc[i*4+j] *= cf[i];

#pragma unroll 8
        for (int kk = 0; kk < 64; kk++){
            float4 ap = *(const float4*)&SsT[kk * QP_ + ty * 4];
            float4 vv = *(const float4*)&Vs[kk * QP_ + tx * 4];
            float a4[4] = {ap.x, ap.y, ap.z, ap.w};
            float b4[4] = {vv.x, vv.y, vv.z, vv.w};
#pragma unroll
            for (int i = 0; i < 4; i++)
#pragma unroll
                for (int j = 0; j < 4; j++)
                    oacc[i*4+j] += a4[i] * b4[j];
        }
        __syncthreads();
    }

#pragma unroll
    for (int i = 0; i < 4; i++){
        float inv = 1.0f / Ls[ty * 4 + i];
        long long orow =
            ((long long)(b * N_ + q0 + ty * 4 + i)) * INNER_ + h * 64 + tx * 4;
        float4 vo = make_float4(oacc[i*4+0]*inv, oacc[i*4+1]*inv,
                                oacc[i*4+2]*inv, oacc[i*4+3]*inv);
        *(float4*)&o[orow] = vo;
        f16 hh, ll;
        split2(vo.x, hh, ll); oh[orow+0] = hh; ol[orow+0] = ll;
        split2(vo.y, hh, ll); oh[orow+1] = hh; ol[orow+1] = ll;
        split2(vo.z, hh, ll); oh[orow+2] = hh; ol[orow+2] = ll;
        split2(vo.w, hh, ll); oh[orow+3] = hh; ol[orow+3] = ll;
    }
}

// ---- launch ----
extern "C" void kernel_launch(void* const* d_in, const int* in_sizes, int n_in,
                              void* d_out, int out_size)
{
    (void)in_sizes; (void)n_in; (void)out_size;
    const float* text  = (const float*)d_in[0];
    const float* audio = (const float*)d_in[1];
    const float* video = (const float*)d_in[2];
    const float* Wa    = (const float*)d_in[3];
    const float* ba    = (const float*)d_in[4];
    const float* lna_g = (const float*)d_in[5];
    const float* lna_b = (const float*)d_in[6];
    const float* Wvid  = (const float*)d_in[7];
    const float* bvid  = (const float*)d_in[8];
    const float* lnv_g = (const float*)d_in[9];
    const float* lnv_b = (const float*)d_in[10];
    const float* ln1_g = (const float*)d_in[11];
    const float* ln1_b = (const float*)d_in[12];
    const float* Wq    = (const float*)d_in[13];
    const float* Wkv   = (const float*)d_in[14];
    const float* qn_g  = (const float*)d_in[15];
    const float* kn_g  = (const float*)d_in[16];
    const float* Wo    = (const float*)d_in[17];
    const float* W1    = (const float*)d_in[18];
    const float* b1    = (const float*)d_in[19];
    const float* ln2_g = (const float*)d_in[20];
    const float* ln2_b = (const float*)d_in[21];
    const float* W2    = (const float*)d_in[22];
    const float* b2    = (const float*)d_in[23];
    float* out = (float*)d_out;

#define SYM(p, s) void* p; cudaGetSymbolAddress(&p, s)
    SYM(atvt, g_atvt); SYM(probs, g_probs);
    SYM(x, g_x);     SYM(qkvp, g_qkv);
    SYM(ob, g_o);    SYM(x2, g_x2);   SYM(ff, g_ff);
    SYM(bias2, g_bias2);
    SYM(inH, g_inH); SYM(inL, g_inL);
    SYM(qh, g_qh);   SYM(ql, g_ql);
    SYM(kh, g_kh);   SYM(vTh, g_vTh);
    SYM(ph, g_ph);   SYM(pl, g_pl);
    SYM(hh, g_hh);   SYM(hl, g_hl);
    SYM(obH, g_obH); SYM(obL, g_obL);
    SYM(x2H, g_x2H); SYM(x2L, g_x2L);
    SYM(ffH, g_ffH); SYM(ffL, g_ffL);
    SYM(WavT, g_WavT); SYM(WqkvT, g_WqkvT);
    SYM(WoT, g_WoT); SYM(W1T, g_W1T); SYM(W2T, g_W2T);
#undef SYM

    cudaFuncSetAttribute(gemm_wmma<EPI_NONE>,      cudaFuncAttributeMaxDynamicSharedMemorySize, GEMM_SMEM_DYN);
    cudaFuncSetAttribute(gemm_wmma<EPI_BIAS>,      cudaFuncAttributeMaxDynamicSharedMemorySize, GEMM_SMEM_DYN);
    cudaFuncSetAttribute(gemm_wmma<EPI_BIAS_GELU>, cudaFuncAttributeMaxDynamicSharedMemorySize, GEMM_SMEM_DYN);
    cudaFuncSetAttribute(gemm_wmma<EPI_BIAS_RES>,  cudaFuncAttributeMaxDynamicSharedMemorySize, GEMM_SMEM_DYN);
    cudaFuncSetAttribute(gemm_wmma<EPI_SPLIT>,     cudaFuncAttributeMaxDynamicSharedMemorySize, GEMM_SMEM_DYN);
    cudaFuncSetAttribute(attn_kernel, cudaFuncAttributeMaxDynamicSharedMemorySize, ATTN_SMEM_BYTES);

    // side stream + fork/join events (created once; same work every call)
    static cudaStream_t s2 = nullptr;
    static cudaEvent_t evFork = nullptr, evJoin = nullptr;
    if (s2 == nullptr){
        cudaStreamCreateWithFlags(&s2, cudaStreamNonBlocking);
        cudaEventCreateWithFlags(&evFork, cudaEventDisableTiming);
        cudaEventCreateWithFlags(&evJoin, cudaEventDisableTiming);
    }

    dim3 t32(32, 8);
    long long DD = (long long)DIM_ * DIM_;
    long long BD = (long long)BN_ * DIM_;

    packbias_kernel<<<4, 256>>>(ba, bvid);

    // fork: side stream transposes weights not needed until later GEMMs
    cudaEventRecord(evFork, 0);
    cudaStreamWaitEvent(s2, evFork, 0);
    tconv_kernel<<<dim3(32, 16, 1), t32, 0, s2>>>(Wq,  (f16*)WqkvT, INNER_, DIM_, 0, 0, 0);
    tconv_kernel<<<dim3(32, 32, 1), t32, 0, s2>>>(Wkv, (f16*)WqkvT + (long long)INNER_*DIM_, 2*INNER_, DIM_, 0, 0, 0);
    tconv_kernel<<<dim3(16, 32, 1), t32, 0, s2>>>(Wo,  (f16*)WoT, DIM_, INNER_, 0, 0, 0);
    tconv_kernel<<<dim3(32, 128,1), t32, 0, s2>>>(W1,  (f16*)W1T, FF_,  DIM_,   0, 0, 0);
    tconv_kernel<<<dim3(128,32, 1), t32, 0, s2>>>(W2,  (f16*)W2T, DIM_, FF_,    0, 0, 0);
    cudaEventRecord(evJoin, s2);

    // main stream: adapter path
    tconv_kernel<<<dim3(32, 32, 1), t32>>>(Wa,  (f16*)WavT,      DIM_, DIM_, 0, 0, 0);
    tconv_kernel<<<dim3(32, 32, 1), t32>>>(Wvid,(f16*)WavT + DD, DIM_, DIM_, 0, 0, 0);
    conv_kernel<<<BN_*DIM_/1024, 256>>>(audio, (f16*)inH, (f16*)inL, BN_*DIM_);
    conv_kernel<<<BN_*DIM_/1024, 256>>>(video, (f16*)inH + BD, (f16*)inL + BD, BN_*DIM_);

    // 1) merged adapters
    gemm_wmma<EPI_BIAS><<<dim3(DIM_/128, BN_/128, 2), 256, GEMM_SMEM_DYN>>>(
        (f16*)inH, (f16*)inL, (f16*)WavT, (float*)atvt, (float*)bias2, nullptr,
        nullptr, nullptr, DIM_, DIM_, DIM_, DIM_, 1.f, 1, DIM_,
        BD, 0, DD, 0, BD, 0);

    float* at = (float*)atvt;
    float* vt = (float*)atvt + BD;
    ln2_kernel<<<2*BN_, 256>>>((float*)atvt, lna_g, lna_b, lnv_g, lnv_b, DIM_);

    // 2) rotary + padded layouts
    prep_kernel<<<B_ * NP_, 256>>>(text, at, (f16*)qh, (f16*)ql, (f16*)kh);
    tconv_kernel<<<dim3(NP_/32, DIM_/32, B_), t32>>>(vt,
        (f16*)vTh, DIM_, NP_, WS_,
        (long long)N_*DIM_, (long long)DIM_*NP_);

    // 3) local attention (8 windows batched)
    gemm_wmma<EPI_NONE><<<dim3((2*WS_)/128, WS_/128, B_*NWIN_), 256, GEMM_SMEM_DYN>>>(
        (f16*)qh, (f16*)ql, (f16*)kh, (float*)probs, nullptr, nullptr,
        nullptr, nullptr, DIM_, DIM_, DIM_, 2*WS_, 0.03125f, NWIN_, 0,
        (long long)N_*DIM_,  (long long)WS_*DIM_,
        (long long)NP_*DIM_, (long long)WS_*DIM_,
        (long long)NWIN_*WS_*2*WS_, (long long)WS_*2*WS_);
    softmax_local_kernel<<<B_*NWIN_*WS_, 256>>>((float*)probs, (f16*)ph, (f16*)pl);
    gemm_wmma<EPI_NONE><<<dim3(DIM_/128, WS_/128, B_*NWIN_), 256, GEMM_SMEM_DYN>>>(
        (f16*)ph, (f16*)pl, (f16*)vTh, (float*)x, nullptr, nullptr,
        nullptr, nullptr, 2*WS_, 2*WS_, NP_, DIM_, 1.f, NWIN_, 0,
        (long long)NWIN_*WS_*2*WS_, (long long)WS_*2*WS_,
        (long long)DIM_*NP_, (long long)WS_,
        (long long)N_*DIM_, (long long)WS_*DIM_);

    // 4) ln1 -> merged qkv projection -> rmsnorm (join side stream first)
    ln_bf_kernel<<<BN_, 256>>>((float*)x, (f16*)hh, (f16*)hl, ln1_g, ln1_b, DIM_);
    cudaStreamWaitEvent(0, evJoin, 0);
    gemm_wmma<EPI_NONE><<<dim3(QKVLD_/128, BN_/128, 1), 256, GEMM_SMEM_DYN>>>(
        (f16*)hh, (f16*)hl, (f16*)WqkvT, (float*)qkvp, nullptr, nullptr,
        nullptr, nullptr, DIM_, DIM_, DIM_, QKVLD_, 1.f, 1, 0, 0,0,0,0,0,0);
    rms_kernel<<<(BN_*HEADS_)/8, 256>>>((float*)qkvp, qn_g, HEADS_, QKVLD_, BN_);
    rms_kernel<<<(BN_*HEADS_)/8, 256>>>((float*)qkvp + INNER_, kn_g, HEADS_, QKVLD_, BN_);

    // 5) causal attention
    attn_kernel<<<dim3(N_/64, B_*HEADS_), 256, ATTN_SMEM_BYTES>>>(
        (float*)qkvp, (float*)ob, (f16*)obH, (f16*)obL);

    // 6) x2 = 2*(o @ Wo)
    gemm_wmma<EPI_SPLIT><<<dim3(DIM_/128, BN_/128, 1), 256, GEMM_SMEM_DYN>>>(
        (f16*)obH, (f16*)obL, (f16*)WoT, (float*)x2, nullptr, nullptr,
        (f16*)x2H, (f16*)x2L, INNER_, INNER_, INNER_, DIM_, 2.f, 1, 0, 0,0,0,0,0,0);

    // 7) FFN
    gemm_wmma<EPI_BIAS_GELU><<<dim3(FF_/128, BN_/128, 1), 256, GEMM_SMEM_DYN>>>(
        (f16*)x2H, (f16*)x2L, (f16*)W1T, (float*)ff, b1, nullptr,
        nullptr, nullptr, DIM_, DIM_, DIM_, FF_, 1.f, 1, 0, 0,0,0,0,0,0);
    ln_bf_kernel<<<BN_, 256>>>((float*)ff, (f16*)ffH, (f16*)ffL, ln2_g, ln2_b, FF_);
    gemm_wmma<EPI_BIAS_RES><<<dim3(DIM_/128, BN_/128, 1), 256, GEMM_SMEM_DYN>>>(
        (f16*)ffH, (f16*)ffL, (f16*)W2T, out, b2, (float*)x2,
        nullptr, nullptr, FF_, FF_, FF_, DIM_, 1.f, 1, 0, 0,0,0,0,0,0);
}

// round 17
// speedup vs baseline: 2.1156x; 1.0061x over previous
#include <cuda_runtime.h>
#include <cuda_fp16.h>
#include <mma.h>
#include <math.h>
#include <stdint.h>

using namespace nvcuda;
typedef __half f16;

#define B_      2
#define N_      2048
#define DIM_    1024
#define INNER_  512
#define HEADS_  8
#define DHEAD_  64
#define WS_     512
#define FF_     4096
#define BN_     (B_*N_)
#define NP_     (N_+WS_)
#define NWIN_   (N_/WS_)
#define QKVLD_  1536

// ---- fp32 scratch ----
__device__ float g_atvt[2*BN_*DIM_];
__device__ float g_probs[B_*NWIN_*WS_*2*WS_];
__device__ float g_x  [BN_*DIM_];
__device__ float g_qkv[BN_*QKVLD_];
__device__ float g_o  [BN_*INNER_];
__device__ float g_ff [BN_*FF_];
__device__ float g_bias2[2*DIM_];

// ---- fp16 scratch ----
__device__ f16 g_inH [2*BN_*DIM_], g_inL [2*BN_*DIM_];
__device__ f16 g_qh [BN_*DIM_],   g_ql [BN_*DIM_];
__device__ f16 g_kh [B_*NP_*DIM_];
__device__ f16 g_vTh[B_*DIM_*NP_];
__device__ f16 g_ph [B_*NWIN_*WS_*2*WS_], g_pl[B_*NWIN_*WS_*2*WS_];
__device__ f16 g_hh [BN_*DIM_],   g_hl [BN_*DIM_];
__device__ f16 g_obH[BN_*INNER_], g_obL[BN_*INNER_];
__device__ f16 g_x2H[BN_*DIM_],   g_x2L[BN_*DIM_];
__device__ f16 g_ffH[BN_*FF_],    g_ffL[BN_*FF_];
__device__ f16 g_WavT[2*DIM_*DIM_];
__device__ f16 g_WqkvT[QKVLD_*DIM_];
__device__ f16 g_WoT [DIM_*INNER_];
__device__ f16 g_W1T [FF_*DIM_];
__device__ f16 g_W2T [DIM_*FF_];

// ---- helpers ----
__device__ __forceinline__ uint32_t s2u(const void* p){
    uint32_t a;
    asm("{ .reg .u64 t; cvta.to.shared.u64 t, %1; cvt.u32.u64 %0, t; }"
        : "=r"(a) : "l"(p));
    return a;
}
__device__ __forceinline__ void cpa16(uint32_t d, const void* s){
    asm volatile("cp.async.cg.shared.global [%0], [%1], 16;" :: "r"(d), "l"(s));
}
__device__ __forceinline__ void cpa_commit(){
    asm volatile("cp.async.commit_group;" ::: "memory");
}
__device__ __forceinline__ void cpa_wait0(){
    asm volatile("cp.async.wait_group 0;" ::: "memory");
}
__device__ __forceinline__ void cpa_wait1(){
    asm volatile("cp.async.wait_group 1;" ::: "memory");
}
__device__ __forceinline__ void split2(float v, f16& h, f16& l){
    h = __float2half_rn(v);
    l = __float2half_rn(v - __half2float(h));
}
__device__ __forceinline__ float gelu_tanh(float v){
    float c = v + 0.044715f * v * v * v;
    return 0.5f * v * (1.0f + tanhf(0.7978845608028654f * c));
}

// ---- fp16 split-A GEMM: C = alpha*(Ah+Al)*Bh^T (+epi). 128x128, BK=64 ----
// Warp tile 32x64 (wm=wid&3, wn=wid>>2): 8 frag loads per 16 mmas.
#define LDSB 72
#define MATB (128*LDSB*2)
#define AH_OFF 0
#define AL_OFF MATB
#define BH_OFF (2*MATB)
#define STGB  (3*MATB)             // 55296 per stage
#define GEMM_SMEM_DYN (2*STGB)     // 110592

#define EPI_NONE       0
#define EPI_BIAS       1
#define EPI_BIAS_GELU  2
#define EPI_BIAS_RESH  3           // bias + residual from fp16 hi/lo pair
#define EPI_SPLIT      4           // alpha, write ONLY fp16 hi/lo

template<int EPI>
__global__ void __launch_bounds__(256, 2)
gemm_wmma(const f16* __restrict__ Ah, const f16* __restrict__ Al,
          const f16* __restrict__ Bh,
          float* __restrict__ C, const float* __restrict__ bias,
          f16* __restrict__ Ch, f16* __restrict__ Cl,
          int K, int lda, int ldb, int ldc, float alpha, int wdiv,
          int biasStride,
          long long sAb, long long sAw, long long sBb, long long sBw,
          long long sCb, long long sCw)
{
    extern __shared__ char dsm[];
    uint32_t sb0 = s2u(dsm);

    int tid = threadIdx.x;
    int wid = tid >> 5;
    int wm = wid & 3;           // 0..3 (32-row block)
    int wn = wid >> 2;          // 0..1 (64-col block)
    int z = blockIdx.z;
    int zb = z / wdiv, zw = z - zb * wdiv;
    long long aoff = zb * sAb + zw * sAw;
    long long boff = zb * sBb + zw * sBw;
    long long coff = zb * sCb + zw * sCw;
    Ah += aoff; Al += aoff;
    Bh += boff;
    C  += coff;
    if (EPI == EPI_BIAS || EPI == EPI_BIAS_GELU || EPI == EPI_BIAS_RESH)
        bias += (long long)zb * biasStride;

    int m0 = blockIdx.y * 128;
    int n0 = blockIdx.x * 128;

    wmma::fragment<wmma::accumulator, 16, 16, 16, float> acc[2][4];
#pragma unroll
    for (int i = 0; i < 2; i++)
#pragma unroll
        for (int j = 0; j < 4; j++) wmma::fill_fragment(acc[i][j], 0.f);

    auto loadStage = [&](int stg, int kk){
        uint32_t sb = sb0 + stg * STGB;
#pragma unroll
        for (int h = 0; h < 4; h++){
            int i = tid + h * 256;
            int row = i >> 3, ch = i & 7;
            uint32_t d = row * (LDSB*2) + ch * 16;
            long long ga = (long long)(m0 + row) * lda + kk + ch * 8;
            long long gb = (long long)(n0 + row) * ldb + kk + ch * 8;
            cpa16(sb + AH_OFF + d, Ah + ga);
            cpa16(sb + AL_OFF + d, Al + ga);
            cpa16(sb + BH_OFF + d, Bh + gb);
        }
    };

    int KT = K >> 6;
    loadStage(0, 0);
    cpa_commit();

    for (int kt = 0; kt < KT; kt++){
        if (kt + 1 < KT){
            loadStage((kt + 1) & 1, (kt + 1) * 64);
            cpa_commit();
            cpa_wait1();
        } else {
            cpa_wait0();
        }
        __syncthreads();

        const f16* st = (const f16*)(dsm + (kt & 1) * STGB);
        const f16* pAh = st + (AH_OFF/2) + (wm*32)*LDSB;
        const f16* pAl = st + (AL_OFF/2) + (wm*32)*LDSB;
        const f16* pBh = st + (BH_OFF/2) + (wn*64)*LDSB;
#pragma unroll
        for (int ks = 0; ks < 4; ks++){
            wmma::fragment<wmma::matrix_b, 16,16,16, f16, wmma::col_major> fBh[4];
#pragma unroll
            for (int j = 0; j < 4; j++)
                wmma::load_matrix_sync(fBh[j], pBh + j*16*LDSB + ks*16, LDSB);
#pragma unroll
            for (int i = 0; i < 2; i++){
                wmma::fragment<wmma::matrix_a, 16,16,16, f16, wmma::row_major> fAh, fAl;
                wmma::load_matrix_sync(fAh, pAh + i*16*LDSB + ks*16, LDSB);
                wmma::load_matrix_sync(fAl, pAl + i*16*LDSB + ks*16, LDSB);
#pragma unroll
                for (int j = 0; j < 4; j++){
                    wmma::mma_sync(acc[i][j], fAh, fBh[j], acc[i][j]);
                    wmma::mma_sync(acc[i][j], fAl, fBh[j], acc[i][j]);
                }
            }
        }
        __syncthreads();
    }

    // ---- block-wide epilogue via smem float staging ----
    float* sF = (float*)dsm;
#pragma unroll
    for (int i = 0; i < 2; i++)
#pragma unroll
        for (int j = 0; j < 4; j++)
            wmma::store_matrix_sync(
                sF + (wm*32 + i*16) * 128 + wn*64 + j*16,
                acc[i][j], 128, wmma::mem_row_major);
    __syncthreads();

#pragma unroll 1
    for (int t = 0; t < 16; t++){
        int i = tid + t * 256;
        int row = i >> 5, c4 = (i & 31) * 4;
        float4 v = *(float4*)&sF[row * 128 + c4];
        v.x *= alpha; v.y *= alpha; v.z *= alpha; v.w *= alpha;
        int gc = n0 + c4;
        if (EPI == EPI_BIAS || EPI == EPI_BIAS_GELU || EPI == EPI_BIAS_RESH){
            float4 bb = *(const float4*)&bias[gc];
            v.x += bb.x; v.y += bb.y; v.z += bb.z; v.w += bb.w;
        }
        if (EPI == EPI_BIAS_GELU){
            v.x = gelu_tanh(v.x); v.y = gelu_tanh(v.y);
            v.z = gelu_tanh(v.z); v.w = gelu_tanh(v.w);
        }
        long long crow = (long long)(m0 + row) * ldc + gc;
        if (EPI == EPI_BIAS_RESH){
            long long so = coff + crow;
            v.x += __half2float(Ch[so+0]) + __half2float(Cl[so+0]);
            v.y += __half2float(Ch[so+1]) + __half2float(Cl[so+1]);
            v.z += __half2float(Ch[so+2]) + __half2float(Cl[so+2]);
            v.w += __half2float(Ch[so+3]) + __half2float(Cl[so+3]);
        }
        if (EPI != EPI_SPLIT)
            *(float4*)&C[crow] = v;
        if (EPI == EPI_SPLIT){
            long long so = coff + crow;
            f16 hh, ll;
            split2(v.x, hh, ll); Ch[so+0] = hh; Cl[so+0] = ll;
            split2(v.y, hh, ll); Ch[so+1] = hh; Cl[so+1] = ll;
            split2(v.z, hh, ll); Ch[so+2] = hh; Cl[so+2] = ll;
            split2(v.w, hh, ll); Ch[so+3] = hh; Cl[so+3] = ll;
        }
    }
}

// ---- bias pack ----
__global__ void packbias_kernel(const float* __restrict__ a, const float* __restrict__ b)
{
    int i = blockIdx.x * 256 + threadIdx.x;
    if (i < DIM_){ g_bias2[i] = a[i]; g_bias2[DIM_ + i] = b[i]; }
}

// ---- merged dual LayerNorm ----
__global__ void ln2_kernel(float* __restrict__ x,
                           const float* __restrict__ g0, const float* __restrict__ b0,
                           const float* __restrict__ g1, const float* __restrict__ b1v,
                           int L)
{
    __shared__ float buf[4096];
    __shared__ float r1[8], r2[8], st[2];
    long long row = blockIdx.x;
    const float* g = (row < BN_) ? g0 : g1;
    const float* bv = (row < BN_) ? b0 : b1v;
    float* xr = x + row * L;
    int tid = threadIdx.x;
    float s = 0.f, s2 = 0.f;
    for (int c = tid; c < L; c += 256){ float v = xr[c]; buf[c] = v; s += v; s2 += v*v; }
#pragma unroll
    for (int o = 16; o > 0; o >>= 1){
        s  += __shfl_xor_sync(0xffffffffu, s,  o);
        s2 += __shfl_xor_sync(0xffffffffu, s2, o);
    }
    int lane = tid & 31, w = tid >> 5;
    if (lane == 0){ r1[w] = s; r2[w] = s2; }
    __syncthreads();
    if (tid == 0){
        float ts = 0.f, ts2 = 0.f;
        for (int k = 0; k < 8; k++){ ts += r1[k]; ts2 += r2[k]; }
        float mean = ts / (float)L;
        st[0] = mean; st[1] = rsqrtf(ts2 / (float)L - mean*mean + 1e-5f);
    }
    __syncthreads();
    float mean = st[0], rstd = st[1];
    for (int c = tid; c < L; c += 256)
        xr[c] = (buf[c] - mean) * rstd * g[c] + bv[c];
}

// ---- LayerNorm -> fp16 hi/lo ----
__global__ void ln_bf_kernel(const float* __restrict__ x, f16* __restrict__ yh,
                             f16* __restrict__ yl,
                             const float* __restrict__ g, const float* __restrict__ bv,
                             int L)
{
    __shared__ float buf[4096];
    __shared__ float r1[8], r2[8], st[2];
    long long row = blockIdx.x;
    const float* xr = x + row * L;
    int tid = threadIdx.x;
    float s = 0.f, s2 = 0.f;
    for (int c = tid; c < L; c += 256){ float v = xr[c]; buf[c] = v; s += v; s2 += v*v; }
#pragma unroll
    for (int o = 16; o > 0; o >>= 1){
        s  += __shfl_xor_sync(0xffffffffu, s,  o);
        s2 += __shfl_xor_sync(0xffffffffu, s2, o);
    }
    int lane = tid & 31, w = tid >> 5;
    if (lane == 0){ r1[w] = s; r2[w] = s2; }
    __syncthreads();
    if (tid == 0){
        float ts = 0.f, ts2 = 0.f;
        for (int k = 0; k < 8; k++){ ts += r1[k]; ts2 += r2[k]; }
        float mean = ts / (float)L;
        st[0] = mean; st[1] = rsqrtf(ts2 / (float)L - mean*mean + 1e-5f);
    }
    __syncthreads();
    float mean = st[0], rstd = st[1];
    for (int c = tid; c < L; c += 256){
        float v = (buf[c] - mean) * rstd * g[c] + bv[c];
        f16 h, l; split2(v, h, l);
        yh[row * L + c] = h; yl[row * L + c] = l;
    }
}

// ---- merged q+k RMSNorm over 64-dim head vectors ----
__global__ void rms2_kernel(float* __restrict__ x,
                            const float* __restrict__ gq, const float* __restrict__ gk)
{
    int vid = blockIdx.x * 8 + (threadIdx.x >> 5);
    int lane = threadIdx.x & 31;
    const int NV = BN_ * HEADS_;
    int half = (vid >= NV) ? 1 : 0;
    int v = vid - half * NV;
    int r = v / HEADS_;
    int h = v - r * HEADS_;
    const float* g = half ? gk : gq;
    float* p = x + (long long)r * QKVLD_ + half * INNER_ + h * DHEAD_;
    float v0 = p[lane], v1 = p[lane + 32];
    float ss = v0*v0 + v1*v1;
#pragma unroll
    for (int o = 16; o > 0; o >>= 1) ss += __shfl_xor_sync(0xffffffffu, ss, o);
    float rs = rsqrtf(ss * (1.0f/64.0f) + 1e-6f);
    p[lane]      = v0 * rs * g[lane];
    p[lane + 32] = v1 * rs * g[lane + 32];
}

// ---- rotary prep ----
__global__ void prep_kernel(const float* __restrict__ text,
                            const float* __restrict__ at,
                            f16* __restrict__ qh, f16* __restrict__ ql,
                            f16* __restrict__ kh)
{
    int row = blockIdx.x;
    int b = row / NP_;
    int pr = row - b * NP_;
    long long kout = (long long)row * DIM_;
    if (pr < WS_){
        f16 zz = __float2half(0.f);
        for (int c = threadIdx.x; c < DIM_; c += 256) kh[kout+c] = zz;
        return;
    }
    int t = pr - WS_;
    long long src = ((long long)b * N_ + t) * DIM_;
    for (int c = threadIdx.x; c < DIM_; c += 256){
        int j = c & 511;
        float invf = exp2f((float)j * (-13.28771238f * (1.0f/512.0f)));
        float ang = (float)t * invf;
        float cs = cosf(ang), sn = sinf(ang);
        float kx = at[src + c];
        float ko = (c < 512) ? -at[src + c + 512] : at[src + c - 512];
        kh[kout + c] = __float2half_rn(kx * cs + ko * sn);
        float qx = text[src + c];
        float qo = (c < 512) ? -text[src + c + 512] : text[src + c - 512];
        f16 h, l;
        split2(qx * cs + qo * sn, h, l);
        qh[src + c] = h; ql[src + c] = l;
    }
}

// ---- transpose to single fp16 ----
__global__ void tconv_kernel(const float* __restrict__ in, f16* __restrict__ oh,
                             int inLd, int outLd, int pad,
                             long long inB, long long outB)
{
    __shared__ float t[32][33];
    in += blockIdx.z * inB;
    oh += blockIdx.z * outB;
    int p0 = blockIdx.x * 32, c0 = blockIdx.y * 32;
    int tx = threadIdx.x, ty = threadIdx.y;
    for (int i = ty; i < 32; i += 8){
        int r = p0 + i - pad;
        t[i][tx] = (r >= 0) ? in[(long long)r * inLd + c0 + tx] : 0.f;
    }
    __syncthreads();
    for (int i = ty; i < 32; i += 8){
        long long o = (long long)(c0 + i) * outLd + p0 + tx;
        oh[o] = __float2half_rn(t[tx][i]);
    }
}

// ---- elementwise split fp32 -> fp16 hi/lo ----
__global__ void conv_kernel(const float* __restrict__ x, f16* __restrict__ h,
                            f16* __restrict__ l, int n)
{
    int i = (blockIdx.x * 256 + threadIdx.x) * 4;
    if (i < n){
        float4 v = *(const float4*)&x[i];
        f16 hh, ll;
        split2(v.x, hh, ll); h[i+0] = hh; l[i+0] = ll;
        split2(v.y, hh, ll); h[i+1] = hh; l[i+1] = ll;
        split2(v.z, hh, ll); h[i+2] = hh; l[i+2] = ll;
        split2(v.w, hh, ll); h[i+3] = hh; l[i+3] = ll;
    }
}

// ---- local-attention masked softmax -> fp16 hi/lo ----
__global__ void softmax_local_kernel(const float* __restrict__ p,
                                     f16* __restrict__ ph, f16* __restrict__ pl)
{
    __shared__ float buf[1024];
    __shared__ float red[8], bc[2];
    int r = blockIdx.x;
    int i = r & (WS_ - 1);
    int z = r >> 9;
    int w = z & (NWIN_ - 1);
    int qp = w * WS_ + i;
    const float* row = p + (long long)r * (2 * WS_);
    int tid = threadIdx.x, lane = tid & 31, wp = tid >> 5;

    float mx = -1e30f;
    for (int j = tid; j < 2*WS_; j += 256){
        int kp = (w - 1) * WS_ + j;
        float v = (kp >= 0 && kp <= qp) ? row[j] : -1e9f;
        buf[j] = v;
        mx = fmaxf(mx, v);
    }
#pragma unroll
    for (int o = 16; o > 0; o >>= 1) mx = fmaxf(mx, __shfl_xor_sync(0xffffffffu, mx, o));
    if (lane == 0) red[wp] = mx;
    __syncthreads();
    if (tid == 0){
        float m = red[0];
        for (int k = 1; k < 8; k++) m = fmaxf(m, red[k]);
        bc[0] = m;
    }
    __syncthreads();
    mx = bc[0];
    float sum = 0.f;
    for (int j = tid; j < 2*WS_; j += 256){
        float e = __expf(buf[j] - mx);
        buf[j] = e; sum += e;
    }
#pragma unroll
    for (int o = 16; o > 0; o >>= 1) sum += __shfl_xor_sync(0xffffffffu, sum, o);
    if (lane == 0) red[wp] = sum;
    __syncthreads();
    if (tid == 0){
        float t = 0.f;
        for (int k = 0; k < 8; k++) t += red[k];
        bc[1] = 1.0f / t;
    }
    __syncthreads();
    float inv = bc[1];
    for (int j = tid; j < 2*WS_; j += 256){
        f16 h, l; split2(buf[j] * inv, h, l);
        long long o = (long long)r * (2*WS_) + j;
        ph[o] = h; pl[o] = l;
    }
}

// ---- causal flash attention fp32; heavy-CTA-first scheduling ----
#define QP_ 68
#define ATTN_SMEM_BYTES (4 * 64 * QP_ * 4 + 3 * 64 * 4)

__global__ void __launch_bounds__(256)
attn_kernel(const float* __restrict__ qkv,
            float* __restrict__ o, f16* __restrict__ oh, f16* __restrict__ ol)
{
    extern __shared__ float sm[];
    float* QsT = sm;
    float* KsT = QsT + 64 * QP_;
    float* Vs  = KsT + 64 * QP_;
    float* SsT = Vs  + 64 * QP_;
    float* Ms = SsT + 64 * QP_;
    float* Ls = Ms + 64;
    float* Cs = Ls + 64;

    int tid = threadIdx.x;
    int bh = blockIdx.y;
    int b = bh >> 3, h = bh & 7;
    int qt = gridDim.x - 1 - blockIdx.x;
    int q0 = qt * 64;
    int ty = tid >> 4, tx = tid & 15;

    for (int idx = tid; idx < 4096; idx += 256){
        int r = idx >> 6, c = idx & 63;
        QsT[c * QP_ + r] =
            qkv[((long long)(b * N_ + q0 + r)) * QKVLD_ + h * 64 + c] * 0.125f;
    }
    if (tid < 64){ Ms[tid] = -INFINITY; Ls[tid] = 0.f; }
    float oacc[16];
#pragma unroll
    for (int i = 0; i < 16; i++) oacc[i] = 0.f;
    __syncthreads();

    int lastTile = qt;
    for (int kt = 0; kt <= lastTile; kt++){
        for (int idx = tid; idx < 4096; idx += 256){
            int r = idx >> 6, c = idx & 63;
            long long base =
                ((long long)(b * N_ + kt * 64 + r)) * QKVLD_ + INNER_ + h * 64 + c;
            KsT[c * QP_ + r] = qkv[base];
            Vs[r * QP_ + c]  = qkv[base + INNER_];
        }
        __syncthreads();

        float sacc[16];
#pragma unroll
        for (int i = 0; i < 16; i++) sacc[i] = 0.f;
#pragma unroll 8
        for (int kk = 0; kk < 64; kk++){
            float4 aq = *(const float4*)&QsT[kk * QP_ + ty * 4];
            float4 bk = *(const float4*)&KsT[kk * QP_ + tx * 4];
            float a4[4] = {aq.x, aq.y, aq.z, aq.w};
            float b4[4] = {bk.x, bk.y, bk.z, bk.w};
#pragma unroll
            for (int i = 0; i < 4; i++)
#pragma unroll
                for (int j = 0; j < 4; j++)
                    sacc[i*4+j] += a4[i] * b4[j];
        }
        bool diag = (kt == lastTile);
#pragma unroll
        for (int i = 0; i < 4; i++)
#pragma unroll
            for (int j = 0; j < 4; j++){
                int qr = ty * 4 + i, kc = tx * 4 + j;
                float s = sacc[i*4+j];
                if (diag && kc > qr) s = -INFINITY;
                SsT[kc * QP_ + qr] = s;
            }
        __syncthreads();

        if (tid < 64){
            int r = tid;
            float mt = -INFINITY;
#pragma unroll 8
            for (int c = 0; c < 64; c++) mt = fmaxf(mt, SsT[c * QP_ + r]);
            float mo = Ms[r];
            float mn = fmaxf(mo, mt);
            float corr = __expf(mo - mn);
            float ls = 0.f;
#pragma unroll 8
            for (int c = 0; c < 64; c++){
                float e = __expf(SsT[c * QP_ + r] - mn);
                SsT[c * QP_ + r] = e;
                ls += e;
            }
            Ls[r] = Ls[r] * corr + ls;
            Ms[r] = mn;
            Cs[r] = corr;
        }
        __syncthreads();

        float cf[4];
#pragma unroll
        for (int i = 0; i < 4; i++) cf[i] = Cs[ty * 4 + i];
#pragma unroll
        for (int i = 0; i < 4; i++)
#pragma unroll
            for (int j = 0; j < 4; j++) oacc[i*4+j] *= cf[i];

#pragma unroll 8
        for (int kk = 0; kk < 64; kk++){
            float4 ap = *(const float4*)&SsT[kk * QP_ + ty * 4];
            float4 vv = *(const float4*)&Vs[kk * QP_ + tx * 4];
            float a4[4] = {ap.x, ap.y, ap.z, ap.w};
            float b4[4] = {vv.x, vv.y, vv.z, vv.w};
#pragma unroll
            for (int i = 0; i < 4; i++)
#pragma unroll
                for (int j = 0; j < 4; j++)
                    oacc[i*4+j] += a4[i] * b4[j];
        }
        __syncthreads();
    }

#pragma unroll
    for (int i = 0; i < 4; i++){
        float inv = 1.0f / Ls[ty * 4 + i];
        long long orow =
            ((long long)(b * N_ + q0 + ty * 4 + i)) * INNER_ + h * 64 + tx * 4;
        float4 vo = make_float4(oacc[i*4+0]*inv, oacc[i*4+1]*inv,
                                oacc[i*4+2]*inv, oacc[i*4+3]*inv);
        *(float4*)&o[orow] = vo;
        f16 hh, ll;
        split2(vo.x, hh, ll); oh[orow+0] = hh; ol[orow+0] = ll;
        split2(vo.y, hh, ll); oh[orow+1] = hh; ol[orow+1] = ll;
        split2(vo.z, hh, ll); oh[orow+2] = hh; ol[orow+2] = ll;
        split2(vo.w, hh, ll); oh[orow+3] = hh; ol[orow+3] = ll;
    }
}

// ---- launch ----
extern "C" void kernel_launch(void* const* d_in, const int* in_sizes, int n_in,
                              void* d_out, int out_size)
{
    (void)in_sizes; (void)n_in; (void)out_size;
    const float* text  = (const float*)d_in[0];
    const float* audio = (const float*)d_in[1];
    const float* video = (const float*)d_in[2];
    const float* Wa    = (const float*)d_in[3];
    const float* ba    = (const float*)d_in[4];
    const float* lna_g = (const float*)d_in[5];
    const float* lna_b = (const float*)d_in[6];
    const float* Wvid  = (const float*)d_in[7];
    const float* bvid  = (const float*)d_in[8];
    const float* lnv_g = (const float*)d_in[9];
    const float* lnv_b = (const float*)d_in[10];
    const float* ln1_g = (const float*)d_in[11];
    const float* ln1_b = (const float*)d_in[12];
    const float* Wq    = (const float*)d_in[13];
    const float* Wkv   = (const float*)d_in[14];
    const float* qn_g  = (const float*)d_in[15];
    const float* kn_g  = (const float*)d_in[16];
    const float* Wo    = (const float*)d_in[17];
    const float* W1    = (const float*)d_in[18];
    const float* b1    = (const float*)d_in[19];
    const float* ln2_g = (const float*)d_in[20];
    const float* ln2_b = (const float*)d_in[21];
    const float* W2    = (const float*)d_in[22];
    const float* b2    = (const float*)d_in[23];
    float* out = (float*)d_out;

#define SYM(p, s) void* p; cudaGetSymbolAddress(&p, s)
    SYM(atvt, g_atvt); SYM(probs, g_probs);
    SYM(x, g_x);     SYM(qkvp, g_qkv);
    SYM(ob, g_o);    SYM(ff, g_ff);
    SYM(bias2, g_bias2);
    SYM(inH, g_inH); SYM(inL, g_inL);
    SYM(qh, g_qh);   SYM(ql, g_ql);
    SYM(kh, g_kh);   SYM(vTh, g_vTh);
    SYM(ph, g_ph);   SYM(pl, g_pl);
    SYM(hh, g_hh);   SYM(hl, g_hl);
    SYM(obH, g_obH); SYM(obL, g_obL);
    SYM(x2H, g_x2H); SYM(x2L, g_x2L);
    SYM(ffH, g_ffH); SYM(ffL, g_ffL);
    SYM(WavT, g_WavT); SYM(WqkvT, g_WqkvT);
    SYM(WoT, g_WoT); SYM(W1T, g_W1T); SYM(W2T, g_W2T);
#undef SYM

    cudaFuncSetAttribute(gemm_wmma<EPI_NONE>,      cudaFuncAttributeMaxDynamicSharedMemorySize, GEMM_SMEM_DYN);
    cudaFuncSetAttribute(gemm_wmma<EPI_BIAS>,      cudaFuncAttributeMaxDynamicSharedMemorySize, GEMM_SMEM_DYN);
    cudaFuncSetAttribute(gemm_wmma<EPI_BIAS_GELU>, cudaFuncAttributeMaxDynamicSharedMemorySize, GEMM_SMEM_DYN);
    cudaFuncSetAttribute(gemm_wmma<EPI_BIAS_RESH>, cudaFuncAttributeMaxDynamicSharedMemorySize, GEMM_SMEM_DYN);
    cudaFuncSetAttribute(gemm_wmma<EPI_SPLIT>,     cudaFuncAttributeMaxDynamicSharedMemorySize, GEMM_SMEM_DYN);
    cudaFuncSetAttribute(attn_kernel, cudaFuncAttributeMaxDynamicSharedMemorySize, ATTN_SMEM_BYTES);

    static cudaStream_t s2 = nullptr;
    static cudaEvent_t evFork = nullptr, evJoin = nullptr;
    if (s2 == nullptr){
        cudaStreamCreateWithFlags(&s2, cudaStreamNonBlocking);
        cudaEventCreateWithFlags(&evFork, cudaEventDisableTiming);
        cudaEventCreateWithFlags(&evJoin, cudaEventDisableTiming);
    }

    dim3 t32(32, 8);
    long long DD = (long long)DIM_ * DIM_;
    long long BD = (long long)BN_ * DIM_;

    packbias_kernel<<<4, 256>>>(ba, bvid);

    // fork: side stream transposes weights needed later
    cudaEventRecord(evFork, 0);
    cudaStreamWaitEvent(s2, evFork, 0);
    tconv_kernel<<<dim3(32, 16, 1), t32, 0, s2>>>(Wq,  (f16*)WqkvT, INNER_, DIM_, 0, 0, 0);
    tconv_kernel<<<dim3(32, 32, 1), t32, 0, s2>>>(Wkv, (f16*)WqkvT + (long long)INNER_*DIM_, 2*INNER_, DIM_, 0, 0, 0);
    tconv_kernel<<<dim3(16, 32, 1), t32, 0, s2>>>(Wo,  (f16*)WoT, DIM_, INNER_, 0, 0, 0);
    tconv_kernel<<<dim3(32, 128,1), t32, 0, s2>>>(W1,  (f16*)W1T, FF_,  DIM_,   0, 0, 0);
    tconv_kernel<<<dim3(128,32, 1), t32, 0, s2>>>(W2,  (f16*)W2T, DIM_, FF_,    0, 0, 0);
    cudaEventRecord(evJoin, s2);

    // main stream: adapter path
    tconv_kernel<<<dim3(32, 32, 1), t32>>>(Wa,  (f16*)WavT,      DIM_, DIM_, 0, 0, 0);
    tconv_kernel<<<dim3(32, 32, 1), t32>>>(Wvid,(f16*)WavT + DD, DIM_, DIM_, 0, 0, 0);
    conv_kernel<<<BN_*DIM_/1024, 256>>>(audio, (f16*)inH, (f16*)inL, BN_*DIM_);
    conv_kernel<<<BN_*DIM_/1024, 256>>>(video, (f16*)inH + BD, (f16*)inL + BD, BN_*DIM_);

    // 1) merged adapters
    gemm_wmma<EPI_BIAS><<<dim3(DIM_/128, BN_/128, 2), 256, GEMM_SMEM_DYN>>>(
        (f16*)inH, (f16*)inL, (f16*)WavT, (float*)atvt, (float*)bias2,
        nullptr, nullptr, DIM_, DIM_, DIM_, DIM_, 1.f, 1, DIM_,
        BD, 0, DD, 0, BD, 0);

    float* at = (float*)atvt;
    float* vt = (float*)atvt + BD;
    ln2_kernel<<<2*BN_, 256>>>((float*)atvt, lna_g, lna_b, lnv_g, lnv_b, DIM_);

    // 2) rotary + padded layouts
    prep_kernel<<<B_ * NP_, 256>>>(text, at, (f16*)qh, (f16*)ql, (f16*)kh);
    tconv_kernel<<<dim3(NP_/32, DIM_/32, B_), t32>>>(vt,
        (f16*)vTh, DIM_, NP_, WS_,
        (long long)N_*DIM_, (long long)DIM_*NP_);

    // 3) local attention (8 windows batched)
    gemm_wmma<EPI_NONE><<<dim3((2*WS_)/128, WS_/128, B_*NWIN_), 256, GEMM_SMEM_DYN>>>(
        (f16*)qh, (f16*)ql, (f16*)kh, (float*)probs, nullptr,
        nullptr, nullptr, DIM_, DIM_, DIM_, 2*WS_, 0.03125f, NWIN_, 0,
        (long long)N_*DIM_,  (long long)WS_*DIM_,
        (long long)NP_*DIM_, (long long)WS_*DIM_,
        (long long)NWIN_*WS_*2*WS_, (long long)WS_*2*WS_);
    softmax_local_kernel<<<B_*NWIN_*WS_, 256>>>((float*)probs, (f16*)ph, (f16*)pl);
    gemm_wmma<EPI_NONE><<<dim3(DIM_/128, WS_/128, B_*NWIN_), 256, GEMM_SMEM_DYN>>>(
        (f16*)ph, (f16*)pl, (f16*)vTh, (float*)x, nullptr,
        nullptr, nullptr, 2*WS_, 2*WS_, NP_, DIM_, 1.f, NWIN_, 0,
        (long long)NWIN_*WS_*2*WS_, (long long)WS_*2*WS_,
        (long long)DIM_*NP_, (long long)WS_,
        (long long)N_*DIM_, (long long)WS_*DIM_);

    // 4) ln1 -> merged qkv projection -> merged rmsnorm (join side stream)
    ln_bf_kernel<<<BN_, 256>>>((float*)x, (f16*)hh, (f16*)hl, ln1_g, ln1_b, DIM_);
    cudaStreamWaitEvent(0, evJoin, 0);
    gemm_wmma<EPI_NONE><<<dim3(QKVLD_/128, BN_/128, 1), 256, GEMM_SMEM_DYN>>>(
        (f16*)hh, (f16*)hl, (f16*)WqkvT, (float*)qkvp, nullptr,
        nullptr, nullptr, DIM_, DIM_, DIM_, QKVLD_, 1.f, 1, 0, 0,0,0,0,0,0);
    rms2_kernel<<<(2*BN_*HEADS_)/8, 256>>>((float*)qkvp, qn_g, kn_g);

    // 5) causal attention
    attn_kernel<<<dim3(N_/64, B_*HEADS_), 256, ATTN_SMEM_BYTES>>>(
        (float*)qkvp, (float*)ob, (f16*)obH, (f16*)obL);

    // 6) x2 = 2*(o @ Wo), emits ONLY fp16 split (residual read later as hi+lo)
    gemm_wmma<EPI_SPLIT><<<dim3(DIM_/128, BN_/128, 1), 256, GEMM_SMEM_DYN>>>(
        (f16*)obH, (f16*)obL, (f16*)WoT, (float*)ob /*unused*/, nullptr,
        (f16*)x2H, (f16*)x2L, INNER_, INNER_, INNER_, DIM_, 2.f, 1, 0, 0,0,0,0,0,0);

    // 7) FFN
    gemm_wmma<EPI_BIAS_GELU><<<dim3(FF_/128, BN_/128, 1), 256, GEMM_SMEM_DYN>>>(
        (f16*)x2H, (f16*)x2L, (f16*)W1T, (float*)ff, b1,
        nullptr, nullptr, DIM_, DIM_, DIM_, FF_, 1.f, 1, 0, 0,0,0,0,0,0);
    ln_bf_kernel<<<BN_, 256>>>((float*)ff, (f16*)ffH, (f16*)ffL, ln2_g, ln2_b, FF_);
    gemm_wmma<EPI_BIAS_RESH><<<dim3(DIM_/128, BN_/128, 1), 256, GEMM_SMEM_DYN>>>(
        (f16*)ffH, (f16*)ffL, (f16*)W2T, out, b2,
        (f16*)x2H, (f16*)x2L, FF_, FF_, FF_, DIM_, 1.f, 1, 0, 0,0,0,0,0,0);
}